// round 10
// baseline (speedup 1.0000x reference)
#include <cuda_runtime.h>
#include <cuda_bf16.h>
#include <math.h>
#include <stdint.h>

#define NS 128
#define NT 256
#define BOUND 2.0f

// ---- dynamic shared memory layout (float indices) ----
#define O_W1    0        // 192
#define O_B1    192      // 64
#define O_WSIG  256      // 64
#define O_WRGB  320      // 201 (+3 pad)
#define O_BRGB  524      // 4
#define O_B2    528      // 64
#define O_Z     592      // 256
#define O_SIG   848      // 256
#define O_RGB   1104     // 768
#define O_RED   1872     // 32
#define O_WT    1904     // 16
#define O_BUF   1920     // 128
#define O_C     2048     // 128
#define O_A     2176     // 128
#define O_HD    2304     // 512 (4 warps x [32 rows][4 heads])
#define O_HB    2816     // 512 (prepacked head B-frags: [4 ks][32 lanes] x uint4)
#define O_BHI   3328     // 2048 floats = 64 rows x 128B (W2^T hi), 1024B-aligned
#define O_BLO   5376     // 2048
#define SMEM_FLOATS 7424    // 29696 bytes

__device__ __forceinline__ uint32_t smem_u32(const void* p) {
    uint32_t a;
    asm("{ .reg .u64 t; cvta.to.shared.u64 t, %1; cvt.u32.u64 %0, t; }" : "=r"(a) : "l"(p));
    return a;
}

#define LDM_X4(r, addr) \
    asm volatile("ldmatrix.sync.aligned.m8n8.x4.shared.b16 {%0,%1,%2,%3}, [%4];" \
        : "=r"((r)[0]), "=r"((r)[1]), "=r"((r)[2]), "=r"((r)[3]) : "r"(addr))

#define MMA16816(d, a, b0, b1) \
    asm volatile("mma.sync.aligned.m16n8k16.row.col.f32.bf16.bf16.f32 " \
        "{%0,%1,%2,%3}, {%4,%5,%6,%7}, {%8,%9}, {%0,%1,%2,%3};" \
        : "+f"((d)[0]), "+f"((d)[1]), "+f"((d)[2]), "+f"((d)[3]) \
        : "r"((a)[0]), "r"((a)[1]), "r"((a)[2]), "r"((a)[3]), "r"(b0), "r"(b1))

// packed dual-FMA (sm_103a f32x2)
__device__ __forceinline__ float2 ffma2(float2 a, float2 b, float2 c) {
    float2 d;
    asm("fma.rn.f32x2 %0, %1, %2, %3;"
        : "=l"(reinterpret_cast<unsigned long long&>(d))
        : "l"(reinterpret_cast<unsigned long long&>(a)),
          "l"(reinterpret_cast<unsigned long long&>(b)),
          "l"(reinterpret_cast<unsigned long long&>(c)));
    return d;
}
// pack two f32 -> bf16x2 (lo half = x, hi half = y)
__device__ __forceinline__ uint32_t pack_bf16x2(float lo, float hi) {
    uint32_t w;
    asm("cvt.rn.bf16x2.f32 %0, %1, %2;" : "=r"(w) : "f"(hi), "f"(lo));
    return w;
}
// residual pair after bf16 rounding: (x,y) - unpack(pack(x,y))
__device__ __forceinline__ uint32_t pack_bf16x2_res(float x, float y, uint32_t hw) {
    float fx = __uint_as_float(hw << 16);
    float fy = __uint_as_float(hw & 0xffff0000u);
    return pack_bf16x2(x - fx, y - fy);
}

__device__ __forceinline__ float clipf(float x, float lo, float hi) {
    return x < lo ? lo : (x > hi ? hi : x);
}

// ---- warp-shuffle scans ----
__device__ __forceinline__ float warp_scan_mul(float v, int lane) {
#pragma unroll
    for (int o = 1; o < 32; o <<= 1) {
        float t = __shfl_up_sync(0xffffffffu, v, o);
        if (lane >= o) v *= t;
    }
    return v;
}
__device__ __forceinline__ float warp_scan_add(float v, int lane) {
#pragma unroll
    for (int o = 1; o < 32; o <<= 1) {
        float t = __shfl_up_sync(0xffffffffu, v, o);
        if (lane >= o) v += t;
    }
    return v;
}
__device__ __forceinline__ float scan128_mul(float v, int tid, float* wt) {
    int lane = tid & 31, w = tid >> 5;
    float s = warp_scan_mul(v, lane);
    if (lane == 31) wt[w] = s;
    __syncthreads();
    float pre = 1.f;
#pragma unroll
    for (int k = 0; k < 3; k++) if (k < w) pre *= wt[k];
    return s * pre;
}
__device__ __forceinline__ float scan128_add(float v, int tid, float* wt) {
    int lane = tid & 31, w = tid >> 5;
    float s = warp_scan_add(v, lane);
    if (lane == 31) wt[w] = s;
    __syncthreads();
    float pre = 0.f;
#pragma unroll
    for (int k = 0; k < 3; k++) if (k < w) pre += wt[k];
    return s + pre;
}

// ---------------------------------------------------------------------------
// One field pass for 128 samples. Warp w owns rows 32w..32w+31. Layer 1 is
// computed directly in m16n8k16 A-fragment layout (no SMEM staging). Output
// columns processed in TWO 32-col halves to halve accumulator registers;
// head-MMA partials accumulate across halves. Head B-fragments come
// prepacked from O_HB.
// ---------------------------------------------------------------------------
__device__ __forceinline__ void field_pass(
    float* sm, uint32_t smem_base, int tid,
    float ox, float oy, float oz, float dx, float dy, float dz,
    float dirR0, float dirR1, float dirR2, int outBase)
{
    const int lane = tid & 31;
    const int wid = tid >> 5;
    const int c = lane & 3, g = lane >> 2;
    const int m0 = 32 * wid;

    const int br = (lane & 7) + ((lane >> 4) << 3);    // B row within n16 group
    const int bkh = (lane >> 3) & 1;                   // B k-half
    const uint32_t bHiBase = smem_base + O_BHI * 4;
    const uint32_t bLoBase = smem_base + O_BLO * 4;

    // ---- per-fragment ray points: rows m0 + 8i + g, i = 0..3 ----
    float pxs[4], pys[4], pzs[4];
#pragma unroll
    for (int i = 0; i < 4; i++) {
        float z = sm[O_Z + outBase + m0 + 8 * i + g];
        pxs[i] = clipf(fmaf(dx, z, ox), -BOUND, BOUND);
        pys[i] = clipf(fmaf(dy, z, oy), -BOUND, BOUND);
        pzs[i] = clipf(fmaf(dz, z, oz), -BOUND, BOUND);
    }

    const float2* w1p = (const float2*)(sm + O_W1);
    const float2* b1p = (const float2*)(sm + O_B1);

    float d2[2][4];
#pragma unroll
    for (int mt = 0; mt < 2; mt++)
#pragma unroll
        for (int e = 0; e < 4; e++) d2[mt][e] = 0.f;

#pragma unroll
    for (int nh = 0; nh < 2; nh++) {
        // ---- main MMA half: D[32][32] over n-tiles 4nh..4nh+3 ----
        float d[2][4][4];
#pragma unroll
        for (int mt = 0; mt < 2; mt++)
#pragma unroll
            for (int n = 0; n < 4; n++)
#pragma unroll
                for (int e = 0; e < 4; e++) d[mt][n][e] = 0.f;

#pragma unroll
        for (int ks = 0; ks < 4; ks++) {
            // A-fragments computed in registers (layer 1, bf16 hi/lo split)
            uint32_t ahi[2][4], alo[2][4];
            const int p0 = 8 * ks + c, p1 = p0 + 4;
            float2 W0x = w1p[p0],      W1x = w1p[p1];
            float2 W0y = w1p[32 + p0], W1y = w1p[32 + p1];
            float2 W0z = w1p[64 + p0], W1z = w1p[64 + p1];
            float2 B0  = b1p[p0],      B1  = b1p[p1];
#pragma unroll
            for (int mt = 0; mt < 2; mt++) {
#pragma unroll
                for (int rr = 0; rr < 2; rr++) {
                    int i = 2 * mt + rr;
                    float2 PX = make_float2(pxs[i], pxs[i]);
                    float2 PY = make_float2(pys[i], pys[i]);
                    float2 PZ = make_float2(pzs[i], pzs[i]);
                    float2 v0 = ffma2(PX, W0x, ffma2(PY, W0y, ffma2(PZ, W0z, B0)));
                    float2 v1 = ffma2(PX, W1x, ffma2(PY, W1y, ffma2(PZ, W1z, B1)));
                    v0.x = fmaxf(v0.x, 0.f); v0.y = fmaxf(v0.y, 0.f);
                    v1.x = fmaxf(v1.x, 0.f); v1.y = fmaxf(v1.y, 0.f);
                    uint32_t h0 = pack_bf16x2(v0.x, v0.y);
                    uint32_t h1 = pack_bf16x2(v1.x, v1.y);
                    ahi[mt][0 + rr] = h0;
                    ahi[mt][2 + rr] = h1;
                    alo[mt][0 + rr] = pack_bf16x2_res(v0.x, v0.y, h0);
                    alo[mt][2 + rr] = pack_bf16x2_res(v1.x, v1.y, h1);
                }
            }
#pragma unroll
            for (int npl = 0; npl < 2; npl++) {
                int np = 2 * nh + npl;
                uint32_t bh[4], bl[4];
                uint32_t boff = (uint32_t)(16 * np + br) * 128u +
                                (uint32_t)(((2 * ks + bkh) ^ (br & 7)) << 4);
                LDM_X4(bh, bHiBase + boff);
                LDM_X4(bl, bLoBase + boff);
#pragma unroll
                for (int mt = 0; mt < 2; mt++) {
                    MMA16816(d[mt][2 * npl + 0], ahi[mt], bh[0], bh[1]);
                    MMA16816(d[mt][2 * npl + 0], alo[mt], bh[0], bh[1]);
                    MMA16816(d[mt][2 * npl + 0], ahi[mt], bl[0], bl[1]);
                    MMA16816(d[mt][2 * npl + 1], ahi[mt], bh[2], bh[3]);
                    MMA16816(d[mt][2 * npl + 1], alo[mt], bh[2], bh[3]);
                    MMA16816(d[mt][2 * npl + 1], ahi[mt], bl[2], bl[3]);
                }
            }
        }

        // ---- head MMA partial for this half: k-steps ks2 = 2nh + {0,1} ----
#pragma unroll
        for (int ks2l = 0; ks2l < 2; ks2l++) {
            int ks2 = 2 * nh + ks2l;
            uint4 hb = *(const uint4*)(sm + O_HB + (ks2 * 32 + lane) * 4);
            uint32_t bh0 = hb.x, bh1 = hb.y, bl0 = hb.z, bl1 = hb.w;

            float2 b2a = *(const float2*)(sm + O_B2 + 16 * ks2 + 2 * c);
            float2 b2b = *(const float2*)(sm + O_B2 + 16 * ks2 + 8 + 2 * c);

#pragma unroll
            for (int mt = 0; mt < 2; mt++) {
                float e00 = fmaxf(d[mt][2 * ks2l][0] + b2a.x, 0.f);
                float e01 = fmaxf(d[mt][2 * ks2l][1] + b2a.y, 0.f);
                float e02 = fmaxf(d[mt][2 * ks2l][2] + b2a.x, 0.f);
                float e03 = fmaxf(d[mt][2 * ks2l][3] + b2a.y, 0.f);
                float e10 = fmaxf(d[mt][2 * ks2l + 1][0] + b2b.x, 0.f);
                float e11 = fmaxf(d[mt][2 * ks2l + 1][1] + b2b.y, 0.f);
                float e12 = fmaxf(d[mt][2 * ks2l + 1][2] + b2b.x, 0.f);
                float e13 = fmaxf(d[mt][2 * ks2l + 1][3] + b2b.y, 0.f);

                uint32_t ah[4], al[4];
                ah[0] = pack_bf16x2(e00, e01);
                ah[1] = pack_bf16x2(e02, e03);
                ah[2] = pack_bf16x2(e10, e11);
                ah[3] = pack_bf16x2(e12, e13);
                al[0] = pack_bf16x2_res(e00, e01, ah[0]);
                al[1] = pack_bf16x2_res(e02, e03, ah[1]);
                al[2] = pack_bf16x2_res(e10, e11, ah[2]);
                al[3] = pack_bf16x2_res(e12, e13, ah[3]);

                MMA16816(d2[mt], ah, bh0, bh1);
                MMA16816(d2[mt], al, bh0, bh1);
                MMA16816(d2[mt], ah, bl0, bl1);
            }
        }
    }

    // ---- stage heads to warp-private scratch, finalize per-sample ----
    {
        float* sHD = sm + O_HD + wid * 128;   // [32 rows][4 heads]
        if (c < 2) {
#pragma unroll
            for (int mt = 0; mt < 2; mt++) {
                *(float2*)(sHD + (16 * mt + g) * 4 + 2 * c)     = make_float2(d2[mt][0], d2[mt][1]);
                *(float2*)(sHD + (16 * mt + 8 + g) * 4 + 2 * c) = make_float2(d2[mt][2], d2[mt][3]);
            }
        }
        __syncwarp();

        float4 hd = *(const float4*)(sHD + lane * 4);
        float sg = hd.x;
        float sigma = fmaxf(sg, 0.f) + __logf(1.f + __expf(-fabsf(sg)));
        float r0 = hd.y + dirR0;
        float r1 = hd.z + dirR1;
        float r2 = hd.w + dirR2;
        sm[O_SIG + outBase + tid] = sigma;
        sm[O_RGB + (outBase + tid) * 3 + 0] = 1.f / (1.f + __expf(-r0));
        sm[O_RGB + (outBase + tid) * 3 + 1] = 1.f / (1.f + __expf(-r1));
        sm[O_RGB + (outBase + tid) * 3 + 2] = 1.f / (1.f + __expf(-r2));
    }
}

// ---------------------------------------------------------------------------
__global__ void __launch_bounds__(128, 5)
nerf_render_kernel(const float* __restrict__ rays_o, const float* __restrict__ rays_d,
                   const float* __restrict__ W1, const float* __restrict__ b1,
                   const float* __restrict__ W2, const float* __restrict__ b2,
                   const float* __restrict__ Wsig, const float* __restrict__ Wrgb,
                   const float* __restrict__ brgb,
                   float* __restrict__ out, int nrays)
{
    extern __shared__ float sm[];
    const int tid = threadIdx.x;
    const int ray = blockIdx.x;
    const uint32_t smem_base = smem_u32(sm);

    // ---- cooperative weight load ----
    for (int i = tid; i < 192; i += 128) sm[O_W1 + i] = W1[i];
    if (tid < 64) { sm[O_B1 + tid] = b1[tid]; sm[O_B2 + tid] = b2[tid]; sm[O_WSIG + tid] = Wsig[tid]; }
    for (int i = tid; i < 201; i += 128) sm[O_WRGB + i] = Wrgb[i];
    if (tid < 3) sm[O_BRGB + tid] = brgb[tid];

    // W2 split -> B planes: B[j][k] = W2[k][j], 128B rows, chunk-XOR swizzle
    {
        char* bhi = (char*)(sm + O_BHI);
        char* blo = (char*)(sm + O_BLO);
#pragma unroll
        for (int t = 0; t < 32; t++) {
            int i = tid + t * 128;
            int k = i >> 6, j = i & 63;
            float v = W2[i];
            __nv_bfloat16 bh = __float2bfloat16(v);
            float fh = __bfloat162float(bh);
            __nv_bfloat16 bl = __float2bfloat16(v - fh);
            uint32_t byte = (uint32_t)(j * 128 + k * 2);
            uint32_t sw = byte ^ ((byte >> 3) & 0x70);
            *(__nv_bfloat16*)(bhi + sw) = bh;
            *(__nv_bfloat16*)(blo + sw) = bl;
        }
    }
    __syncthreads();   // WSIG/WRGB visible for prepack

    // ---- prepack head-MMA B-fragments (ray-invariant, once per CTA) ----
    // thread tid = (ks = tid>>5, lane = tid&31); lane = (g = lane>>2, c = lane&3)
    {
        int ks = tid >> 5, lane = tid & 31;
        int tig = lane & 3, g = lane >> 2;
        int kb = 16 * ks + 2 * tig;
        float w0, w1, w2, w3;
        if (g == 0) {
            w0 = sm[O_WSIG + kb];     w1 = sm[O_WSIG + kb + 1];
            w2 = sm[O_WSIG + kb + 8]; w3 = sm[O_WSIG + kb + 9];
        } else if (g < 4) {
            int ch = g - 1;
            w0 = sm[O_WRGB + 3 * kb + ch];       w1 = sm[O_WRGB + 3 * (kb + 1) + ch];
            w2 = sm[O_WRGB + 3 * (kb + 8) + ch]; w3 = sm[O_WRGB + 3 * (kb + 9) + ch];
        } else {
            w0 = w1 = w2 = w3 = 0.f;
        }
        uint32_t bh0 = pack_bf16x2(w0, w1);
        uint32_t bh1 = pack_bf16x2(w2, w3);
        uint32_t bl0 = pack_bf16x2_res(w0, w1, bh0);
        uint32_t bl1 = pack_bf16x2_res(w2, w3, bh1);
        *(uint4*)(sm + O_HB + tid * 4) = make_uint4(bh0, bh1, bl0, bl1);
    }

    // ---- per-ray setup ----
    const float ox = rays_o[ray * 3 + 0], oy = rays_o[ray * 3 + 1], oz = rays_o[ray * 3 + 2];
    const float dx = rays_d[ray * 3 + 0], dy = rays_d[ray * 3 + 1], dz = rays_d[ray * 3 + 2];

    float near = -3.0e38f, far = 3.0e38f;
    {
        float o3[3] = {ox, oy, oz}, d3[3] = {dx, dy, dz};
#pragma unroll
        for (int c = 0; c < 3; c++) {
            float den = d3[c] + 1e-15f;
            float tmn = (-BOUND - o3[c]) / den;
            float tmx = ( BOUND - o3[c]) / den;
            near = fmaxf(near, fminf(tmn, tmx));
            far  = fminf(far,  fmaxf(tmn, tmx));
        }
        if (far < near) { near = 1e9f; far = 1e9f; }
        near = fmaxf(near, 0.05f);
    }
    const float span = far - near;
    const float sample_dist = span / (float)NS;

    float* sZ   = sm + O_Z;
    float* sSig = sm + O_SIG;
    float* sRGB = sm + O_RGB;
    float* sBuf = sm + O_BUF;
    float* sC   = sm + O_C;
    float* sA   = sm + O_A;
    float* sRed = sm + O_RED;
    float* sWT  = sm + O_WT;

    // dir-dependent head terms
    const float dirR0 = fmaf(dx, sm[O_WRGB + 64 * 3 + 0], fmaf(dy, sm[O_WRGB + 65 * 3 + 0], fmaf(dz, sm[O_WRGB + 66 * 3 + 0], sm[O_BRGB + 0])));
    const float dirR1 = fmaf(dx, sm[O_WRGB + 64 * 3 + 1], fmaf(dy, sm[O_WRGB + 65 * 3 + 1], fmaf(dz, sm[O_WRGB + 66 * 3 + 1], sm[O_BRGB + 1])));
    const float dirR2 = fmaf(dx, sm[O_WRGB + 64 * 3 + 2], fmaf(dy, sm[O_WRGB + 65 * 3 + 2], fmaf(dz, sm[O_WRGB + 66 * 3 + 2], sm[O_BRGB + 2])));

    // ========== Phase A: coarse ==========
    sZ[tid] = near + span * ((float)tid * (1.f / 127.f));
    __syncthreads();   // sZ + HB prepack visible
    field_pass(sm, smem_base, tid, ox, oy, oz, dx, dy, dz, dirR0, dirR1, dirR2, 0);
    __syncthreads();

    // ========== Phase B: weights -> pdf -> inverse-CDF scatter ==========
    {
        float delta = (tid < NS - 1) ? (sZ[tid + 1] - sZ[tid]) : sample_dist;
        float alpha = 1.f - __expf(-delta * sSig[tid]);
        float shifted = 1.f - alpha + 1e-15f;
        if (tid < NS - 1) sC[tid] = sZ[tid] + 0.5f * delta;
        float Tincl = scan128_mul(shifted, tid, sWT);   // sync inside
        float w = alpha * (Tincl / shifted);            // exclusive via division
        sA[tid] = w;
        __syncthreads();
        float pv = (tid < 126) ? (sA[tid + 1] + 1e-5f) : 0.f;
        float csum = scan128_add(pv, tid, sWT);         // sync inside
        sBuf[tid] = csum;
        __syncthreads();
        const float invS = 1.f / sBuf[125];

        // thread tid = bin: u in [c[tid], c[tid+1]) -> scatter fine z
        if (tid < 127) {
            float clo = (tid == 0) ? 0.f : sBuf[tid - 1] * invS;
            bool last = (tid == 126);
            float chi = last ? 3.0e38f : sBuf[tid] * invS;
            int t0 = max(0, (int)ceilf(fmaf(128.f, clo, -0.5f)));
            int t1 = last ? 127 : (min(128, (int)ceilf(fmaf(128.f, chi, -0.5f))) - 1);
            if (t0 <= t1) {
                int above = min(tid + 1, 126);
                float cb = clo;
                float ca = sBuf[above - 1] * invS;
                float bb = sC[tid], ba = sC[above];
                float den = ca - cb;
                if (den < 1e-5f) den = 1.f;
                float scale = (ba - bb) / den;
                for (int t = t0; t <= t1; t++) {
                    float u = 0.00390625f + (float)t * 0.0078125f;
                    sZ[NS + t] = bb + (u - cb) * scale;
                }
            }
        }
    }
    __syncthreads();

    // ========== Phase C: fine ==========
    float new_z = sZ[NS + tid];
    field_pass(sm, smem_base, tid, ox, oy, oz, dx, dy, dz, dirR0, dirR1, dirR2, NS);
    __syncthreads();

    // ========== Phase D: stable merge of two sorted runs ==========
    {
        float zA = sZ[tid], zB = new_z;
        int lo = 0, hi = NS;
        while (lo < hi) { int m = (lo + hi) >> 1; if (sZ[NS + m] < zA) lo = m + 1; else hi = m; }
        int posA = tid + lo;
        lo = 0; hi = NS;
        while (lo < hi) { int m = (lo + hi) >> 1; if (sZ[m] <= zB) lo = m + 1; else hi = m; }
        int posB = tid + lo;

        float sgA = sSig[tid], sgB = sSig[NS + tid];
        float a0 = sRGB[tid * 3 + 0], a1 = sRGB[tid * 3 + 1], a2 = sRGB[tid * 3 + 2];
        float b0 = sRGB[(NS + tid) * 3 + 0], b1v = sRGB[(NS + tid) * 3 + 1], b2v = sRGB[(NS + tid) * 3 + 2];
        __syncthreads();
        sZ[posA] = zA; sSig[posA] = sgA;
        sRGB[posA * 3 + 0] = a0; sRGB[posA * 3 + 1] = a1; sRGB[posA * 3 + 2] = a2;
        sZ[posB] = zB; sSig[posB] = sgB;
        sRGB[posB * 3 + 0] = b0; sRGB[posB * 3 + 1] = b1v; sRGB[posB * 3 + 2] = b2v;
        __syncthreads();
    }

    // ========== Phase E: final composite ==========
    {
        const int i0 = 2 * tid, i1 = 2 * tid + 1;
        float d0 = sZ[i0 + 1] - sZ[i0];
        float d1 = (i1 < NT - 1) ? (sZ[i1 + 1] - sZ[i1]) : sample_dist;
        float al0 = 1.f - __expf(-d0 * sSig[i0]);
        float al1 = 1.f - __expf(-d1 * sSig[i1]);
        float s0 = 1.f - al0 + 1e-15f;
        float s1 = 1.f - al1 + 1e-15f;

        int lane = tid & 31, w = tid >> 5;
        float p = s0 * s1;
        float pincl = warp_scan_mul(p, lane);
        if (lane == 31) sWT[w] = pincl;
        __syncthreads();
        float pre = 1.f;
#pragma unroll
        for (int k = 0; k < 3; k++) if (k < w) pre *= sWT[k];
        float e = __shfl_up_sync(0xffffffffu, pincl, 1);
        e = (lane == 0) ? 1.f : e;
        e *= pre;
        float w0 = al0 * e;
        float w1 = al1 * e * s0;

        float v0 = clipf((sZ[i0] - near) / span, 0.f, 1.f);
        float v1 = clipf((sZ[i1] - near) / span, 0.f, 1.f);
        float wsum = w0 + w1;
        float dsum = w0 * v0 + w1 * v1;
        float rs0 = fmaf(w0, sRGB[i0 * 3 + 0], w1 * sRGB[i1 * 3 + 0]);
        float rs1 = fmaf(w0, sRGB[i0 * 3 + 1], w1 * sRGB[i1 * 3 + 1]);
        float rs2 = fmaf(w0, sRGB[i0 * 3 + 2], w1 * sRGB[i1 * 3 + 2]);

#pragma unroll
        for (int o = 16; o > 0; o >>= 1) {
            wsum += __shfl_down_sync(0xffffffffu, wsum, o);
            dsum += __shfl_down_sync(0xffffffffu, dsum, o);
            rs0  += __shfl_down_sync(0xffffffffu, rs0, o);
            rs1  += __shfl_down_sync(0xffffffffu, rs1, o);
            rs2  += __shfl_down_sync(0xffffffffu, rs2, o);
        }
        if (lane == 0) {
            sRed[w * 5 + 0] = wsum; sRed[w * 5 + 1] = dsum;
            sRed[w * 5 + 2] = rs0;  sRed[w * 5 + 3] = rs1; sRed[w * 5 + 4] = rs2;
        }
        __syncthreads();
        if (tid == 0) {
            float W = 0, D = 0, R0 = 0, R1 = 0, R2 = 0;
#pragma unroll
            for (int w2 = 0; w2 < 4; w2++) {
                W += sRed[w2 * 5 + 0]; D += sRed[w2 * 5 + 1];
                R0 += sRed[w2 * 5 + 2]; R1 += sRed[w2 * 5 + 3]; R2 += sRed[w2 * 5 + 4];
            }
            float bg = 1.f - W;
            out[ray] = D;
            out[nrays + ray * 3 + 0] = R0 + bg;
            out[nrays + ray * 3 + 1] = R1 + bg;
            out[nrays + ray * 3 + 2] = R2 + bg;
        }
    }
}

extern "C" void kernel_launch(void* const* d_in, const int* in_sizes, int n_in,
                              void* d_out, int out_size) {
    const float* rays_o = (const float*)d_in[0];
    const float* rays_d = (const float*)d_in[1];
    const float* W1   = (const float*)d_in[2];
    const float* b1   = (const float*)d_in[3];
    const float* W2   = (const float*)d_in[4];
    const float* b2   = (const float*)d_in[5];
    const float* Wsig = (const float*)d_in[6];
    const float* Wrgb = (const float*)d_in[7];
    const float* brgb = (const float*)d_in[8];
    float* out = (float*)d_out;

    int nrays = in_sizes[0] / 3;   // B*N
    size_t smem_bytes = (size_t)SMEM_FLOATS * sizeof(float);
    cudaFuncSetAttribute(nerf_render_kernel,
                         cudaFuncAttributeMaxDynamicSharedMemorySize, (int)smem_bytes);
    nerf_render_kernel<<<nrays, 128, smem_bytes>>>(rays_o, rays_d, W1, b1, W2, b2,
                                                   Wsig, Wrgb, brgb, out, nrays);
}

// round 11
// speedup vs baseline: 1.0683x; 1.0683x over previous
#include <cuda_runtime.h>
#include <cuda_bf16.h>
#include <math.h>
#include <stdint.h>

#define NS 128
#define NT 256
#define BOUND 2.0f

// ---- dynamic shared memory layout (float indices) ----
#define O_W1    0        // 192
#define O_B1    192      // 64
#define O_WSIG  256      // 64
#define O_WRGB  320      // 201 (+3 pad)
#define O_BRGB  524      // 4
#define O_B2    528      // 64
#define O_Z     592      // 256
#define O_SIG   848      // 256
#define O_RGB   1104     // 768
#define O_RED   1872     // 32
#define O_WT    1904     // 16
#define O_BUF   1920     // 128
#define O_C     2048     // 128
#define O_A     2176     // 128
#define O_HD    2304     // 512 (4 warps x [32 rows][4 heads])
#define O_HB    2816     // 512 (prepacked head B-frags: [4 ks][32 lanes] x uint4)
#define O_BHI   3328     // 2048 floats = 64 rows x 128B (W2^T hi), 1024B-aligned
#define O_BLO   5376     // 2048
#define SMEM_FLOATS 7424    // 29696 bytes

__device__ __forceinline__ uint32_t smem_u32(const void* p) {
    uint32_t a;
    asm("{ .reg .u64 t; cvta.to.shared.u64 t, %1; cvt.u32.u64 %0, t; }" : "=r"(a) : "l"(p));
    return a;
}

#define LDM_X4(r, addr) \
    asm volatile("ldmatrix.sync.aligned.m8n8.x4.shared.b16 {%0,%1,%2,%3}, [%4];" \
        : "=r"((r)[0]), "=r"((r)[1]), "=r"((r)[2]), "=r"((r)[3]) : "r"(addr))

#define MMA16816(d, a, b0, b1) \
    asm volatile("mma.sync.aligned.m16n8k16.row.col.f32.bf16.bf16.f32 " \
        "{%0,%1,%2,%3}, {%4,%5,%6,%7}, {%8,%9}, {%0,%1,%2,%3};" \
        : "+f"((d)[0]), "+f"((d)[1]), "+f"((d)[2]), "+f"((d)[3]) \
        : "r"((a)[0]), "r"((a)[1]), "r"((a)[2]), "r"((a)[3]), "r"(b0), "r"(b1))

// packed dual-FMA (sm_103a f32x2)
__device__ __forceinline__ float2 ffma2(float2 a, float2 b, float2 c) {
    float2 d;
    asm("fma.rn.f32x2 %0, %1, %2, %3;"
        : "=l"(reinterpret_cast<unsigned long long&>(d))
        : "l"(reinterpret_cast<unsigned long long&>(a)),
          "l"(reinterpret_cast<unsigned long long&>(b)),
          "l"(reinterpret_cast<unsigned long long&>(c)));
    return d;
}
// pack two f32 -> bf16x2 (lo half = x, hi half = y)
__device__ __forceinline__ uint32_t pack_bf16x2(float lo, float hi) {
    uint32_t w;
    asm("cvt.rn.bf16x2.f32 %0, %1, %2;" : "=r"(w) : "f"(hi), "f"(lo));
    return w;
}
// residual pair after bf16 rounding: (x,y) - unpack(pack(x,y))
__device__ __forceinline__ uint32_t pack_bf16x2_res(float x, float y, uint32_t hw) {
    float fx = __uint_as_float(hw << 16);
    float fy = __uint_as_float(hw & 0xffff0000u);
    return pack_bf16x2(x - fx, y - fy);
}

__device__ __forceinline__ float clipf(float x, float lo, float hi) {
    return x < lo ? lo : (x > hi ? hi : x);
}

// ---- warp-shuffle scans ----
__device__ __forceinline__ float warp_scan_mul(float v, int lane) {
#pragma unroll
    for (int o = 1; o < 32; o <<= 1) {
        float t = __shfl_up_sync(0xffffffffu, v, o);
        if (lane >= o) v *= t;
    }
    return v;
}
__device__ __forceinline__ float warp_scan_add(float v, int lane) {
#pragma unroll
    for (int o = 1; o < 32; o <<= 1) {
        float t = __shfl_up_sync(0xffffffffu, v, o);
        if (lane >= o) v += t;
    }
    return v;
}
__device__ __forceinline__ float scan128_mul(float v, int tid, float* wt) {
    int lane = tid & 31, w = tid >> 5;
    float s = warp_scan_mul(v, lane);
    if (lane == 31) wt[w] = s;
    __syncthreads();
    float pre = 1.f;
#pragma unroll
    for (int k = 0; k < 3; k++) if (k < w) pre *= wt[k];
    return s * pre;
}
__device__ __forceinline__ float scan128_add(float v, int tid, float* wt) {
    int lane = tid & 31, w = tid >> 5;
    float s = warp_scan_add(v, lane);
    if (lane == 31) wt[w] = s;
    __syncthreads();
    float pre = 0.f;
#pragma unroll
    for (int k = 0; k < 3; k++) if (k < w) pre += wt[k];
    return s + pre;
}

// ---------------------------------------------------------------------------
// One field pass for 128 samples (R9 structure). Warp w owns rows 32w..32w+31.
// Layer 1 computed directly in m16n8k16 A-fragment layout (no SMEM staging).
// Head-MMA B-fragments come prepacked from O_HB (ray-invariant).
// ---------------------------------------------------------------------------
__device__ __forceinline__ void field_pass(
    float* sm, uint32_t smem_base, int tid,
    float ox, float oy, float oz, float dx, float dy, float dz,
    float dirR0, float dirR1, float dirR2, int outBase)
{
    const int lane = tid & 31;
    const int wid = tid >> 5;
    const int c = lane & 3, g = lane >> 2;
    const int m0 = 32 * wid;

    const int br = (lane & 7) + ((lane >> 4) << 3);    // B row within n16 group
    const int bkh = (lane >> 3) & 1;                   // B k-half
    const uint32_t bHiBase = smem_base + O_BHI * 4;
    const uint32_t bLoBase = smem_base + O_BLO * 4;

    // ---- per-fragment ray points: rows m0 + 8i + g, i = 0..3 ----
    float pxs[4], pys[4], pzs[4];
#pragma unroll
    for (int i = 0; i < 4; i++) {
        float z = sm[O_Z + outBase + m0 + 8 * i + g];
        pxs[i] = clipf(fmaf(dx, z, ox), -BOUND, BOUND);
        pys[i] = clipf(fmaf(dy, z, oy), -BOUND, BOUND);
        pzs[i] = clipf(fmaf(dz, z, oz), -BOUND, BOUND);
    }

    // ---- warp MMA: D[32][64] = Ahi*Bhi + Ahi*Blo + Alo*Bhi ----
    float d[2][8][4];
#pragma unroll
    for (int mt = 0; mt < 2; mt++)
#pragma unroll
        for (int n = 0; n < 8; n++)
#pragma unroll
            for (int e = 0; e < 4; e++) d[mt][n][e] = 0.f;

    const float2* w1p = (const float2*)(sm + O_W1);
    const float2* b1p = (const float2*)(sm + O_B1);

#pragma unroll
    for (int ks = 0; ks < 4; ks++) {
        // A-fragments computed in registers (layer 1, bf16 hi/lo split)
        uint32_t ahi[2][4], alo[2][4];
        const int p0 = 8 * ks + c, p1 = p0 + 4;
        float2 W0x = w1p[p0],      W1x = w1p[p1];
        float2 W0y = w1p[32 + p0], W1y = w1p[32 + p1];
        float2 W0z = w1p[64 + p0], W1z = w1p[64 + p1];
        float2 B0  = b1p[p0],      B1  = b1p[p1];
#pragma unroll
        for (int mt = 0; mt < 2; mt++) {
#pragma unroll
            for (int rr = 0; rr < 2; rr++) {
                int i = 2 * mt + rr;
                float2 PX = make_float2(pxs[i], pxs[i]);
                float2 PY = make_float2(pys[i], pys[i]);
                float2 PZ = make_float2(pzs[i], pzs[i]);
                float2 v0 = ffma2(PX, W0x, ffma2(PY, W0y, ffma2(PZ, W0z, B0)));
                float2 v1 = ffma2(PX, W1x, ffma2(PY, W1y, ffma2(PZ, W1z, B1)));
                v0.x = fmaxf(v0.x, 0.f); v0.y = fmaxf(v0.y, 0.f);
                v1.x = fmaxf(v1.x, 0.f); v1.y = fmaxf(v1.y, 0.f);
                uint32_t h0 = pack_bf16x2(v0.x, v0.y);
                uint32_t h1 = pack_bf16x2(v1.x, v1.y);
                ahi[mt][0 + rr] = h0;
                ahi[mt][2 + rr] = h1;
                alo[mt][0 + rr] = pack_bf16x2_res(v0.x, v0.y, h0);
                alo[mt][2 + rr] = pack_bf16x2_res(v1.x, v1.y, h1);
            }
        }
#pragma unroll
        for (int np = 0; np < 4; np++) {
            uint32_t bh[4], bl[4];
            uint32_t boff = (uint32_t)(16 * np + br) * 128u +
                            (uint32_t)(((2 * ks + bkh) ^ (br & 7)) << 4);
            LDM_X4(bh, bHiBase + boff);
            LDM_X4(bl, bLoBase + boff);
#pragma unroll
            for (int mt = 0; mt < 2; mt++) {
                MMA16816(d[mt][2 * np + 0], ahi[mt], bh[0], bh[1]);
                MMA16816(d[mt][2 * np + 0], alo[mt], bh[0], bh[1]);
                MMA16816(d[mt][2 * np + 0], ahi[mt], bl[0], bl[1]);
                MMA16816(d[mt][2 * np + 1], ahi[mt], bh[2], bh[3]);
                MMA16816(d[mt][2 * np + 1], alo[mt], bh[2], bh[3]);
                MMA16816(d[mt][2 * np + 1], ahi[mt], bl[2], bl[3]);
            }
        }
    }

    // ---- head MMA epilogue: heads[128][8] = relu(D+b2) @ Whead[64][8] ----
    {
        float d2[2][4];
#pragma unroll
        for (int mt = 0; mt < 2; mt++)
#pragma unroll
            for (int e = 0; e < 4; e++) d2[mt][e] = 0.f;

#pragma unroll
        for (int ks = 0; ks < 4; ks++) {
            uint4 hb = *(const uint4*)(sm + O_HB + (ks * 32 + lane) * 4);
            uint32_t bh0 = hb.x, bh1 = hb.y, bl0 = hb.z, bl1 = hb.w;

            float2 b2a = *(const float2*)(sm + O_B2 + 16 * ks + 2 * c);
            float2 b2b = *(const float2*)(sm + O_B2 + 16 * ks + 8 + 2 * c);

#pragma unroll
            for (int mt = 0; mt < 2; mt++) {
                float e00 = fmaxf(d[mt][2 * ks][0] + b2a.x, 0.f);
                float e01 = fmaxf(d[mt][2 * ks][1] + b2a.y, 0.f);
                float e02 = fmaxf(d[mt][2 * ks][2] + b2a.x, 0.f);
                float e03 = fmaxf(d[mt][2 * ks][3] + b2a.y, 0.f);
                float e10 = fmaxf(d[mt][2 * ks + 1][0] + b2b.x, 0.f);
                float e11 = fmaxf(d[mt][2 * ks + 1][1] + b2b.y, 0.f);
                float e12 = fmaxf(d[mt][2 * ks + 1][2] + b2b.x, 0.f);
                float e13 = fmaxf(d[mt][2 * ks + 1][3] + b2b.y, 0.f);

                uint32_t ah[4], al[4];
                ah[0] = pack_bf16x2(e00, e01);
                ah[1] = pack_bf16x2(e02, e03);
                ah[2] = pack_bf16x2(e10, e11);
                ah[3] = pack_bf16x2(e12, e13);
                al[0] = pack_bf16x2_res(e00, e01, ah[0]);
                al[1] = pack_bf16x2_res(e02, e03, ah[1]);
                al[2] = pack_bf16x2_res(e10, e11, ah[2]);
                al[3] = pack_bf16x2_res(e12, e13, ah[3]);

                MMA16816(d2[mt], ah, bh0, bh1);
                MMA16816(d2[mt], al, bh0, bh1);
                MMA16816(d2[mt], ah, bl0, bl1);
            }
        }

        // stage heads to warp-private scratch
        float* sHD = sm + O_HD + wid * 128;   // [32 rows][4 heads]
        if (c < 2) {
#pragma unroll
            for (int mt = 0; mt < 2; mt++) {
                *(float2*)(sHD + (16 * mt + g) * 4 + 2 * c)     = make_float2(d2[mt][0], d2[mt][1]);
                *(float2*)(sHD + (16 * mt + 8 + g) * 4 + 2 * c) = make_float2(d2[mt][2], d2[mt][3]);
            }
        }
        __syncwarp();

        // finalize: thread = its own sample
        float4 hd = *(const float4*)(sHD + lane * 4);
        float sg = hd.x;
        float sigma = fmaxf(sg, 0.f) + __logf(1.f + __expf(-fabsf(sg)));
        float r0 = hd.y + dirR0;
        float r1 = hd.z + dirR1;
        float r2 = hd.w + dirR2;
        sm[O_SIG + outBase + tid] = sigma;
        sm[O_RGB + (outBase + tid) * 3 + 0] = 1.f / (1.f + __expf(-r0));
        sm[O_RGB + (outBase + tid) * 3 + 1] = 1.f / (1.f + __expf(-r1));
        sm[O_RGB + (outBase + tid) * 3 + 2] = 1.f / (1.f + __expf(-r2));
    }
}

// ---------------------------------------------------------------------------
__global__ void __launch_bounds__(128, 4)
nerf_render_kernel(const float* __restrict__ rays_o, const float* __restrict__ rays_d,
                   const float* __restrict__ W1, const float* __restrict__ b1,
                   const float* __restrict__ W2, const float* __restrict__ b2,
                   const float* __restrict__ Wsig, const float* __restrict__ Wrgb,
                   const float* __restrict__ brgb,
                   float* __restrict__ out, int nrays)
{
    extern __shared__ float sm[];
    const int tid = threadIdx.x;
    const int ray = blockIdx.x;
    const uint32_t smem_base = smem_u32(sm);

    // ---- cooperative weight load ----
    for (int i = tid; i < 192; i += 128) sm[O_W1 + i] = W1[i];
    if (tid < 64) { sm[O_B1 + tid] = b1[tid]; sm[O_B2 + tid] = b2[tid]; sm[O_WSIG + tid] = Wsig[tid]; }
    for (int i = tid; i < 201; i += 128) sm[O_WRGB + i] = Wrgb[i];
    if (tid < 3) sm[O_BRGB + tid] = brgb[tid];

    // W2 split -> B planes: B[j][k] = W2[k][j], 128B rows, chunk-XOR swizzle
    {
        char* bhi = (char*)(sm + O_BHI);
        char* blo = (char*)(sm + O_BLO);
#pragma unroll
        for (int t = 0; t < 32; t++) {
            int i = tid + t * 128;
            int k = i >> 6, j = i & 63;
            float v = W2[i];
            __nv_bfloat16 bh = __float2bfloat16(v);
            float fh = __bfloat162float(bh);
            __nv_bfloat16 bl = __float2bfloat16(v - fh);
            uint32_t byte = (uint32_t)(j * 128 + k * 2);
            uint32_t sw = byte ^ ((byte >> 3) & 0x70);
            *(__nv_bfloat16*)(bhi + sw) = bh;
            *(__nv_bfloat16*)(blo + sw) = bl;
        }
    }
    __syncthreads();   // WSIG/WRGB visible for prepack

    // ---- prepack head-MMA B-fragments (ray-invariant, once per CTA) ----
    {
        int ks = tid >> 5, lane = tid & 31;
        int tig = lane & 3, g = lane >> 2;
        int kb = 16 * ks + 2 * tig;
        float w0, w1, w2, w3;
        if (g == 0) {
            w0 = sm[O_WSIG + kb];     w1 = sm[O_WSIG + kb + 1];
            w2 = sm[O_WSIG + kb + 8]; w3 = sm[O_WSIG + kb + 9];
        } else if (g < 4) {
            int ch = g - 1;
            w0 = sm[O_WRGB + 3 * kb + ch];       w1 = sm[O_WRGB + 3 * (kb + 1) + ch];
            w2 = sm[O_WRGB + 3 * (kb + 8) + ch]; w3 = sm[O_WRGB + 3 * (kb + 9) + ch];
        } else {
            w0 = w1 = w2 = w3 = 0.f;
        }
        uint32_t bh0 = pack_bf16x2(w0, w1);
        uint32_t bh1 = pack_bf16x2(w2, w3);
        uint32_t bl0 = pack_bf16x2_res(w0, w1, bh0);
        uint32_t bl1 = pack_bf16x2_res(w2, w3, bh1);
        *(uint4*)(sm + O_HB + tid * 4) = make_uint4(bh0, bh1, bl0, bl1);
    }

    // ---- per-ray setup ----
    const float ox = rays_o[ray * 3 + 0], oy = rays_o[ray * 3 + 1], oz = rays_o[ray * 3 + 2];
    const float dx = rays_d[ray * 3 + 0], dy = rays_d[ray * 3 + 1], dz = rays_d[ray * 3 + 2];

    float near = -3.0e38f, far = 3.0e38f;
    {
        float o3[3] = {ox, oy, oz}, d3[3] = {dx, dy, dz};
#pragma unroll
        for (int c = 0; c < 3; c++) {
            float den = d3[c] + 1e-15f;
            float tmn = (-BOUND - o3[c]) / den;
            float tmx = ( BOUND - o3[c]) / den;
            near = fmaxf(near, fminf(tmn, tmx));
            far  = fminf(far,  fmaxf(tmn, tmx));
        }
        if (far < near) { near = 1e9f; far = 1e9f; }
        near = fmaxf(near, 0.05f);
    }
    const float span = far - near;
    const float sample_dist = span / (float)NS;

    float* sZ   = sm + O_Z;
    float* sSig = sm + O_SIG;
    float* sRGB = sm + O_RGB;
    float* sBuf = sm + O_BUF;
    float* sC   = sm + O_C;
    float* sA   = sm + O_A;
    float* sRed = sm + O_RED;
    float* sWT  = sm + O_WT;

    // dir-dependent head terms
    const float dirR0 = fmaf(dx, sm[O_WRGB + 64 * 3 + 0], fmaf(dy, sm[O_WRGB + 65 * 3 + 0], fmaf(dz, sm[O_WRGB + 66 * 3 + 0], sm[O_BRGB + 0])));
    const float dirR1 = fmaf(dx, sm[O_WRGB + 64 * 3 + 1], fmaf(dy, sm[O_WRGB + 65 * 3 + 1], fmaf(dz, sm[O_WRGB + 66 * 3 + 1], sm[O_BRGB + 1])));
    const float dirR2 = fmaf(dx, sm[O_WRGB + 64 * 3 + 2], fmaf(dy, sm[O_WRGB + 65 * 3 + 2], fmaf(dz, sm[O_WRGB + 66 * 3 + 2], sm[O_BRGB + 2])));

    // ========== Phase A: coarse ==========
    sZ[tid] = near + span * ((float)tid * (1.f / 127.f));
    __syncthreads();   // sZ + HB prepack visible
    field_pass(sm, smem_base, tid, ox, oy, oz, dx, dy, dz, dirR0, dirR1, dirR2, 0);
    __syncthreads();

    // ========== Phase B: weights -> pdf -> inverse-CDF scatter ==========
    {
        float delta = (tid < NS - 1) ? (sZ[tid + 1] - sZ[tid]) : sample_dist;
        float alpha = 1.f - __expf(-delta * sSig[tid]);
        float shifted = 1.f - alpha + 1e-15f;
        if (tid < NS - 1) sC[tid] = sZ[tid] + 0.5f * delta;
        float Tincl = scan128_mul(shifted, tid, sWT);   // sync inside
        float w = alpha * (Tincl / shifted);            // exclusive via division
        sA[tid] = w;
        __syncthreads();
        float pv = (tid < 126) ? (sA[tid + 1] + 1e-5f) : 0.f;
        float csum = scan128_add(pv, tid, sWT);         // sync inside
        sBuf[tid] = csum;
        __syncthreads();
        const float invS = 1.f / sBuf[125];

        // thread tid = bin: u in [c[tid], c[tid+1]) -> scatter fine z
        if (tid < 127) {
            float clo = (tid == 0) ? 0.f : sBuf[tid - 1] * invS;
            bool last = (tid == 126);
            float chi = last ? 3.0e38f : sBuf[tid] * invS;
            int t0 = max(0, (int)ceilf(fmaf(128.f, clo, -0.5f)));
            int t1 = last ? 127 : (min(128, (int)ceilf(fmaf(128.f, chi, -0.5f))) - 1);
            if (t0 <= t1) {
                int above = min(tid + 1, 126);
                float cb = clo;
                float ca = sBuf[above - 1] * invS;
                float bb = sC[tid], ba = sC[above];
                float den = ca - cb;
                if (den < 1e-5f) den = 1.f;
                float scale = (ba - bb) / den;
                for (int t = t0; t <= t1; t++) {
                    float u = 0.00390625f + (float)t * 0.0078125f;
                    sZ[NS + t] = bb + (u - cb) * scale;
                }
            }
        }
    }
    __syncthreads();

    // ========== Phase C: fine ==========
    float new_z = sZ[NS + tid];
    field_pass(sm, smem_base, tid, ox, oy, oz, dx, dy, dz, dirR0, dirR1, dirR2, NS);
    __syncthreads();

    // ========== Phase D: stable merge of two sorted runs ==========
    {
        float zA = sZ[tid], zB = new_z;
        int lo = 0, hi = NS;
        while (lo < hi) { int m = (lo + hi) >> 1; if (sZ[NS + m] < zA) lo = m + 1; else hi = m; }
        int posA = tid + lo;
        lo = 0; hi = NS;
        while (lo < hi) { int m = (lo + hi) >> 1; if (sZ[m] <= zB) lo = m + 1; else hi = m; }
        int posB = tid + lo;

        float sgA = sSig[tid], sgB = sSig[NS + tid];
        float a0 = sRGB[tid * 3 + 0], a1 = sRGB[tid * 3 + 1], a2 = sRGB[tid * 3 + 2];
        float b0 = sRGB[(NS + tid) * 3 + 0], b1v = sRGB[(NS + tid) * 3 + 1], b2v = sRGB[(NS + tid) * 3 + 2];
        __syncthreads();
        sZ[posA] = zA; sSig[posA] = sgA;
        sRGB[posA * 3 + 0] = a0; sRGB[posA * 3 + 1] = a1; sRGB[posA * 3 + 2] = a2;
        sZ[posB] = zB; sSig[posB] = sgB;
        sRGB[posB * 3 + 0] = b0; sRGB[posB * 3 + 1] = b1v; sRGB[posB * 3 + 2] = b2v;
        __syncthreads();
    }

    // ========== Phase E: final composite ==========
    {
        const int i0 = 2 * tid, i1 = 2 * tid + 1;
        float d0 = sZ[i0 + 1] - sZ[i0];
        float d1 = (i1 < NT - 1) ? (sZ[i1 + 1] - sZ[i1]) : sample_dist;
        float al0 = 1.f - __expf(-d0 * sSig[i0]);
        float al1 = 1.f - __expf(-d1 * sSig[i1]);
        float s0 = 1.f - al0 + 1e-15f;
        float s1 = 1.f - al1 + 1e-15f;

        int lane = tid & 31, w = tid >> 5;
        float p = s0 * s1;
        float pincl = warp_scan_mul(p, lane);
        if (lane == 31) sWT[w] = pincl;
        __syncthreads();
        float pre = 1.f;
#pragma unroll
        for (int k = 0; k < 3; k++) if (k < w) pre *= sWT[k];
        float e = __shfl_up_sync(0xffffffffu, pincl, 1);
        e = (lane == 0) ? 1.f : e;
        e *= pre;
        float w0 = al0 * e;
        float w1 = al1 * e * s0;

        float v0 = clipf((sZ[i0] - near) / span, 0.f, 1.f);
        float v1 = clipf((sZ[i1] - near) / span, 0.f, 1.f);
        float wsum = w0 + w1;
        float dsum = w0 * v0 + w1 * v1;
        float rs0 = fmaf(w0, sRGB[i0 * 3 + 0], w1 * sRGB[i1 * 3 + 0]);
        float rs1 = fmaf(w0, sRGB[i0 * 3 + 1], w1 * sRGB[i1 * 3 + 1]);
        float rs2 = fmaf(w0, sRGB[i0 * 3 + 2], w1 * sRGB[i1 * 3 + 2]);

#pragma unroll
        for (int o = 16; o > 0; o >>= 1) {
            wsum += __shfl_down_sync(0xffffffffu, wsum, o);
            dsum += __shfl_down_sync(0xffffffffu, dsum, o);
            rs0  += __shfl_down_sync(0xffffffffu, rs0, o);
            rs1  += __shfl_down_sync(0xffffffffu, rs1, o);
            rs2  += __shfl_down_sync(0xffffffffu, rs2, o);
        }
        if (lane == 0) {
            sRed[w * 5 + 0] = wsum; sRed[w * 5 + 1] = dsum;
            sRed[w * 5 + 2] = rs0;  sRed[w * 5 + 3] = rs1; sRed[w * 5 + 4] = rs2;
        }
        __syncthreads();
        if (tid == 0) {
            float W = 0, D = 0, R0 = 0, R1 = 0, R2 = 0;
#pragma unroll
            for (int w2 = 0; w2 < 4; w2++) {
                W += sRed[w2 * 5 + 0]; D += sRed[w2 * 5 + 1];
                R0 += sRed[w2 * 5 + 2]; R1 += sRed[w2 * 5 + 3]; R2 += sRed[w2 * 5 + 4];
            }
            float bg = 1.f - W;
            out[ray] = D;
            out[nrays + ray * 3 + 0] = R0 + bg;
            out[nrays + ray * 3 + 1] = R1 + bg;
            out[nrays + ray * 3 + 2] = R2 + bg;
        }
    }
}

extern "C" void kernel_launch(void* const* d_in, const int* in_sizes, int n_in,
                              void* d_out, int out_size) {
    const float* rays_o = (const float*)d_in[0];
    const float* rays_d = (const float*)d_in[1];
    const float* W1   = (const float*)d_in[2];
    const float* b1   = (const float*)d_in[3];
    const float* W2   = (const float*)d_in[4];
    const float* b2   = (const float*)d_in[5];
    const float* Wsig = (const float*)d_in[6];
    const float* Wrgb = (const float*)d_in[7];
    const float* brgb = (const float*)d_in[8];
    float* out = (float*)d_out;

    int nrays = in_sizes[0] / 3;   // B*N
    size_t smem_bytes = (size_t)SMEM_FLOATS * sizeof(float);
    cudaFuncSetAttribute(nerf_render_kernel,
                         cudaFuncAttributeMaxDynamicSharedMemorySize, (int)smem_bytes);
    nerf_render_kernel<<<nrays, 128, smem_bytes>>>(rays_o, rays_d, W1, b1, W2, b2,
                                                   Wsig, Wrgb, brgb, out, nrays);
}

// round 12
// speedup vs baseline: 1.0885x; 1.0189x over previous
#include <cuda_runtime.h>
#include <cuda_bf16.h>
#include <math.h>
#include <stdint.h>

#define NS 128
#define NT 256
#define BOUND 2.0f

// ---- dynamic shared memory layout (float indices) ----
#define O_W1    0        // 192
#define O_B1    192      // 64
#define O_WSIG  256      // 64
#define O_WRGB  320      // 201 (+3 pad)
#define O_BRGB  524      // 4
#define O_B2    528      // 64
#define O_Z     592      // 256
#define O_SIG   848      // 256
#define O_RGB   1104     // 768
#define O_RED   1872     // 32
#define O_WT    1904     // 16
#define O_BUF   1920     // 128
#define O_C     2048     // 128
#define O_A     2176     // 128
#define O_HD    2304     // 512 (4 warps x [32 rows][4 heads])
#define O_HB    2816     // 512 (prepacked head B-frags: [4 ks][32 lanes] x uint4)
#define O_BHI   3328     // 2048 floats = 64 rows x 128B (W2^T hi), 1024B-aligned
#define O_BLO   5376     // 2048
#define SMEM_FLOATS 7424    // 29696 bytes

__device__ __forceinline__ uint32_t smem_u32(const void* p) {
    uint32_t a;
    asm("{ .reg .u64 t; cvta.to.shared.u64 t, %1; cvt.u32.u64 %0, t; }" : "=r"(a) : "l"(p));
    return a;
}

#define LDM_X4(r, addr) \
    asm volatile("ldmatrix.sync.aligned.m8n8.x4.shared.b16 {%0,%1,%2,%3}, [%4];" \
        : "=r"((r)[0]), "=r"((r)[1]), "=r"((r)[2]), "=r"((r)[3]) : "r"(addr))

#define MMA16816(d, a, b0, b1) \
    asm volatile("mma.sync.aligned.m16n8k16.row.col.f32.bf16.bf16.f32 " \
        "{%0,%1,%2,%3}, {%4,%5,%6,%7}, {%8,%9}, {%0,%1,%2,%3};" \
        : "+f"((d)[0]), "+f"((d)[1]), "+f"((d)[2]), "+f"((d)[3]) \
        : "r"((a)[0]), "r"((a)[1]), "r"((a)[2]), "r"((a)[3]), "r"(b0), "r"(b1))

// packed dual-FMA (sm_103a f32x2)
__device__ __forceinline__ float2 ffma2(float2 a, float2 b, float2 c) {
    float2 d;
    asm("fma.rn.f32x2 %0, %1, %2, %3;"
        : "=l"(reinterpret_cast<unsigned long long&>(d))
        : "l"(reinterpret_cast<unsigned long long&>(a)),
          "l"(reinterpret_cast<unsigned long long&>(b)),
          "l"(reinterpret_cast<unsigned long long&>(c)));
    return d;
}
// pack two f32 -> bf16x2 (lo half = x, hi half = y)
__device__ __forceinline__ uint32_t pack_bf16x2(float lo, float hi) {
    uint32_t w;
    asm("cvt.rn.bf16x2.f32 %0, %1, %2;" : "=r"(w) : "f"(hi), "f"(lo));
    return w;
}
// residual pair after bf16 rounding: (x,y) - unpack(pack(x,y))
__device__ __forceinline__ uint32_t pack_bf16x2_res(float x, float y, uint32_t hw) {
    float fx = __uint_as_float(hw << 16);
    float fy = __uint_as_float(hw & 0xffff0000u);
    return pack_bf16x2(x - fx, y - fy);
}

__device__ __forceinline__ float clipf(float x, float lo, float hi) {
    return x < lo ? lo : (x > hi ? hi : x);
}

// ---- warp-shuffle scans ----
__device__ __forceinline__ float warp_scan_mul(float v, int lane) {
#pragma unroll
    for (int o = 1; o < 32; o <<= 1) {
        float t = __shfl_up_sync(0xffffffffu, v, o);
        if (lane >= o) v *= t;
    }
    return v;
}
__device__ __forceinline__ float warp_scan_add(float v, int lane) {
#pragma unroll
    for (int o = 1; o < 32; o <<= 1) {
        float t = __shfl_up_sync(0xffffffffu, v, o);
        if (lane >= o) v += t;
    }
    return v;
}
__device__ __forceinline__ float scan128_mul(float v, int tid, float* wt) {
    int lane = tid & 31, w = tid >> 5;
    float s = warp_scan_mul(v, lane);
    if (lane == 31) wt[w] = s;
    __syncthreads();
    float pre = 1.f;
#pragma unroll
    for (int k = 0; k < 3; k++) if (k < w) pre *= wt[k];
    return s * pre;
}
__device__ __forceinline__ float scan128_add(float v, int tid, float* wt) {
    int lane = tid & 31, w = tid >> 5;
    float s = warp_scan_add(v, lane);
    if (lane == 31) wt[w] = s;
    __syncthreads();
    float pre = 0.f;
#pragma unroll
    for (int k = 0; k < 3; k++) if (k < w) pre += wt[k];
    return s + pre;
}

// ---------------------------------------------------------------------------
// One field pass for 128 samples. Warp w owns rows 32w..32w+31.
// Layer 1 computed directly in m16n8k16 A-fragment layout (no SMEM staging).
// Main MMA issued TERM-MAJOR per np: accumulator reuse distance = 4
// (per-accumulator term order unchanged -> bitwise-identical results).
// ---------------------------------------------------------------------------
__device__ __forceinline__ void field_pass(
    float* sm, uint32_t smem_base, int tid,
    float ox, float oy, float oz, float dx, float dy, float dz,
    float dirR0, float dirR1, float dirR2, int outBase)
{
    const int lane = tid & 31;
    const int wid = tid >> 5;
    const int c = lane & 3, g = lane >> 2;
    const int m0 = 32 * wid;

    const int br = (lane & 7) + ((lane >> 4) << 3);    // B row within n16 group
    const int bkh = (lane >> 3) & 1;                   // B k-half
    const uint32_t bHiBase = smem_base + O_BHI * 4;
    const uint32_t bLoBase = smem_base + O_BLO * 4;

    // ---- per-fragment ray points: rows m0 + 8i + g, i = 0..3 ----
    float pxs[4], pys[4], pzs[4];
#pragma unroll
    for (int i = 0; i < 4; i++) {
        float z = sm[O_Z + outBase + m0 + 8 * i + g];
        pxs[i] = clipf(fmaf(dx, z, ox), -BOUND, BOUND);
        pys[i] = clipf(fmaf(dy, z, oy), -BOUND, BOUND);
        pzs[i] = clipf(fmaf(dz, z, oz), -BOUND, BOUND);
    }

    // ---- warp MMA: D[32][64] = Ahi*Bhi + Ahi*Blo + Alo*Bhi ----
    float d[2][8][4];
#pragma unroll
    for (int mt = 0; mt < 2; mt++)
#pragma unroll
        for (int n = 0; n < 8; n++)
#pragma unroll
            for (int e = 0; e < 4; e++) d[mt][n][e] = 0.f;

    const float2* w1p = (const float2*)(sm + O_W1);
    const float2* b1p = (const float2*)(sm + O_B1);

#pragma unroll
    for (int ks = 0; ks < 4; ks++) {
        // A-fragments computed in registers (layer 1, bf16 hi/lo split)
        uint32_t ahi[2][4], alo[2][4];
        const int p0 = 8 * ks + c, p1 = p0 + 4;
        float2 W0x = w1p[p0],      W1x = w1p[p1];
        float2 W0y = w1p[32 + p0], W1y = w1p[32 + p1];
        float2 W0z = w1p[64 + p0], W1z = w1p[64 + p1];
        float2 B0  = b1p[p0],      B1  = b1p[p1];
#pragma unroll
        for (int mt = 0; mt < 2; mt++) {
#pragma unroll
            for (int rr = 0; rr < 2; rr++) {
                int i = 2 * mt + rr;
                float2 PX = make_float2(pxs[i], pxs[i]);
                float2 PY = make_float2(pys[i], pys[i]);
                float2 PZ = make_float2(pzs[i], pzs[i]);
                float2 v0 = ffma2(PX, W0x, ffma2(PY, W0y, ffma2(PZ, W0z, B0)));
                float2 v1 = ffma2(PX, W1x, ffma2(PY, W1y, ffma2(PZ, W1z, B1)));
                v0.x = fmaxf(v0.x, 0.f); v0.y = fmaxf(v0.y, 0.f);
                v1.x = fmaxf(v1.x, 0.f); v1.y = fmaxf(v1.y, 0.f);
                uint32_t h0 = pack_bf16x2(v0.x, v0.y);
                uint32_t h1 = pack_bf16x2(v1.x, v1.y);
                ahi[mt][0 + rr] = h0;
                ahi[mt][2 + rr] = h1;
                alo[mt][0 + rr] = pack_bf16x2_res(v0.x, v0.y, h0);
                alo[mt][2 + rr] = pack_bf16x2_res(v1.x, v1.y, h1);
            }
        }
#pragma unroll
        for (int np = 0; np < 4; np++) {
            uint32_t bh[4], bl[4];
            uint32_t boff = (uint32_t)(16 * np + br) * 128u +
                            (uint32_t)(((2 * ks + bkh) ^ (br & 7)) << 4);
            LDM_X4(bh, bHiBase + boff);
            LDM_X4(bl, bLoBase + boff);
            // term-major issue: accumulator reuse distance 4
            // term 0: Ahi * Bhi
            MMA16816(d[0][2 * np + 0], ahi[0], bh[0], bh[1]);
            MMA16816(d[0][2 * np + 1], ahi[0], bh[2], bh[3]);
            MMA16816(d[1][2 * np + 0], ahi[1], bh[0], bh[1]);
            MMA16816(d[1][2 * np + 1], ahi[1], bh[2], bh[3]);
            // term 1: Alo * Bhi
            MMA16816(d[0][2 * np + 0], alo[0], bh[0], bh[1]);
            MMA16816(d[0][2 * np + 1], alo[0], bh[2], bh[3]);
            MMA16816(d[1][2 * np + 0], alo[1], bh[0], bh[1]);
            MMA16816(d[1][2 * np + 1], alo[1], bh[2], bh[3]);
            // term 2: Ahi * Blo
            MMA16816(d[0][2 * np + 0], ahi[0], bl[0], bl[1]);
            MMA16816(d[0][2 * np + 1], ahi[0], bl[2], bl[3]);
            MMA16816(d[1][2 * np + 0], ahi[1], bl[0], bl[1]);
            MMA16816(d[1][2 * np + 1], ahi[1], bl[2], bl[3]);
        }
    }

    // ---- head MMA epilogue: heads[128][8] = relu(D+b2) @ Whead[64][8] ----
    {
        float d2[2][4];
#pragma unroll
        for (int mt = 0; mt < 2; mt++)
#pragma unroll
            for (int e = 0; e < 4; e++) d2[mt][e] = 0.f;

#pragma unroll
        for (int ks = 0; ks < 4; ks++) {
            uint4 hb = *(const uint4*)(sm + O_HB + (ks * 32 + lane) * 4);
            uint32_t bh0 = hb.x, bh1 = hb.y, bl0 = hb.z, bl1 = hb.w;

            float2 b2a = *(const float2*)(sm + O_B2 + 16 * ks + 2 * c);
            float2 b2b = *(const float2*)(sm + O_B2 + 16 * ks + 8 + 2 * c);

            // build A-frags for both mt first, then issue term-major
            uint32_t ah[2][4], al[2][4];
#pragma unroll
            for (int mt = 0; mt < 2; mt++) {
                float e00 = fmaxf(d[mt][2 * ks][0] + b2a.x, 0.f);
                float e01 = fmaxf(d[mt][2 * ks][1] + b2a.y, 0.f);
                float e02 = fmaxf(d[mt][2 * ks][2] + b2a.x, 0.f);
                float e03 = fmaxf(d[mt][2 * ks][3] + b2a.y, 0.f);
                float e10 = fmaxf(d[mt][2 * ks + 1][0] + b2b.x, 0.f);
                float e11 = fmaxf(d[mt][2 * ks + 1][1] + b2b.y, 0.f);
                float e12 = fmaxf(d[mt][2 * ks + 1][2] + b2b.x, 0.f);
                float e13 = fmaxf(d[mt][2 * ks + 1][3] + b2b.y, 0.f);

                ah[mt][0] = pack_bf16x2(e00, e01);
                ah[mt][1] = pack_bf16x2(e02, e03);
                ah[mt][2] = pack_bf16x2(e10, e11);
                ah[mt][3] = pack_bf16x2(e12, e13);
                al[mt][0] = pack_bf16x2_res(e00, e01, ah[mt][0]);
                al[mt][1] = pack_bf16x2_res(e02, e03, ah[mt][1]);
                al[mt][2] = pack_bf16x2_res(e10, e11, ah[mt][2]);
                al[mt][3] = pack_bf16x2_res(e12, e13, ah[mt][3]);
            }
            // term-major: reuse distance 2
            MMA16816(d2[0], ah[0], bh0, bh1);
            MMA16816(d2[1], ah[1], bh0, bh1);
            MMA16816(d2[0], al[0], bh0, bh1);
            MMA16816(d2[1], al[1], bh0, bh1);
            MMA16816(d2[0], ah[0], bl0, bl1);
            MMA16816(d2[1], ah[1], bl0, bl1);
        }

        // stage heads to warp-private scratch
        float* sHD = sm + O_HD + wid * 128;   // [32 rows][4 heads]
        if (c < 2) {
#pragma unroll
            for (int mt = 0; mt < 2; mt++) {
                *(float2*)(sHD + (16 * mt + g) * 4 + 2 * c)     = make_float2(d2[mt][0], d2[mt][1]);
                *(float2*)(sHD + (16 * mt + 8 + g) * 4 + 2 * c) = make_float2(d2[mt][2], d2[mt][3]);
            }
        }
        __syncwarp();

        // finalize: thread = its own sample
        float4 hd = *(const float4*)(sHD + lane * 4);
        float sg = hd.x;
        float sigma = fmaxf(sg, 0.f) + __logf(1.f + __expf(-fabsf(sg)));
        float r0 = hd.y + dirR0;
        float r1 = hd.z + dirR1;
        float r2 = hd.w + dirR2;
        sm[O_SIG + outBase + tid] = sigma;
        sm[O_RGB + (outBase + tid) * 3 + 0] = 1.f / (1.f + __expf(-r0));
        sm[O_RGB + (outBase + tid) * 3 + 1] = 1.f / (1.f + __expf(-r1));
        sm[O_RGB + (outBase + tid) * 3 + 2] = 1.f / (1.f + __expf(-r2));
    }
}

// ---------------------------------------------------------------------------
__global__ void __launch_bounds__(128, 4)
nerf_render_kernel(const float* __restrict__ rays_o, const float* __restrict__ rays_d,
                   const float* __restrict__ W1, const float* __restrict__ b1,
                   const float* __restrict__ W2, const float* __restrict__ b2,
                   const float* __restrict__ Wsig, const float* __restrict__ Wrgb,
                   const float* __restrict__ brgb,
                   float* __restrict__ out, int nrays)
{
    extern __shared__ float sm[];
    const int tid = threadIdx.x;
    const int ray = blockIdx.x;
    const uint32_t smem_base = smem_u32(sm);

    // ---- cooperative weight load ----
    for (int i = tid; i < 192; i += 128) sm[O_W1 + i] = W1[i];
    if (tid < 64) { sm[O_B1 + tid] = b1[tid]; sm[O_B2 + tid] = b2[tid]; sm[O_WSIG + tid] = Wsig[tid]; }
    for (int i = tid; i < 201; i += 128) sm[O_WRGB + i] = Wrgb[i];
    if (tid < 3) sm[O_BRGB + tid] = brgb[tid];

    // W2 split -> B planes: B[j][k] = W2[k][j], 128B rows, chunk-XOR swizzle
    {
        char* bhi = (char*)(sm + O_BHI);
        char* blo = (char*)(sm + O_BLO);
#pragma unroll
        for (int t = 0; t < 32; t++) {
            int i = tid + t * 128;
            int k = i >> 6, j = i & 63;
            float v = W2[i];
            __nv_bfloat16 bh = __float2bfloat16(v);
            float fh = __bfloat162float(bh);
            __nv_bfloat16 bl = __float2bfloat16(v - fh);
            uint32_t byte = (uint32_t)(j * 128 + k * 2);
            uint32_t sw = byte ^ ((byte >> 3) & 0x70);
            *(__nv_bfloat16*)(bhi + sw) = bh;
            *(__nv_bfloat16*)(blo + sw) = bl;
        }
    }
    __syncthreads();   // WSIG/WRGB visible for prepack

    // ---- prepack head-MMA B-fragments (ray-invariant, once per CTA) ----
    {
        int ks = tid >> 5, lane = tid & 31;
        int tig = lane & 3, g = lane >> 2;
        int kb = 16 * ks + 2 * tig;
        float w0, w1, w2, w3;
        if (g == 0) {
            w0 = sm[O_WSIG + kb];     w1 = sm[O_WSIG + kb + 1];
            w2 = sm[O_WSIG + kb + 8]; w3 = sm[O_WSIG + kb + 9];
        } else if (g < 4) {
            int ch = g - 1;
            w0 = sm[O_WRGB + 3 * kb + ch];       w1 = sm[O_WRGB + 3 * (kb + 1) + ch];
            w2 = sm[O_WRGB + 3 * (kb + 8) + ch]; w3 = sm[O_WRGB + 3 * (kb + 9) + ch];
        } else {
            w0 = w1 = w2 = w3 = 0.f;
        }
        uint32_t bh0 = pack_bf16x2(w0, w1);
        uint32_t bh1 = pack_bf16x2(w2, w3);
        uint32_t bl0 = pack_bf16x2_res(w0, w1, bh0);
        uint32_t bl1 = pack_bf16x2_res(w2, w3, bh1);
        *(uint4*)(sm + O_HB + tid * 4) = make_uint4(bh0, bh1, bl0, bl1);
    }

    // ---- per-ray setup ----
    const float ox = rays_o[ray * 3 + 0], oy = rays_o[ray * 3 + 1], oz = rays_o[ray * 3 + 2];
    const float dx = rays_d[ray * 3 + 0], dy = rays_d[ray * 3 + 1], dz = rays_d[ray * 3 + 2];

    float near = -3.0e38f, far = 3.0e38f;
    {
        float o3[3] = {ox, oy, oz}, d3[3] = {dx, dy, dz};
#pragma unroll
        for (int c = 0; c < 3; c++) {
            float den = d3[c] + 1e-15f;
            float tmn = (-BOUND - o3[c]) / den;
            float tmx = ( BOUND - o3[c]) / den;
            near = fmaxf(near, fminf(tmn, tmx));
            far  = fminf(far,  fmaxf(tmn, tmx));
        }
        if (far < near) { near = 1e9f; far = 1e9f; }
        near = fmaxf(near, 0.05f);
    }
    const float span = far - near;
    const float sample_dist = span / (float)NS;

    float* sZ   = sm + O_Z;
    float* sSig = sm + O_SIG;
    float* sRGB = sm + O_RGB;
    float* sBuf = sm + O_BUF;
    float* sC   = sm + O_C;
    float* sA   = sm + O_A;
    float* sRed = sm + O_RED;
    float* sWT  = sm + O_WT;

    // dir-dependent head terms
    const float dirR0 = fmaf(dx, sm[O_WRGB + 64 * 3 + 0], fmaf(dy, sm[O_WRGB + 65 * 3 + 0], fmaf(dz, sm[O_WRGB + 66 * 3 + 0], sm[O_BRGB + 0])));
    const float dirR1 = fmaf(dx, sm[O_WRGB + 64 * 3 + 1], fmaf(dy, sm[O_WRGB + 65 * 3 + 1], fmaf(dz, sm[O_WRGB + 66 * 3 + 1], sm[O_BRGB + 1])));
    const float dirR2 = fmaf(dx, sm[O_WRGB + 64 * 3 + 2], fmaf(dy, sm[O_WRGB + 65 * 3 + 2], fmaf(dz, sm[O_WRGB + 66 * 3 + 2], sm[O_BRGB + 2])));

    // ========== Phase A: coarse ==========
    sZ[tid] = near + span * ((float)tid * (1.f / 127.f));
    __syncthreads();   // sZ + HB prepack visible
    field_pass(sm, smem_base, tid, ox, oy, oz, dx, dy, dz, dirR0, dirR1, dirR2, 0);
    __syncthreads();

    // ========== Phase B: weights -> pdf -> inverse-CDF scatter ==========
    {
        float delta = (tid < NS - 1) ? (sZ[tid + 1] - sZ[tid]) : sample_dist;
        float alpha = 1.f - __expf(-delta * sSig[tid]);
        float shifted = 1.f - alpha + 1e-15f;
        if (tid < NS - 1) sC[tid] = sZ[tid] + 0.5f * delta;
        float Tincl = scan128_mul(shifted, tid, sWT);   // sync inside
        float w = alpha * (Tincl / shifted);            // exclusive via division
        sA[tid] = w;
        __syncthreads();
        float pv = (tid < 126) ? (sA[tid + 1] + 1e-5f) : 0.f;
        float csum = scan128_add(pv, tid, sWT);         // sync inside
        sBuf[tid] = csum;
        __syncthreads();
        const float invS = 1.f / sBuf[125];

        // thread tid = bin: u in [c[tid], c[tid+1]) -> scatter fine z
        if (tid < 127) {
            float clo = (tid == 0) ? 0.f : sBuf[tid - 1] * invS;
            bool last = (tid == 126);
            float chi = last ? 3.0e38f : sBuf[tid] * invS;
            int t0 = max(0, (int)ceilf(fmaf(128.f, clo, -0.5f)));
            int t1 = last ? 127 : (min(128, (int)ceilf(fmaf(128.f, chi, -0.5f))) - 1);
            if (t0 <= t1) {
                int above = min(tid + 1, 126);
                float cb = clo;
                float ca = sBuf[above - 1] * invS;
                float bb = sC[tid], ba = sC[above];
                float den = ca - cb;
                if (den < 1e-5f) den = 1.f;
                float scale = (ba - bb) / den;
                for (int t = t0; t <= t1; t++) {
                    float u = 0.00390625f + (float)t * 0.0078125f;
                    sZ[NS + t] = bb + (u - cb) * scale;
                }
            }
        }
    }
    __syncthreads();

    // ========== Phase C: fine ==========
    float new_z = sZ[NS + tid];
    field_pass(sm, smem_base, tid, ox, oy, oz, dx, dy, dz, dirR0, dirR1, dirR2, NS);
    __syncthreads();

    // ========== Phase D: stable merge of two sorted runs ==========
    {
        float zA = sZ[tid], zB = new_z;
        int lo = 0, hi = NS;
        while (lo < hi) { int m = (lo + hi) >> 1; if (sZ[NS + m] < zA) lo = m + 1; else hi = m; }
        int posA = tid + lo;
        lo = 0; hi = NS;
        while (lo < hi) { int m = (lo + hi) >> 1; if (sZ[m] <= zB) lo = m + 1; else hi = m; }
        int posB = tid + lo;

        float sgA = sSig[tid], sgB = sSig[NS + tid];
        float a0 = sRGB[tid * 3 + 0], a1 = sRGB[tid * 3 + 1], a2 = sRGB[tid * 3 + 2];
        float b0 = sRGB[(NS + tid) * 3 + 0], b1v = sRGB[(NS + tid) * 3 + 1], b2v = sRGB[(NS + tid) * 3 + 2];
        __syncthreads();
        sZ[posA] = zA; sSig[posA] = sgA;
        sRGB[posA * 3 + 0] = a0; sRGB[posA * 3 + 1] = a1; sRGB[posA * 3 + 2] = a2;
        sZ[posB] = zB; sSig[posB] = sgB;
        sRGB[posB * 3 + 0] = b0; sRGB[posB * 3 + 1] = b1v; sRGB[posB * 3 + 2] = b2v;
        __syncthreads();
    }

    // ========== Phase E: final composite ==========
    {
        const int i0 = 2 * tid, i1 = 2 * tid + 1;
        float d0 = sZ[i0 + 1] - sZ[i0];
        float d1 = (i1 < NT - 1) ? (sZ[i1 + 1] - sZ[i1]) : sample_dist;
        float al0 = 1.f - __expf(-d0 * sSig[i0]);
        float al1 = 1.f - __expf(-d1 * sSig[i1]);
        float s0 = 1.f - al0 + 1e-15f;
        float s1 = 1.f - al1 + 1e-15f;

        int lane = tid & 31, w = tid >> 5;
        float p = s0 * s1;
        float pincl = warp_scan_mul(p, lane);
        if (lane == 31) sWT[w] = pincl;
        __syncthreads();
        float pre = 1.f;
#pragma unroll
        for (int k = 0; k < 3; k++) if (k < w) pre *= sWT[k];
        float e = __shfl_up_sync(0xffffffffu, pincl, 1);
        e = (lane == 0) ? 1.f : e;
        e *= pre;
        float w0 = al0 * e;
        float w1 = al1 * e * s0;

        float v0 = clipf((sZ[i0] - near) / span, 0.f, 1.f);
        float v1 = clipf((sZ[i1] - near) / span, 0.f, 1.f);
        float wsum = w0 + w1;
        float dsum = w0 * v0 + w1 * v1;
        float rs0 = fmaf(w0, sRGB[i0 * 3 + 0], w1 * sRGB[i1 * 3 + 0]);
        float rs1 = fmaf(w0, sRGB[i0 * 3 + 1], w1 * sRGB[i1 * 3 + 1]);
        float rs2 = fmaf(w0, sRGB[i0 * 3 + 2], w1 * sRGB[i1 * 3 + 2]);

#pragma unroll
        for (int o = 16; o > 0; o >>= 1) {
            wsum += __shfl_down_sync(0xffffffffu, wsum, o);
            dsum += __shfl_down_sync(0xffffffffu, dsum, o);
            rs0  += __shfl_down_sync(0xffffffffu, rs0, o);
            rs1  += __shfl_down_sync(0xffffffffu, rs1, o);
            rs2  += __shfl_down_sync(0xffffffffu, rs2, o);
        }
        if (lane == 0) {
            sRed[w * 5 + 0] = wsum; sRed[w * 5 + 1] = dsum;
            sRed[w * 5 + 2] = rs0;  sRed[w * 5 + 3] = rs1; sRed[w * 5 + 4] = rs2;
        }
        __syncthreads();
        if (tid == 0) {
            float W = 0, D = 0, R0 = 0, R1 = 0, R2 = 0;
#pragma unroll
            for (int w2 = 0; w2 < 4; w2++) {
                W += sRed[w2 * 5 + 0]; D += sRed[w2 * 5 + 1];
                R0 += sRed[w2 * 5 + 2]; R1 += sRed[w2 * 5 + 3]; R2 += sRed[w2 * 5 + 4];
            }
            float bg = 1.f - W;
            out[ray] = D;
            out[nrays + ray * 3 + 0] = R0 + bg;
            out[nrays + ray * 3 + 1] = R1 + bg;
            out[nrays + ray * 3 + 2] = R2 + bg;
        }
    }
}

extern "C" void kernel_launch(void* const* d_in, const int* in_sizes, int n_in,
                              void* d_out, int out_size) {
    const float* rays_o = (const float*)d_in[0];
    const float* rays_d = (const float*)d_in[1];
    const float* W1   = (const float*)d_in[2];
    const float* b1   = (const float*)d_in[3];
    const float* W2   = (const float*)d_in[4];
    const float* b2   = (const float*)d_in[5];
    const float* Wsig = (const float*)d_in[6];
    const float* Wrgb = (const float*)d_in[7];
    const float* brgb = (const float*)d_in[8];
    float* out = (float*)d_out;

    int nrays = in_sizes[0] / 3;   // B*N
    size_t smem_bytes = (size_t)SMEM_FLOATS * sizeof(float);
    cudaFuncSetAttribute(nerf_render_kernel,
                         cudaFuncAttributeMaxDynamicSharedMemorySize, (int)smem_bytes);
    nerf_render_kernel<<<nrays, 128, smem_bytes>>>(rays_o, rays_d, W1, b1, W2, b2,
                                                   Wsig, Wrgb, brgb, out, nrays);
}

// round 13
// speedup vs baseline: 1.2990x; 1.1934x over previous
#include <cuda_runtime.h>
#include <cuda_fp16.h>
#include <math.h>
#include <stdint.h>

#define NS 128
#define NT 256
#define BOUND 2.0f

// ---- dynamic shared memory layout (float indices) ----
#define O_W1    0        // 192
#define O_B1    192      // 64
#define O_WSIG  256      // 64
#define O_WRGB  320      // 201 (+3 pad)
#define O_BRGB  524      // 4
#define O_B2    528      // 64
#define O_Z     592      // 256
#define O_SIG   848      // 256
#define O_RGB   1104     // 768
#define O_RED   1872     // 32
#define O_WT    1904     // 16
#define O_BUF   1920     // 128
#define O_C     2048     // 128
#define O_A     2176     // 128
#define O_HD    2304     // 512 (4 warps x [32 rows][4 heads])
#define O_HB    2816     // 256 (prepacked head B-frags: [4 ks][32 lanes] x uint2)
#define O_BHI   3072     // 2048 floats = 64 rows x 128B (W2^T fp16 hi), 1024B-aligned
#define SMEM_FLOATS 5120    // 20480 bytes

__device__ __forceinline__ uint32_t smem_u32(const void* p) {
    uint32_t a;
    asm("{ .reg .u64 t; cvta.to.shared.u64 t, %1; cvt.u32.u64 %0, t; }" : "=r"(a) : "l"(p));
    return a;
}

#define LDM_X4(r, addr) \
    asm volatile("ldmatrix.sync.aligned.m8n8.x4.shared.b16 {%0,%1,%2,%3}, [%4];" \
        : "=r"((r)[0]), "=r"((r)[1]), "=r"((r)[2]), "=r"((r)[3]) : "r"(addr))

#define MMA16816(d, a, b0, b1) \
    asm volatile("mma.sync.aligned.m16n8k16.row.col.f32.f16.f16.f32 " \
        "{%0,%1,%2,%3}, {%4,%5,%6,%7}, {%8,%9}, {%0,%1,%2,%3};" \
        : "+f"((d)[0]), "+f"((d)[1]), "+f"((d)[2]), "+f"((d)[3]) \
        : "r"((a)[0]), "r"((a)[1]), "r"((a)[2]), "r"((a)[3]), "r"(b0), "r"(b1))

// packed dual-FMA (sm_103a f32x2)
__device__ __forceinline__ float2 ffma2(float2 a, float2 b, float2 c) {
    float2 d;
    asm("fma.rn.f32x2 %0, %1, %2, %3;"
        : "=l"(reinterpret_cast<unsigned long long&>(d))
        : "l"(reinterpret_cast<unsigned long long&>(a)),
          "l"(reinterpret_cast<unsigned long long&>(b)),
          "l"(reinterpret_cast<unsigned long long&>(c)));
    return d;
}
// pack two f32 -> f16x2 (lo half = x, hi half = y)
__device__ __forceinline__ uint32_t pack_f16x2(float lo, float hi) {
    uint32_t w;
    asm("cvt.rn.f16x2.f32 %0, %1, %2;" : "=r"(w) : "f"(hi), "f"(lo));
    return w;
}
// residual pair after fp16 rounding: (x,y) - unpack(pack(x,y))
__device__ __forceinline__ uint32_t pack_f16x2_res(float x, float y, uint32_t hw) {
    __half2 h = *reinterpret_cast<__half2*>(&hw);
    float2 f = __half22float2(h);   // .x = low half
    return pack_f16x2(x - f.x, y - f.y);
}

__device__ __forceinline__ float clipf(float x, float lo, float hi) {
    return x < lo ? lo : (x > hi ? hi : x);
}

// ---- warp-shuffle scans ----
__device__ __forceinline__ float warp_scan_mul(float v, int lane) {
#pragma unroll
    for (int o = 1; o < 32; o <<= 1) {
        float t = __shfl_up_sync(0xffffffffu, v, o);
        if (lane >= o) v *= t;
    }
    return v;
}
__device__ __forceinline__ float warp_scan_add(float v, int lane) {
#pragma unroll
    for (int o = 1; o < 32; o <<= 1) {
        float t = __shfl_up_sync(0xffffffffu, v, o);
        if (lane >= o) v += t;
    }
    return v;
}
__device__ __forceinline__ float scan128_mul(float v, int tid, float* wt) {
    int lane = tid & 31, w = tid >> 5;
    float s = warp_scan_mul(v, lane);
    if (lane == 31) wt[w] = s;
    __syncthreads();
    float pre = 1.f;
#pragma unroll
    for (int k = 0; k < 3; k++) if (k < w) pre *= wt[k];
    return s * pre;
}
__device__ __forceinline__ float scan128_add(float v, int tid, float* wt) {
    int lane = tid & 31, w = tid >> 5;
    float s = warp_scan_add(v, lane);
    if (lane == 31) wt[w] = s;
    __syncthreads();
    float pre = 0.f;
#pragma unroll
    for (int k = 0; k < 3; k++) if (k < w) pre += wt[k];
    return s + pre;
}

// ---------------------------------------------------------------------------
// One field pass for 128 samples. Warp w owns rows 32w..32w+31.
// Layer 1 computed directly in m16n8k16 A-fragment layout (no SMEM staging).
// fp16 2-term split: D = Ahi*Bhi + Alo*Bhi (B residual dropped; error ~2^-11
// per product, compressed ~20x by the downstream pipeline).
// ---------------------------------------------------------------------------
__device__ __forceinline__ void field_pass(
    float* sm, uint32_t smem_base, int tid,
    float ox, float oy, float oz, float dx, float dy, float dz,
    float dirR0, float dirR1, float dirR2, int outBase)
{
    const int lane = tid & 31;
    const int wid = tid >> 5;
    const int c = lane & 3, g = lane >> 2;
    const int m0 = 32 * wid;

    const int br = (lane & 7) + ((lane >> 4) << 3);    // B row within n16 group
    const int bkh = (lane >> 3) & 1;                   // B k-half
    const uint32_t bHiBase = smem_base + O_BHI * 4;

    // ---- per-fragment ray points: rows m0 + 8i + g, i = 0..3 ----
    float pxs[4], pys[4], pzs[4];
#pragma unroll
    for (int i = 0; i < 4; i++) {
        float z = sm[O_Z + outBase + m0 + 8 * i + g];
        pxs[i] = clipf(fmaf(dx, z, ox), -BOUND, BOUND);
        pys[i] = clipf(fmaf(dy, z, oy), -BOUND, BOUND);
        pzs[i] = clipf(fmaf(dz, z, oz), -BOUND, BOUND);
    }

    // ---- warp MMA: D[32][64] = Ahi*Bhi + Alo*Bhi ----
    float d[2][8][4];
#pragma unroll
    for (int mt = 0; mt < 2; mt++)
#pragma unroll
        for (int n = 0; n < 8; n++)
#pragma unroll
            for (int e = 0; e < 4; e++) d[mt][n][e] = 0.f;

    const float2* w1p = (const float2*)(sm + O_W1);
    const float2* b1p = (const float2*)(sm + O_B1);

#pragma unroll
    for (int ks = 0; ks < 4; ks++) {
        // A-fragments computed in registers (layer 1, fp16 hi/lo split)
        uint32_t ahi[2][4], alo[2][4];
        const int p0 = 8 * ks + c, p1 = p0 + 4;
        float2 W0x = w1p[p0],      W1x = w1p[p1];
        float2 W0y = w1p[32 + p0], W1y = w1p[32 + p1];
        float2 W0z = w1p[64 + p0], W1z = w1p[64 + p1];
        float2 B0  = b1p[p0],      B1  = b1p[p1];
#pragma unroll
        for (int mt = 0; mt < 2; mt++) {
#pragma unroll
            for (int rr = 0; rr < 2; rr++) {
                int i = 2 * mt + rr;
                float2 PX = make_float2(pxs[i], pxs[i]);
                float2 PY = make_float2(pys[i], pys[i]);
                float2 PZ = make_float2(pzs[i], pzs[i]);
                float2 v0 = ffma2(PX, W0x, ffma2(PY, W0y, ffma2(PZ, W0z, B0)));
                float2 v1 = ffma2(PX, W1x, ffma2(PY, W1y, ffma2(PZ, W1z, B1)));
                v0.x = fmaxf(v0.x, 0.f); v0.y = fmaxf(v0.y, 0.f);
                v1.x = fmaxf(v1.x, 0.f); v1.y = fmaxf(v1.y, 0.f);
                uint32_t h0 = pack_f16x2(v0.x, v0.y);
                uint32_t h1 = pack_f16x2(v1.x, v1.y);
                ahi[mt][0 + rr] = h0;
                ahi[mt][2 + rr] = h1;
                alo[mt][0 + rr] = pack_f16x2_res(v0.x, v0.y, h0);
                alo[mt][2 + rr] = pack_f16x2_res(v1.x, v1.y, h1);
            }
        }
#pragma unroll
        for (int np = 0; np < 4; np++) {
            uint32_t bh[4];
            uint32_t boff = (uint32_t)(16 * np + br) * 128u +
                            (uint32_t)(((2 * ks + bkh) ^ (br & 7)) << 4);
            LDM_X4(bh, bHiBase + boff);
            // term-major issue: accumulator reuse distance 4
            MMA16816(d[0][2 * np + 0], ahi[0], bh[0], bh[1]);
            MMA16816(d[0][2 * np + 1], ahi[0], bh[2], bh[3]);
            MMA16816(d[1][2 * np + 0], ahi[1], bh[0], bh[1]);
            MMA16816(d[1][2 * np + 1], ahi[1], bh[2], bh[3]);
            MMA16816(d[0][2 * np + 0], alo[0], bh[0], bh[1]);
            MMA16816(d[0][2 * np + 1], alo[0], bh[2], bh[3]);
            MMA16816(d[1][2 * np + 0], alo[1], bh[0], bh[1]);
            MMA16816(d[1][2 * np + 1], alo[1], bh[2], bh[3]);
        }
    }

    // ---- head MMA epilogue: heads[128][8] = relu(D+b2) @ Whead[64][8] ----
    {
        float d2[2][4];
#pragma unroll
        for (int mt = 0; mt < 2; mt++)
#pragma unroll
            for (int e = 0; e < 4; e++) d2[mt][e] = 0.f;

#pragma unroll
        for (int ks = 0; ks < 4; ks++) {
            uint2 hb = *(const uint2*)(sm + O_HB + (ks * 32 + lane) * 2);
            uint32_t bh0 = hb.x, bh1 = hb.y;

            float2 b2a = *(const float2*)(sm + O_B2 + 16 * ks + 2 * c);
            float2 b2b = *(const float2*)(sm + O_B2 + 16 * ks + 8 + 2 * c);

            uint32_t ah[2][4], al[2][4];
#pragma unroll
            for (int mt = 0; mt < 2; mt++) {
                float e00 = fmaxf(d[mt][2 * ks][0] + b2a.x, 0.f);
                float e01 = fmaxf(d[mt][2 * ks][1] + b2a.y, 0.f);
                float e02 = fmaxf(d[mt][2 * ks][2] + b2a.x, 0.f);
                float e03 = fmaxf(d[mt][2 * ks][3] + b2a.y, 0.f);
                float e10 = fmaxf(d[mt][2 * ks + 1][0] + b2b.x, 0.f);
                float e11 = fmaxf(d[mt][2 * ks + 1][1] + b2b.y, 0.f);
                float e12 = fmaxf(d[mt][2 * ks + 1][2] + b2b.x, 0.f);
                float e13 = fmaxf(d[mt][2 * ks + 1][3] + b2b.y, 0.f);

                ah[mt][0] = pack_f16x2(e00, e01);
                ah[mt][1] = pack_f16x2(e02, e03);
                ah[mt][2] = pack_f16x2(e10, e11);
                ah[mt][3] = pack_f16x2(e12, e13);
                al[mt][0] = pack_f16x2_res(e00, e01, ah[mt][0]);
                al[mt][1] = pack_f16x2_res(e02, e03, ah[mt][1]);
                al[mt][2] = pack_f16x2_res(e10, e11, ah[mt][2]);
                al[mt][3] = pack_f16x2_res(e12, e13, ah[mt][3]);
            }
            // term-major: reuse distance 2
            MMA16816(d2[0], ah[0], bh0, bh1);
            MMA16816(d2[1], ah[1], bh0, bh1);
            MMA16816(d2[0], al[0], bh0, bh1);
            MMA16816(d2[1], al[1], bh0, bh1);
        }

        // stage heads to warp-private scratch
        float* sHD = sm + O_HD + wid * 128;   // [32 rows][4 heads]
        if (c < 2) {
#pragma unroll
            for (int mt = 0; mt < 2; mt++) {
                *(float2*)(sHD + (16 * mt + g) * 4 + 2 * c)     = make_float2(d2[mt][0], d2[mt][1]);
                *(float2*)(sHD + (16 * mt + 8 + g) * 4 + 2 * c) = make_float2(d2[mt][2], d2[mt][3]);
            }
        }
        __syncwarp();

        // finalize: thread = its own sample
        float4 hd = *(const float4*)(sHD + lane * 4);
        float sg = hd.x;
        float sigma = fmaxf(sg, 0.f) + __logf(1.f + __expf(-fabsf(sg)));
        float r0 = hd.y + dirR0;
        float r1 = hd.z + dirR1;
        float r2 = hd.w + dirR2;
        sm[O_SIG + outBase + tid] = sigma;
        sm[O_RGB + (outBase + tid) * 3 + 0] = 1.f / (1.f + __expf(-r0));
        sm[O_RGB + (outBase + tid) * 3 + 1] = 1.f / (1.f + __expf(-r1));
        sm[O_RGB + (outBase + tid) * 3 + 2] = 1.f / (1.f + __expf(-r2));
    }
}

// ---------------------------------------------------------------------------
__global__ void __launch_bounds__(128, 4)
nerf_render_kernel(const float* __restrict__ rays_o, const float* __restrict__ rays_d,
                   const float* __restrict__ W1, const float* __restrict__ b1,
                   const float* __restrict__ W2, const float* __restrict__ b2,
                   const float* __restrict__ Wsig, const float* __restrict__ Wrgb,
                   const float* __restrict__ brgb,
                   float* __restrict__ out, int nrays)
{
    extern __shared__ float sm[];
    const int tid = threadIdx.x;
    const int ray = blockIdx.x;
    const uint32_t smem_base = smem_u32(sm);

    // ---- cooperative weight load ----
    for (int i = tid; i < 192; i += 128) sm[O_W1 + i] = W1[i];
    if (tid < 64) { sm[O_B1 + tid] = b1[tid]; sm[O_B2 + tid] = b2[tid]; sm[O_WSIG + tid] = Wsig[tid]; }
    for (int i = tid; i < 201; i += 128) sm[O_WRGB + i] = Wrgb[i];
    if (tid < 3) sm[O_BRGB + tid] = brgb[tid];

    // W2 -> fp16 B plane: B[j][k] = W2[k][j], 128B rows, chunk-XOR swizzle
    {
        char* bhi = (char*)(sm + O_BHI);
#pragma unroll
        for (int t = 0; t < 32; t++) {
            int i = tid + t * 128;
            int k = i >> 6, j = i & 63;
            __half bh = __float2half_rn(W2[i]);
            uint32_t byte = (uint32_t)(j * 128 + k * 2);
            uint32_t sw = byte ^ ((byte >> 3) & 0x70);
            *(__half*)(bhi + sw) = bh;
        }
    }
    __syncthreads();   // WSIG/WRGB visible for prepack

    // ---- prepack head-MMA B-fragments (ray-invariant, once per CTA) ----
    {
        int ks = tid >> 5, lane = tid & 31;
        int tig = lane & 3, g = lane >> 2;
        int kb = 16 * ks + 2 * tig;
        float w0, w1, w2, w3;
        if (g == 0) {
            w0 = sm[O_WSIG + kb];     w1 = sm[O_WSIG + kb + 1];
            w2 = sm[O_WSIG + kb + 8]; w3 = sm[O_WSIG + kb + 9];
        } else if (g < 4) {
            int ch = g - 1;
            w0 = sm[O_WRGB + 3 * kb + ch];       w1 = sm[O_WRGB + 3 * (kb + 1) + ch];
            w2 = sm[O_WRGB + 3 * (kb + 8) + ch]; w3 = sm[O_WRGB + 3 * (kb + 9) + ch];
        } else {
            w0 = w1 = w2 = w3 = 0.f;
        }
        uint32_t bh0 = pack_f16x2(w0, w1);
        uint32_t bh1 = pack_f16x2(w2, w3);
        *(uint2*)(sm + O_HB + tid * 2) = make_uint2(bh0, bh1);
    }

    // ---- per-ray setup ----
    const float ox = rays_o[ray * 3 + 0], oy = rays_o[ray * 3 + 1], oz = rays_o[ray * 3 + 2];
    const float dx = rays_d[ray * 3 + 0], dy = rays_d[ray * 3 + 1], dz = rays_d[ray * 3 + 2];

    float near = -3.0e38f, far = 3.0e38f;
    {
        float o3[3] = {ox, oy, oz}, d3[3] = {dx, dy, dz};
#pragma unroll
        for (int c = 0; c < 3; c++) {
            float den = d3[c] + 1e-15f;
            float tmn = (-BOUND - o3[c]) / den;
            float tmx = ( BOUND - o3[c]) / den;
            near = fmaxf(near, fminf(tmn, tmx));
            far  = fminf(far,  fmaxf(tmn, tmx));
        }
        if (far < near) { near = 1e9f; far = 1e9f; }
        near = fmaxf(near, 0.05f);
    }
    const float span = far - near;
    const float sample_dist = span / (float)NS;

    float* sZ   = sm + O_Z;
    float* sSig = sm + O_SIG;
    float* sRGB = sm + O_RGB;
    float* sBuf = sm + O_BUF;
    float* sC   = sm + O_C;
    float* sA   = sm + O_A;
    float* sRed = sm + O_RED;
    float* sWT  = sm + O_WT;

    // dir-dependent head terms
    const float dirR0 = fmaf(dx, sm[O_WRGB + 64 * 3 + 0], fmaf(dy, sm[O_WRGB + 65 * 3 + 0], fmaf(dz, sm[O_WRGB + 66 * 3 + 0], sm[O_BRGB + 0])));
    const float dirR1 = fmaf(dx, sm[O_WRGB + 64 * 3 + 1], fmaf(dy, sm[O_WRGB + 65 * 3 + 1], fmaf(dz, sm[O_WRGB + 66 * 3 + 1], sm[O_BRGB + 1])));
    const float dirR2 = fmaf(dx, sm[O_WRGB + 64 * 3 + 2], fmaf(dy, sm[O_WRGB + 65 * 3 + 2], fmaf(dz, sm[O_WRGB + 66 * 3 + 2], sm[O_BRGB + 2])));

    // ========== Phase A: coarse ==========
    sZ[tid] = near + span * ((float)tid * (1.f / 127.f));
    __syncthreads();   // sZ + HB prepack visible
    field_pass(sm, smem_base, tid, ox, oy, oz, dx, dy, dz, dirR0, dirR1, dirR2, 0);
    __syncthreads();

    // ========== Phase B: weights -> pdf -> inverse-CDF scatter ==========
    {
        float delta = (tid < NS - 1) ? (sZ[tid + 1] - sZ[tid]) : sample_dist;
        float alpha = 1.f - __expf(-delta * sSig[tid]);
        float shifted = 1.f - alpha + 1e-15f;
        if (tid < NS - 1) sC[tid] = sZ[tid] + 0.5f * delta;
        float Tincl = scan128_mul(shifted, tid, sWT);   // sync inside
        float w = alpha * (Tincl / shifted);            // exclusive via division
        sA[tid] = w;
        __syncthreads();
        float pv = (tid < 126) ? (sA[tid + 1] + 1e-5f) : 0.f;
        float csum = scan128_add(pv, tid, sWT);         // sync inside
        sBuf[tid] = csum;
        __syncthreads();
        const float invS = 1.f / sBuf[125];

        // thread tid = bin: u in [c[tid], c[tid+1]) -> scatter fine z
        if (tid < 127) {
            float clo = (tid == 0) ? 0.f : sBuf[tid - 1] * invS;
            bool last = (tid == 126);
            float chi = last ? 3.0e38f : sBuf[tid] * invS;
            int t0 = max(0, (int)ceilf(fmaf(128.f, clo, -0.5f)));
            int t1 = last ? 127 : (min(128, (int)ceilf(fmaf(128.f, chi, -0.5f))) - 1);
            if (t0 <= t1) {
                int above = min(tid + 1, 126);
                float cb = clo;
                float ca = sBuf[above - 1] * invS;
                float bb = sC[tid], ba = sC[above];
                float den = ca - cb;
                if (den < 1e-5f) den = 1.f;
                float scale = (ba - bb) / den;
                for (int t = t0; t <= t1; t++) {
                    float u = 0.00390625f + (float)t * 0.0078125f;
                    sZ[NS + t] = bb + (u - cb) * scale;
                }
            }
        }
    }
    __syncthreads();

    // ========== Phase C: fine ==========
    float new_z = sZ[NS + tid];
    field_pass(sm, smem_base, tid, ox, oy, oz, dx, dy, dz, dirR0, dirR1, dirR2, NS);
    __syncthreads();

    // ========== Phase D: stable merge of two sorted runs ==========
    {
        float zA = sZ[tid], zB = new_z;
        int lo = 0, hi = NS;
        while (lo < hi) { int m = (lo + hi) >> 1; if (sZ[NS + m] < zA) lo = m + 1; else hi = m; }
        int posA = tid + lo;
        lo = 0; hi = NS;
        while (lo < hi) { int m = (lo + hi) >> 1; if (sZ[m] <= zB) lo = m + 1; else hi = m; }
        int posB = tid + lo;

        float sgA = sSig[tid], sgB = sSig[NS + tid];
        float a0 = sRGB[tid * 3 + 0], a1 = sRGB[tid * 3 + 1], a2 = sRGB[tid * 3 + 2];
        float b0 = sRGB[(NS + tid) * 3 + 0], b1v = sRGB[(NS + tid) * 3 + 1], b2v = sRGB[(NS + tid) * 3 + 2];
        __syncthreads();
        sZ[posA] = zA; sSig[posA] = sgA;
        sRGB[posA * 3 + 0] = a0; sRGB[posA * 3 + 1] = a1; sRGB[posA * 3 + 2] = a2;
        sZ[posB] = zB; sSig[posB] = sgB;
        sRGB[posB * 3 + 0] = b0; sRGB[posB * 3 + 1] = b1v; sRGB[posB * 3 + 2] = b2v;
        __syncthreads();
    }

    // ========== Phase E: final composite ==========
    {
        const int i0 = 2 * tid, i1 = 2 * tid + 1;
        float d0 = sZ[i0 + 1] - sZ[i0];
        float d1 = (i1 < NT - 1) ? (sZ[i1 + 1] - sZ[i1]) : sample_dist;
        float al0 = 1.f - __expf(-d0 * sSig[i0]);
        float al1 = 1.f - __expf(-d1 * sSig[i1]);
        float s0 = 1.f - al0 + 1e-15f;
        float s1 = 1.f - al1 + 1e-15f;

        int lane = tid & 31, w = tid >> 5;
        float p = s0 * s1;
        float pincl = warp_scan_mul(p, lane);
        if (lane == 31) sWT[w] = pincl;
        __syncthreads();
        float pre = 1.f;
#pragma unroll
        for (int k = 0; k < 3; k++) if (k < w) pre *= sWT[k];
        float e = __shfl_up_sync(0xffffffffu, pincl, 1);
        e = (lane == 0) ? 1.f : e;
        e *= pre;
        float w0 = al0 * e;
        float w1 = al1 * e * s0;

        float v0 = clipf((sZ[i0] - near) / span, 0.f, 1.f);
        float v1 = clipf((sZ[i1] - near) / span, 0.f, 1.f);
        float wsum = w0 + w1;
        float dsum = w0 * v0 + w1 * v1;
        float rs0 = fmaf(w0, sRGB[i0 * 3 + 0], w1 * sRGB[i1 * 3 + 0]);
        float rs1 = fmaf(w0, sRGB[i0 * 3 + 1], w1 * sRGB[i1 * 3 + 1]);
        float rs2 = fmaf(w0, sRGB[i0 * 3 + 2], w1 * sRGB[i1 * 3 + 2]);

#pragma unroll
        for (int o = 16; o > 0; o >>= 1) {
            wsum += __shfl_down_sync(0xffffffffu, wsum, o);
            dsum += __shfl_down_sync(0xffffffffu, dsum, o);
            rs0  += __shfl_down_sync(0xffffffffu, rs0, o);
            rs1  += __shfl_down_sync(0xffffffffu, rs1, o);
            rs2  += __shfl_down_sync(0xffffffffu, rs2, o);
        }
        if (lane == 0) {
            sRed[w * 5 + 0] = wsum; sRed[w * 5 + 1] = dsum;
            sRed[w * 5 + 2] = rs0;  sRed[w * 5 + 3] = rs1; sRed[w * 5 + 4] = rs2;
        }
        __syncthreads();
        if (tid == 0) {
            float W = 0, D = 0, R0 = 0, R1 = 0, R2 = 0;
#pragma unroll
            for (int w2 = 0; w2 < 4; w2++) {
                W += sRed[w2 * 5 + 0]; D += sRed[w2 * 5 + 1];
                R0 += sRed[w2 * 5 + 2]; R1 += sRed[w2 * 5 + 3]; R2 += sRed[w2 * 5 + 4];
            }
            float bg = 1.f - W;
            out[ray] = D;
            out[nrays + ray * 3 + 0] = R0 + bg;
            out[nrays + ray * 3 + 1] = R1 + bg;
            out[nrays + ray * 3 + 2] = R2 + bg;
        }
    }
}

extern "C" void kernel_launch(void* const* d_in, const int* in_sizes, int n_in,
                              void* d_out, int out_size) {
    const float* rays_o = (const float*)d_in[0];
    const float* rays_d = (const float*)d_in[1];
    const float* W1   = (const float*)d_in[2];
    const float* b1   = (const float*)d_in[3];
    const float* W2   = (const float*)d_in[4];
    const float* b2   = (const float*)d_in[5];
    const float* Wsig = (const float*)d_in[6];
    const float* Wrgb = (const float*)d_in[7];
    const float* brgb = (const float*)d_in[8];
    float* out = (float*)d_out;

    int nrays = in_sizes[0] / 3;   // B*N
    size_t smem_bytes = (size_t)SMEM_FLOATS * sizeof(float);
    cudaFuncSetAttribute(nerf_render_kernel,
                         cudaFuncAttributeMaxDynamicSharedMemorySize, (int)smem_bytes);
    nerf_render_kernel<<<nrays, 128, smem_bytes>>>(rays_o, rays_d, W1, b1, W2, b2,
                                                   Wsig, Wrgb, brgb, out, nrays);
}

// round 14
// speedup vs baseline: 1.7345x; 1.3353x over previous
#include <cuda_runtime.h>
#include <cuda_fp16.h>
#include <math.h>
#include <stdint.h>

#define NS 128
#define NT 256
#define BOUND 2.0f

// ---- dynamic shared memory layout (float indices) ----
#define O_W1    0        // 192
#define O_B1    192      // 64
#define O_WSIG  256      // 64
#define O_WRGB  320      // 201 (+3 pad)
#define O_BRGB  524      // 4
#define O_B2    528      // 64
#define O_Z     592      // 256
#define O_SIG   848      // 256
#define O_RGB   1104     // 768
#define O_RED   1872     // 32
#define O_WT    1904     // 16
#define O_BUF   1920     // 128
#define O_C     2048     // 128
#define O_A     2176     // 128
#define O_HD    2304     // 512 (4 warps x [32 rows][4 heads])
#define O_HB    2816     // 256 (prepacked head B-frags: [4 ks][32 lanes] x uint2)
#define O_BHI   3072     // 2048 floats = 64 rows x 128B (W2^T fp16), 1024B-aligned
#define SMEM_FLOATS 5120    // 20480 bytes

__device__ __forceinline__ uint32_t smem_u32(const void* p) {
    uint32_t a;
    asm("{ .reg .u64 t; cvta.to.shared.u64 t, %1; cvt.u32.u64 %0, t; }" : "=r"(a) : "l"(p));
    return a;
}

#define LDM_X4(r, addr) \
    asm volatile("ldmatrix.sync.aligned.m8n8.x4.shared.b16 {%0,%1,%2,%3}, [%4];" \
        : "=r"((r)[0]), "=r"((r)[1]), "=r"((r)[2]), "=r"((r)[3]) : "r"(addr))

#define MMA16816(d, a, b0, b1) \
    asm volatile("mma.sync.aligned.m16n8k16.row.col.f32.f16.f16.f32 " \
        "{%0,%1,%2,%3}, {%4,%5,%6,%7}, {%8,%9}, {%0,%1,%2,%3};" \
        : "+f"((d)[0]), "+f"((d)[1]), "+f"((d)[2]), "+f"((d)[3]) \
        : "r"((a)[0]), "r"((a)[1]), "r"((a)[2]), "r"((a)[3]), "r"(b0), "r"(b1))

// packed dual-FMA (sm_103a f32x2)
__device__ __forceinline__ float2 ffma2(float2 a, float2 b, float2 c) {
    float2 d;
    asm("fma.rn.f32x2 %0, %1, %2, %3;"
        : "=l"(reinterpret_cast<unsigned long long&>(d))
        : "l"(reinterpret_cast<unsigned long long&>(a)),
          "l"(reinterpret_cast<unsigned long long&>(b)),
          "l"(reinterpret_cast<unsigned long long&>(c)));
    return d;
}
// pack two f32 -> f16x2 (lo half = x, hi half = y)
__device__ __forceinline__ uint32_t pack_f16x2(float lo, float hi) {
    uint32_t w;
    asm("cvt.rn.f16x2.f32 %0, %1, %2;" : "=r"(w) : "f"(hi), "f"(lo));
    return w;
}

__device__ __forceinline__ float clipf(float x, float lo, float hi) {
    return x < lo ? lo : (x > hi ? hi : x);
}

// ---- warp-shuffle scans ----
__device__ __forceinline__ float warp_scan_mul(float v, int lane) {
#pragma unroll
    for (int o = 1; o < 32; o <<= 1) {
        float t = __shfl_up_sync(0xffffffffu, v, o);
        if (lane >= o) v *= t;
    }
    return v;
}
__device__ __forceinline__ float warp_scan_add(float v, int lane) {
#pragma unroll
    for (int o = 1; o < 32; o <<= 1) {
        float t = __shfl_up_sync(0xffffffffu, v, o);
        if (lane >= o) v += t;
    }
    return v;
}
__device__ __forceinline__ float scan128_mul(float v, int tid, float* wt) {
    int lane = tid & 31, w = tid >> 5;
    float s = warp_scan_mul(v, lane);
    if (lane == 31) wt[w] = s;
    __syncthreads();
    float pre = 1.f;
#pragma unroll
    for (int k = 0; k < 3; k++) if (k < w) pre *= wt[k];
    return s * pre;
}
__device__ __forceinline__ float scan128_add(float v, int tid, float* wt) {
    int lane = tid & 31, w = tid >> 5;
    float s = warp_scan_add(v, lane);
    if (lane == 31) wt[w] = s;
    __syncthreads();
    float pre = 0.f;
#pragma unroll
    for (int k = 0; k < 3; k++) if (k < w) pre += wt[k];
    return s + pre;
}

// ---------------------------------------------------------------------------
// One field pass for 128 samples. Warp w owns rows 32w..32w+31.
// Layer 1 computed directly in m16n8k16 A-fragment layout (no SMEM staging).
// Pure fp16 single-term MMA (error ~2^-11 per product; measured pipeline
// compression gives final rel_err ~1e-4, 10x under the 1e-3 threshold).
// ---------------------------------------------------------------------------
__device__ __forceinline__ void field_pass(
    float* sm, uint32_t smem_base, int tid,
    float ox, float oy, float oz, float dx, float dy, float dz,
    float dirR0, float dirR1, float dirR2, int outBase)
{
    const int lane = tid & 31;
    const int wid = tid >> 5;
    const int c = lane & 3, g = lane >> 2;
    const int m0 = 32 * wid;

    const int br = (lane & 7) + ((lane >> 4) << 3);    // B row within n16 group
    const int bkh = (lane >> 3) & 1;                   // B k-half
    const uint32_t bHiBase = smem_base + O_BHI * 4;

    // ---- per-fragment ray points: rows m0 + 8i + g, i = 0..3 ----
    float pxs[4], pys[4], pzs[4];
#pragma unroll
    for (int i = 0; i < 4; i++) {
        float z = sm[O_Z + outBase + m0 + 8 * i + g];
        pxs[i] = clipf(fmaf(dx, z, ox), -BOUND, BOUND);
        pys[i] = clipf(fmaf(dy, z, oy), -BOUND, BOUND);
        pzs[i] = clipf(fmaf(dz, z, oz), -BOUND, BOUND);
    }

    // ---- warp MMA: D[32][64] = A(fp16) * B(fp16), fp32 accum ----
    float d[2][8][4];
#pragma unroll
    for (int mt = 0; mt < 2; mt++)
#pragma unroll
        for (int n = 0; n < 8; n++)
#pragma unroll
            for (int e = 0; e < 4; e++) d[mt][n][e] = 0.f;

    const float2* w1p = (const float2*)(sm + O_W1);
    const float2* b1p = (const float2*)(sm + O_B1);

#pragma unroll
    for (int ks = 0; ks < 4; ks++) {
        // A-fragments computed in registers (layer 1, fp16)
        uint32_t ahi[2][4];
        const int p0 = 8 * ks + c, p1 = p0 + 4;
        float2 W0x = w1p[p0],      W1x = w1p[p1];
        float2 W0y = w1p[32 + p0], W1y = w1p[32 + p1];
        float2 W0z = w1p[64 + p0], W1z = w1p[64 + p1];
        float2 B0  = b1p[p0],      B1  = b1p[p1];
#pragma unroll
        for (int mt = 0; mt < 2; mt++) {
#pragma unroll
            for (int rr = 0; rr < 2; rr++) {
                int i = 2 * mt + rr;
                float2 PX = make_float2(pxs[i], pxs[i]);
                float2 PY = make_float2(pys[i], pys[i]);
                float2 PZ = make_float2(pzs[i], pzs[i]);
                float2 v0 = ffma2(PX, W0x, ffma2(PY, W0y, ffma2(PZ, W0z, B0)));
                float2 v1 = ffma2(PX, W1x, ffma2(PY, W1y, ffma2(PZ, W1z, B1)));
                v0.x = fmaxf(v0.x, 0.f); v0.y = fmaxf(v0.y, 0.f);
                v1.x = fmaxf(v1.x, 0.f); v1.y = fmaxf(v1.y, 0.f);
                ahi[mt][0 + rr] = pack_f16x2(v0.x, v0.y);
                ahi[mt][2 + rr] = pack_f16x2(v1.x, v1.y);
            }
        }
#pragma unroll
        for (int np = 0; np < 4; np++) {
            uint32_t bh[4];
            uint32_t boff = (uint32_t)(16 * np + br) * 128u +
                            (uint32_t)(((2 * ks + bkh) ^ (br & 7)) << 4);
            LDM_X4(bh, bHiBase + boff);
            MMA16816(d[0][2 * np + 0], ahi[0], bh[0], bh[1]);
            MMA16816(d[0][2 * np + 1], ahi[0], bh[2], bh[3]);
            MMA16816(d[1][2 * np + 0], ahi[1], bh[0], bh[1]);
            MMA16816(d[1][2 * np + 1], ahi[1], bh[2], bh[3]);
        }
    }

    // ---- head MMA epilogue: heads[128][8] = relu(D+b2) @ Whead[64][8] ----
    {
        float d2[2][4];
#pragma unroll
        for (int mt = 0; mt < 2; mt++)
#pragma unroll
            for (int e = 0; e < 4; e++) d2[mt][e] = 0.f;

#pragma unroll
        for (int ks = 0; ks < 4; ks++) {
            uint2 hb = *(const uint2*)(sm + O_HB + (ks * 32 + lane) * 2);
            uint32_t bh0 = hb.x, bh1 = hb.y;

            float2 b2a = *(const float2*)(sm + O_B2 + 16 * ks + 2 * c);
            float2 b2b = *(const float2*)(sm + O_B2 + 16 * ks + 8 + 2 * c);

            uint32_t ah[2][4];
#pragma unroll
            for (int mt = 0; mt < 2; mt++) {
                float e00 = fmaxf(d[mt][2 * ks][0] + b2a.x, 0.f);
                float e01 = fmaxf(d[mt][2 * ks][1] + b2a.y, 0.f);
                float e02 = fmaxf(d[mt][2 * ks][2] + b2a.x, 0.f);
                float e03 = fmaxf(d[mt][2 * ks][3] + b2a.y, 0.f);
                float e10 = fmaxf(d[mt][2 * ks + 1][0] + b2b.x, 0.f);
                float e11 = fmaxf(d[mt][2 * ks + 1][1] + b2b.y, 0.f);
                float e12 = fmaxf(d[mt][2 * ks + 1][2] + b2b.x, 0.f);
                float e13 = fmaxf(d[mt][2 * ks + 1][3] + b2b.y, 0.f);

                ah[mt][0] = pack_f16x2(e00, e01);
                ah[mt][1] = pack_f16x2(e02, e03);
                ah[mt][2] = pack_f16x2(e10, e11);
                ah[mt][3] = pack_f16x2(e12, e13);
            }
            MMA16816(d2[0], ah[0], bh0, bh1);
            MMA16816(d2[1], ah[1], bh0, bh1);
        }

        // stage heads to warp-private scratch
        float* sHD = sm + O_HD + wid * 128;   // [32 rows][4 heads]
        if (c < 2) {
#pragma unroll
            for (int mt = 0; mt < 2; mt++) {
                *(float2*)(sHD + (16 * mt + g) * 4 + 2 * c)     = make_float2(d2[mt][0], d2[mt][1]);
                *(float2*)(sHD + (16 * mt + 8 + g) * 4 + 2 * c) = make_float2(d2[mt][2], d2[mt][3]);
            }
        }
        __syncwarp();

        // finalize: thread = its own sample
        float4 hd = *(const float4*)(sHD + lane * 4);
        float sg = hd.x;
        float sigma = fmaxf(sg, 0.f) + __logf(1.f + __expf(-fabsf(sg)));
        float r0 = hd.y + dirR0;
        float r1 = hd.z + dirR1;
        float r2 = hd.w + dirR2;
        sm[O_SIG + outBase + tid] = sigma;
        sm[O_RGB + (outBase + tid) * 3 + 0] = 1.f / (1.f + __expf(-r0));
        sm[O_RGB + (outBase + tid) * 3 + 1] = 1.f / (1.f + __expf(-r1));
        sm[O_RGB + (outBase + tid) * 3 + 2] = 1.f / (1.f + __expf(-r2));
    }
}

// ---------------------------------------------------------------------------
__global__ void __launch_bounds__(128, 4)
nerf_render_kernel(const float* __restrict__ rays_o, const float* __restrict__ rays_d,
                   const float* __restrict__ W1, const float* __restrict__ b1,
                   const float* __restrict__ W2, const float* __restrict__ b2,
                   const float* __restrict__ Wsig, const float* __restrict__ Wrgb,
                   const float* __restrict__ brgb,
                   float* __restrict__ out, int nrays)
{
    extern __shared__ float sm[];
    const int tid = threadIdx.x;
    const int ray = blockIdx.x;
    const uint32_t smem_base = smem_u32(sm);

    // ---- cooperative weight load ----
    for (int i = tid; i < 192; i += 128) sm[O_W1 + i] = W1[i];
    if (tid < 64) { sm[O_B1 + tid] = b1[tid]; sm[O_B2 + tid] = b2[tid]; sm[O_WSIG + tid] = Wsig[tid]; }
    for (int i = tid; i < 201; i += 128) sm[O_WRGB + i] = Wrgb[i];
    if (tid < 3) sm[O_BRGB + tid] = brgb[tid];

    // W2 -> fp16 B plane: B[j][k] = W2[k][j], 128B rows, chunk-XOR swizzle
    {
        char* bhi = (char*)(sm + O_BHI);
#pragma unroll
        for (int t = 0; t < 32; t++) {
            int i = tid + t * 128;
            int k = i >> 6, j = i & 63;
            __half bh = __float2half_rn(W2[i]);
            uint32_t byte = (uint32_t)(j * 128 + k * 2);
            uint32_t sw = byte ^ ((byte >> 3) & 0x70);
            *(__half*)(bhi + sw) = bh;
        }
    }
    __syncthreads();   // WSIG/WRGB visible for prepack

    // ---- prepack head-MMA B-fragments (ray-invariant, once per CTA) ----
    {
        int ks = tid >> 5, lane = tid & 31;
        int tig = lane & 3, g = lane >> 2;
        int kb = 16 * ks + 2 * tig;
        float w0, w1, w2, w3;
        if (g == 0) {
            w0 = sm[O_WSIG + kb];     w1 = sm[O_WSIG + kb + 1];
            w2 = sm[O_WSIG + kb + 8]; w3 = sm[O_WSIG + kb + 9];
        } else if (g < 4) {
            int ch = g - 1;
            w0 = sm[O_WRGB + 3 * kb + ch];       w1 = sm[O_WRGB + 3 * (kb + 1) + ch];
            w2 = sm[O_WRGB + 3 * (kb + 8) + ch]; w3 = sm[O_WRGB + 3 * (kb + 9) + ch];
        } else {
            w0 = w1 = w2 = w3 = 0.f;
        }
        uint32_t bh0 = pack_f16x2(w0, w1);
        uint32_t bh1 = pack_f16x2(w2, w3);
        *(uint2*)(sm + O_HB + tid * 2) = make_uint2(bh0, bh1);
    }

    // ---- per-ray setup ----
    const float ox = rays_o[ray * 3 + 0], oy = rays_o[ray * 3 + 1], oz = rays_o[ray * 3 + 2];
    const float dx = rays_d[ray * 3 + 0], dy = rays_d[ray * 3 + 1], dz = rays_d[ray * 3 + 2];

    float near = -3.0e38f, far = 3.0e38f;
    {
        float o3[3] = {ox, oy, oz}, d3[3] = {dx, dy, dz};
#pragma unroll
        for (int c = 0; c < 3; c++) {
            float den = d3[c] + 1e-15f;
            float tmn = (-BOUND - o3[c]) / den;
            float tmx = ( BOUND - o3[c]) / den;
            near = fmaxf(near, fminf(tmn, tmx));
            far  = fminf(far,  fmaxf(tmn, tmx));
        }
        if (far < near) { near = 1e9f; far = 1e9f; }
        near = fmaxf(near, 0.05f);
    }
    const float span = far - near;
    const float sample_dist = span / (float)NS;

    float* sZ   = sm + O_Z;
    float* sSig = sm + O_SIG;
    float* sRGB = sm + O_RGB;
    float* sBuf = sm + O_BUF;
    float* sC   = sm + O_C;
    float* sA   = sm + O_A;
    float* sRed = sm + O_RED;
    float* sWT  = sm + O_WT;

    // dir-dependent head terms
    const float dirR0 = fmaf(dx, sm[O_WRGB + 64 * 3 + 0], fmaf(dy, sm[O_WRGB + 65 * 3 + 0], fmaf(dz, sm[O_WRGB + 66 * 3 + 0], sm[O_BRGB + 0])));
    const float dirR1 = fmaf(dx, sm[O_WRGB + 64 * 3 + 1], fmaf(dy, sm[O_WRGB + 65 * 3 + 1], fmaf(dz, sm[O_WRGB + 66 * 3 + 1], sm[O_BRGB + 1])));
    const float dirR2 = fmaf(dx, sm[O_WRGB + 64 * 3 + 2], fmaf(dy, sm[O_WRGB + 65 * 3 + 2], fmaf(dz, sm[O_WRGB + 66 * 3 + 2], sm[O_BRGB + 2])));

    // ========== Phase A: coarse ==========
    sZ[tid] = near + span * ((float)tid * (1.f / 127.f));
    __syncthreads();   // sZ + HB prepack visible
    field_pass(sm, smem_base, tid, ox, oy, oz, dx, dy, dz, dirR0, dirR1, dirR2, 0);
    __syncthreads();

    // ========== Phase B: weights -> pdf -> inverse-CDF scatter ==========
    {
        float delta = (tid < NS - 1) ? (sZ[tid + 1] - sZ[tid]) : sample_dist;
        float alpha = 1.f - __expf(-delta * sSig[tid]);
        float shifted = 1.f - alpha + 1e-15f;
        if (tid < NS - 1) sC[tid] = sZ[tid] + 0.5f * delta;
        float Tincl = scan128_mul(shifted, tid, sWT);   // sync inside
        float w = alpha * (Tincl / shifted);            // exclusive via division
        sA[tid] = w;
        __syncthreads();
        float pv = (tid < 126) ? (sA[tid + 1] + 1e-5f) : 0.f;
        float csum = scan128_add(pv, tid, sWT);         // sync inside
        sBuf[tid] = csum;
        __syncthreads();
        const float invS = 1.f / sBuf[125];

        // thread tid = bin: u in [c[tid], c[tid+1]) -> scatter fine z
        if (tid < 127) {
            float clo = (tid == 0) ? 0.f : sBuf[tid - 1] * invS;
            bool last = (tid == 126);
            float chi = last ? 3.0e38f : sBuf[tid] * invS;
            int t0 = max(0, (int)ceilf(fmaf(128.f, clo, -0.5f)));
            int t1 = last ? 127 : (min(128, (int)ceilf(fmaf(128.f, chi, -0.5f))) - 1);
            if (t0 <= t1) {
                int above = min(tid + 1, 126);
                float cb = clo;
                float ca = sBuf[above - 1] * invS;
                float bb = sC[tid], ba = sC[above];
                float den = ca - cb;
                if (den < 1e-5f) den = 1.f;
                float scale = (ba - bb) / den;
                for (int t = t0; t <= t1; t++) {
                    float u = 0.00390625f + (float)t * 0.0078125f;
                    sZ[NS + t] = bb + (u - cb) * scale;
                }
            }
        }
    }
    __syncthreads();

    // ========== Phase C: fine ==========
    float new_z = sZ[NS + tid];
    field_pass(sm, smem_base, tid, ox, oy, oz, dx, dy, dz, dirR0, dirR1, dirR2, NS);
    __syncthreads();

    // ========== Phase D: stable merge of two sorted runs ==========
    {
        float zA = sZ[tid], zB = new_z;
        int lo = 0, hi = NS;
        while (lo < hi) { int m = (lo + hi) >> 1; if (sZ[NS + m] < zA) lo = m + 1; else hi = m; }
        int posA = tid + lo;
        lo = 0; hi = NS;
        while (lo < hi) { int m = (lo + hi) >> 1; if (sZ[m] <= zB) lo = m + 1; else hi = m; }
        int posB = tid + lo;

        float sgA = sSig[tid], sgB = sSig[NS + tid];
        float a0 = sRGB[tid * 3 + 0], a1 = sRGB[tid * 3 + 1], a2 = sRGB[tid * 3 + 2];
        float b0 = sRGB[(NS + tid) * 3 + 0], b1v = sRGB[(NS + tid) * 3 + 1], b2v = sRGB[(NS + tid) * 3 + 2];
        __syncthreads();
        sZ[posA] = zA; sSig[posA] = sgA;
        sRGB[posA * 3 + 0] = a0; sRGB[posA * 3 + 1] = a1; sRGB[posA * 3 + 2] = a2;
        sZ[posB] = zB; sSig[posB] = sgB;
        sRGB[posB * 3 + 0] = b0; sRGB[posB * 3 + 1] = b1v; sRGB[posB * 3 + 2] = b2v;
        __syncthreads();
    }

    // ========== Phase E: final composite ==========
    {
        const int i0 = 2 * tid, i1 = 2 * tid + 1;
        float d0 = sZ[i0 + 1] - sZ[i0];
        float d1 = (i1 < NT - 1) ? (sZ[i1 + 1] - sZ[i1]) : sample_dist;
        float al0 = 1.f - __expf(-d0 * sSig[i0]);
        float al1 = 1.f - __expf(-d1 * sSig[i1]);
        float s0 = 1.f - al0 + 1e-15f;
        float s1 = 1.f - al1 + 1e-15f;

        int lane = tid & 31, w = tid >> 5;
        float p = s0 * s1;
        float pincl = warp_scan_mul(p, lane);
        if (lane == 31) sWT[w] = pincl;
        __syncthreads();
        float pre = 1.f;
#pragma unroll
        for (int k = 0; k < 3; k++) if (k < w) pre *= sWT[k];
        float e = __shfl_up_sync(0xffffffffu, pincl, 1);
        e = (lane == 0) ? 1.f : e;
        e *= pre;
        float w0 = al0 * e;
        float w1 = al1 * e * s0;

        float v0 = clipf((sZ[i0] - near) / span, 0.f, 1.f);
        float v1 = clipf((sZ[i1] - near) / span, 0.f, 1.f);
        float wsum = w0 + w1;
        float dsum = w0 * v0 + w1 * v1;
        float rs0 = fmaf(w0, sRGB[i0 * 3 + 0], w1 * sRGB[i1 * 3 + 0]);
        float rs1 = fmaf(w0, sRGB[i0 * 3 + 1], w1 * sRGB[i1 * 3 + 1]);
        float rs2 = fmaf(w0, sRGB[i0 * 3 + 2], w1 * sRGB[i1 * 3 + 2]);

#pragma unroll
        for (int o = 16; o > 0; o >>= 1) {
            wsum += __shfl_down_sync(0xffffffffu, wsum, o);
            dsum += __shfl_down_sync(0xffffffffu, dsum, o);
            rs0  += __shfl_down_sync(0xffffffffu, rs0, o);
            rs1  += __shfl_down_sync(0xffffffffu, rs1, o);
            rs2  += __shfl_down_sync(0xffffffffu, rs2, o);
        }
        if (lane == 0) {
            sRed[w * 5 + 0] = wsum; sRed[w * 5 + 1] = dsum;
            sRed[w * 5 + 2] = rs0;  sRed[w * 5 + 3] = rs1; sRed[w * 5 + 4] = rs2;
        }
        __syncthreads();
        if (tid == 0) {
            float W = 0, D = 0, R0 = 0, R1 = 0, R2 = 0;
#pragma unroll
            for (int w2 = 0; w2 < 4; w2++) {
                W += sRed[w2 * 5 + 0]; D += sRed[w2 * 5 + 1];
                R0 += sRed[w2 * 5 + 2]; R1 += sRed[w2 * 5 + 3]; R2 += sRed[w2 * 5 + 4];
            }
            float bg = 1.f - W;
            out[ray] = D;
            out[nrays + ray * 3 + 0] = R0 + bg;
            out[nrays + ray * 3 + 1] = R1 + bg;
            out[nrays + ray * 3 + 2] = R2 + bg;
        }
    }
}

extern "C" void kernel_launch(void* const* d_in, const int* in_sizes, int n_in,
                              void* d_out, int out_size) {
    const float* rays_o = (const float*)d_in[0];
    const float* rays_d = (const float*)d_in[1];
    const float* W1   = (const float*)d_in[2];
    const float* b1   = (const float*)d_in[3];
    const float* W2   = (const float*)d_in[4];
    const float* b2   = (const float*)d_in[5];
    const float* Wsig = (const float*)d_in[6];
    const float* Wrgb = (const float*)d_in[7];
    const float* brgb = (const float*)d_in[8];
    float* out = (float*)d_out;

    int nrays = in_sizes[0] / 3;   // B*N
    size_t smem_bytes = (size_t)SMEM_FLOATS * sizeof(float);
    cudaFuncSetAttribute(nerf_render_kernel,
                         cudaFuncAttributeMaxDynamicSharedMemorySize, (int)smem_bytes);
    nerf_render_kernel<<<nrays, 128, smem_bytes>>>(rays_o, rays_d, W1, b1, W2, b2,
                                                   Wsig, Wrgb, brgb, out, nrays);
}

// round 15
// speedup vs baseline: 1.7583x; 1.0138x over previous
#include <cuda_runtime.h>
#include <cuda_fp16.h>
#include <math.h>
#include <stdint.h>

#define NS 128
#define NT 256
#define BOUND 2.0f

// ---- dynamic shared memory layout (float indices) ----
#define O_W1    0        // 192
#define O_B1    192      // 64
#define O_WSIG  256      // 64
#define O_WRGB  320      // 201 (+3 pad)
#define O_BRGB  524      // 4
#define O_B2    528      // 64
#define O_Z     592      // 256
#define O_SIG   848      // 256
#define O_RGB   1104     // 768
#define O_RED   1872     // 32
#define O_WT    1904     // 16
#define O_BUF   1920     // 128
#define O_C     2048     // 128
#define O_A     2176     // 128
#define O_HD    2304     // 512 (4 warps x [32 rows][4 heads])
#define O_HB    2816     // 256 (prepacked head B-frags: [4 ks][32 lanes] x uint2)
#define O_BHI   3072     // 2048 floats = 64 rows x 128B (W2^T fp16), 1024B-aligned
#define SMEM_FLOATS 5120    // 20480 bytes

__device__ __forceinline__ uint32_t smem_u32(const void* p) {
    uint32_t a;
    asm("{ .reg .u64 t; cvta.to.shared.u64 t, %1; cvt.u32.u64 %0, t; }" : "=r"(a) : "l"(p));
    return a;
}

#define LDM_X4(r, addr) \
    asm volatile("ldmatrix.sync.aligned.m8n8.x4.shared.b16 {%0,%1,%2,%3}, [%4];" \
        : "=r"((r)[0]), "=r"((r)[1]), "=r"((r)[2]), "=r"((r)[3]) : "r"(addr))

#define MMA16816(d, a, b0, b1) \
    asm volatile("mma.sync.aligned.m16n8k16.row.col.f32.f16.f16.f32 " \
        "{%0,%1,%2,%3}, {%4,%5,%6,%7}, {%8,%9}, {%0,%1,%2,%3};" \
        : "+f"((d)[0]), "+f"((d)[1]), "+f"((d)[2]), "+f"((d)[3]) \
        : "r"((a)[0]), "r"((a)[1]), "r"((a)[2]), "r"((a)[3]), "r"(b0), "r"(b1))

// packed dual-FMA (sm_103a f32x2)
__device__ __forceinline__ float2 ffma2(float2 a, float2 b, float2 c) {
    float2 d;
    asm("fma.rn.f32x2 %0, %1, %2, %3;"
        : "=l"(reinterpret_cast<unsigned long long&>(d))
        : "l"(reinterpret_cast<unsigned long long&>(a)),
          "l"(reinterpret_cast<unsigned long long&>(b)),
          "l"(reinterpret_cast<unsigned long long&>(c)));
    return d;
}
// pack two f32 -> f16x2 (lo half = x, hi half = y)
__device__ __forceinline__ uint32_t pack_f16x2(float lo, float hi) {
    uint32_t w;
    asm("cvt.rn.f16x2.f32 %0, %1, %2;" : "=r"(w) : "f"(hi), "f"(lo));
    return w;
}

__device__ __forceinline__ float clipf(float x, float lo, float hi) {
    return x < lo ? lo : (x > hi ? hi : x);
}

// ---- warp-shuffle scans ----
__device__ __forceinline__ float warp_scan_mul(float v, int lane) {
#pragma unroll
    for (int o = 1; o < 32; o <<= 1) {
        float t = __shfl_up_sync(0xffffffffu, v, o);
        if (lane >= o) v *= t;
    }
    return v;
}
__device__ __forceinline__ float warp_scan_add(float v, int lane) {
#pragma unroll
    for (int o = 1; o < 32; o <<= 1) {
        float t = __shfl_up_sync(0xffffffffu, v, o);
        if (lane >= o) v += t;
    }
    return v;
}
__device__ __forceinline__ float scan128_mul(float v, int tid, float* wt) {
    int lane = tid & 31, w = tid >> 5;
    float s = warp_scan_mul(v, lane);
    if (lane == 31) wt[w] = s;
    __syncthreads();
    float pre = 1.f;
#pragma unroll
    for (int k = 0; k < 3; k++) if (k < w) pre *= wt[k];
    return s * pre;
}
__device__ __forceinline__ float scan128_add(float v, int tid, float* wt) {
    int lane = tid & 31, w = tid >> 5;
    float s = warp_scan_add(v, lane);
    if (lane == 31) wt[w] = s;
    __syncthreads();
    float pre = 0.f;
#pragma unroll
    for (int k = 0; k < 3; k++) if (k < w) pre += wt[k];
    return s + pre;
}

// ---------------------------------------------------------------------------
// One field pass for 128 samples. Warp w owns rows 32w..32w+31.
// Layer 1 computed directly in m16n8k16 A-fragment layout (no SMEM staging).
// Pure fp16 single-term MMA (final rel_err ~5.4e-5, dominated by W2's fp16
// quantization — 18x under the 1e-3 threshold).
// ---------------------------------------------------------------------------
__device__ __forceinline__ void field_pass(
    float* sm, uint32_t smem_base, int tid,
    float ox, float oy, float oz, float dx, float dy, float dz,
    float dirR0, float dirR1, float dirR2, int outBase)
{
    const int lane = tid & 31;
    const int wid = tid >> 5;
    const int c = lane & 3, g = lane >> 2;
    const int m0 = 32 * wid;

    const int br = (lane & 7) + ((lane >> 4) << 3);    // B row within n16 group
    const int bkh = (lane >> 3) & 1;                   // B k-half
    const uint32_t bHiBase = smem_base + O_BHI * 4;

    // ---- per-fragment ray points: rows m0 + 8i + g, i = 0..3 ----
    float pxs[4], pys[4], pzs[4];
#pragma unroll
    for (int i = 0; i < 4; i++) {
        float z = sm[O_Z + outBase + m0 + 8 * i + g];
        pxs[i] = clipf(fmaf(dx, z, ox), -BOUND, BOUND);
        pys[i] = clipf(fmaf(dy, z, oy), -BOUND, BOUND);
        pzs[i] = clipf(fmaf(dz, z, oz), -BOUND, BOUND);
    }

    // ---- warp MMA: D[32][64] = A(fp16) * B(fp16), fp32 accum ----
    float d[2][8][4];
#pragma unroll
    for (int mt = 0; mt < 2; mt++)
#pragma unroll
        for (int n = 0; n < 8; n++)
#pragma unroll
            for (int e = 0; e < 4; e++) d[mt][n][e] = 0.f;

    const float2* w1p = (const float2*)(sm + O_W1);
    const float2* b1p = (const float2*)(sm + O_B1);

#pragma unroll
    for (int ks = 0; ks < 4; ks++) {
        // A-fragments computed in registers (layer 1, fp16)
        uint32_t ahi[2][4];
        const int p0 = 8 * ks + c, p1 = p0 + 4;
        float2 W0x = w1p[p0],      W1x = w1p[p1];
        float2 W0y = w1p[32 + p0], W1y = w1p[32 + p1];
        float2 W0z = w1p[64 + p0], W1z = w1p[64 + p1];
        float2 B0  = b1p[p0],      B1  = b1p[p1];
#pragma unroll
        for (int mt = 0; mt < 2; mt++) {
#pragma unroll
            for (int rr = 0; rr < 2; rr++) {
                int i = 2 * mt + rr;
                float2 PX = make_float2(pxs[i], pxs[i]);
                float2 PY = make_float2(pys[i], pys[i]);
                float2 PZ = make_float2(pzs[i], pzs[i]);
                float2 v0 = ffma2(PX, W0x, ffma2(PY, W0y, ffma2(PZ, W0z, B0)));
                float2 v1 = ffma2(PX, W1x, ffma2(PY, W1y, ffma2(PZ, W1z, B1)));
                v0.x = fmaxf(v0.x, 0.f); v0.y = fmaxf(v0.y, 0.f);
                v1.x = fmaxf(v1.x, 0.f); v1.y = fmaxf(v1.y, 0.f);
                ahi[mt][0 + rr] = pack_f16x2(v0.x, v0.y);
                ahi[mt][2 + rr] = pack_f16x2(v1.x, v1.y);
            }
        }
#pragma unroll
        for (int np = 0; np < 4; np++) {
            uint32_t bh[4];
            uint32_t boff = (uint32_t)(16 * np + br) * 128u +
                            (uint32_t)(((2 * ks + bkh) ^ (br & 7)) << 4);
            LDM_X4(bh, bHiBase + boff);
            MMA16816(d[0][2 * np + 0], ahi[0], bh[0], bh[1]);
            MMA16816(d[0][2 * np + 1], ahi[0], bh[2], bh[3]);
            MMA16816(d[1][2 * np + 0], ahi[1], bh[0], bh[1]);
            MMA16816(d[1][2 * np + 1], ahi[1], bh[2], bh[3]);
        }
    }

    // ---- head MMA epilogue: heads[128][8] = relu(D+b2) @ Whead[64][8] ----
    {
        float d2[2][4];
#pragma unroll
        for (int mt = 0; mt < 2; mt++)
#pragma unroll
            for (int e = 0; e < 4; e++) d2[mt][e] = 0.f;

#pragma unroll
        for (int ks = 0; ks < 4; ks++) {
            uint2 hb = *(const uint2*)(sm + O_HB + (ks * 32 + lane) * 2);
            uint32_t bh0 = hb.x, bh1 = hb.y;

            float2 b2a = *(const float2*)(sm + O_B2 + 16 * ks + 2 * c);
            float2 b2b = *(const float2*)(sm + O_B2 + 16 * ks + 8 + 2 * c);

            uint32_t ah[2][4];
#pragma unroll
            for (int mt = 0; mt < 2; mt++) {
                float e00 = fmaxf(d[mt][2 * ks][0] + b2a.x, 0.f);
                float e01 = fmaxf(d[mt][2 * ks][1] + b2a.y, 0.f);
                float e02 = fmaxf(d[mt][2 * ks][2] + b2a.x, 0.f);
                float e03 = fmaxf(d[mt][2 * ks][3] + b2a.y, 0.f);
                float e10 = fmaxf(d[mt][2 * ks + 1][0] + b2b.x, 0.f);
                float e11 = fmaxf(d[mt][2 * ks + 1][1] + b2b.y, 0.f);
                float e12 = fmaxf(d[mt][2 * ks + 1][2] + b2b.x, 0.f);
                float e13 = fmaxf(d[mt][2 * ks + 1][3] + b2b.y, 0.f);

                ah[mt][0] = pack_f16x2(e00, e01);
                ah[mt][1] = pack_f16x2(e02, e03);
                ah[mt][2] = pack_f16x2(e10, e11);
                ah[mt][3] = pack_f16x2(e12, e13);
            }
            MMA16816(d2[0], ah[0], bh0, bh1);
            MMA16816(d2[1], ah[1], bh0, bh1);
        }

        // stage heads to warp-private scratch
        float* sHD = sm + O_HD + wid * 128;   // [32 rows][4 heads]
        if (c < 2) {
#pragma unroll
            for (int mt = 0; mt < 2; mt++) {
                *(float2*)(sHD + (16 * mt + g) * 4 + 2 * c)     = make_float2(d2[mt][0], d2[mt][1]);
                *(float2*)(sHD + (16 * mt + 8 + g) * 4 + 2 * c) = make_float2(d2[mt][2], d2[mt][3]);
            }
        }
        __syncwarp();

        // finalize: thread = its own sample
        float4 hd = *(const float4*)(sHD + lane * 4);
        float sg = hd.x;
        float sigma = fmaxf(sg, 0.f) + __logf(1.f + __expf(-fabsf(sg)));
        float r0 = hd.y + dirR0;
        float r1 = hd.z + dirR1;
        float r2 = hd.w + dirR2;
        sm[O_SIG + outBase + tid] = sigma;
        sm[O_RGB + (outBase + tid) * 3 + 0] = 1.f / (1.f + __expf(-r0));
        sm[O_RGB + (outBase + tid) * 3 + 1] = 1.f / (1.f + __expf(-r1));
        sm[O_RGB + (outBase + tid) * 3 + 2] = 1.f / (1.f + __expf(-r2));
    }
}

// ---------------------------------------------------------------------------
__global__ void __launch_bounds__(128, 5)
nerf_render_kernel(const float* __restrict__ rays_o, const float* __restrict__ rays_d,
                   const float* __restrict__ W1, const float* __restrict__ b1,
                   const float* __restrict__ W2, const float* __restrict__ b2,
                   const float* __restrict__ Wsig, const float* __restrict__ Wrgb,
                   const float* __restrict__ brgb,
                   float* __restrict__ out, int nrays)
{
    extern __shared__ float sm[];
    const int tid = threadIdx.x;
    const int ray = blockIdx.x;
    const uint32_t smem_base = smem_u32(sm);

    // ---- cooperative weight load ----
    for (int i = tid; i < 192; i += 128) sm[O_W1 + i] = W1[i];
    if (tid < 64) { sm[O_B1 + tid] = b1[tid]; sm[O_B2 + tid] = b2[tid]; sm[O_WSIG + tid] = Wsig[tid]; }
    for (int i = tid; i < 201; i += 128) sm[O_WRGB + i] = Wrgb[i];
    if (tid < 3) sm[O_BRGB + tid] = brgb[tid];

    // W2 -> fp16 B plane: B[j][k] = W2[k][j], 128B rows, chunk-XOR swizzle
    {
        char* bhi = (char*)(sm + O_BHI);
#pragma unroll
        for (int t = 0; t < 32; t++) {
            int i = tid + t * 128;
            int k = i >> 6, j = i & 63;
            __half bh = __float2half_rn(W2[i]);
            uint32_t byte = (uint32_t)(j * 128 + k * 2);
            uint32_t sw = byte ^ ((byte >> 3) & 0x70);
            *(__half*)(bhi + sw) = bh;
        }
    }
    __syncthreads();   // WSIG/WRGB visible for prepack

    // ---- prepack head-MMA B-fragments (ray-invariant, once per CTA) ----
    {
        int ks = tid >> 5, lane = tid & 31;
        int tig = lane & 3, g = lane >> 2;
        int kb = 16 * ks + 2 * tig;
        float w0, w1, w2, w3;
        if (g == 0) {
            w0 = sm[O_WSIG + kb];     w1 = sm[O_WSIG + kb + 1];
            w2 = sm[O_WSIG + kb + 8]; w3 = sm[O_WSIG + kb + 9];
        } else if (g < 4) {
            int ch = g - 1;
            w0 = sm[O_WRGB + 3 * kb + ch];       w1 = sm[O_WRGB + 3 * (kb + 1) + ch];
            w2 = sm[O_WRGB + 3 * (kb + 8) + ch]; w3 = sm[O_WRGB + 3 * (kb + 9) + ch];
        } else {
            w0 = w1 = w2 = w3 = 0.f;
        }
        uint32_t bh0 = pack_f16x2(w0, w1);
        uint32_t bh1 = pack_f16x2(w2, w3);
        *(uint2*)(sm + O_HB + tid * 2) = make_uint2(bh0, bh1);
    }

    // ---- per-ray setup ----
    const float ox = rays_o[ray * 3 + 0], oy = rays_o[ray * 3 + 1], oz = rays_o[ray * 3 + 2];
    const float dx = rays_d[ray * 3 + 0], dy = rays_d[ray * 3 + 1], dz = rays_d[ray * 3 + 2];

    float near = -3.0e38f, far = 3.0e38f;
    {
        float o3[3] = {ox, oy, oz}, d3[3] = {dx, dy, dz};
#pragma unroll
        for (int c = 0; c < 3; c++) {
            float den = d3[c] + 1e-15f;
            float tmn = (-BOUND - o3[c]) / den;
            float tmx = ( BOUND - o3[c]) / den;
            near = fmaxf(near, fminf(tmn, tmx));
            far  = fminf(far,  fmaxf(tmn, tmx));
        }
        if (far < near) { near = 1e9f; far = 1e9f; }
        near = fmaxf(near, 0.05f);
    }
    const float span = far - near;
    const float sample_dist = span / (float)NS;

    float* sZ   = sm + O_Z;
    float* sSig = sm + O_SIG;
    float* sRGB = sm + O_RGB;
    float* sBuf = sm + O_BUF;
    float* sC   = sm + O_C;
    float* sA   = sm + O_A;
    float* sRed = sm + O_RED;
    float* sWT  = sm + O_WT;

    // dir-dependent head terms
    const float dirR0 = fmaf(dx, sm[O_WRGB + 64 * 3 + 0], fmaf(dy, sm[O_WRGB + 65 * 3 + 0], fmaf(dz, sm[O_WRGB + 66 * 3 + 0], sm[O_BRGB + 0])));
    const float dirR1 = fmaf(dx, sm[O_WRGB + 64 * 3 + 1], fmaf(dy, sm[O_WRGB + 65 * 3 + 1], fmaf(dz, sm[O_WRGB + 66 * 3 + 1], sm[O_BRGB + 1])));
    const float dirR2 = fmaf(dx, sm[O_WRGB + 64 * 3 + 2], fmaf(dy, sm[O_WRGB + 65 * 3 + 2], fmaf(dz, sm[O_WRGB + 66 * 3 + 2], sm[O_BRGB + 2])));

    // ========== Phase A: coarse ==========
    sZ[tid] = near + span * ((float)tid * (1.f / 127.f));
    __syncthreads();   // sZ + HB prepack visible
    field_pass(sm, smem_base, tid, ox, oy, oz, dx, dy, dz, dirR0, dirR1, dirR2, 0);
    __syncthreads();

    // ========== Phase B: weights -> pdf -> inverse-CDF scatter ==========
    {
        float delta = (tid < NS - 1) ? (sZ[tid + 1] - sZ[tid]) : sample_dist;
        float alpha = 1.f - __expf(-delta * sSig[tid]);
        float shifted = 1.f - alpha + 1e-15f;
        if (tid < NS - 1) sC[tid] = sZ[tid] + 0.5f * delta;
        float Tincl = scan128_mul(shifted, tid, sWT);   // sync inside
        float w = alpha * (Tincl / shifted);            // exclusive via division
        sA[tid] = w;
        __syncthreads();
        float pv = (tid < 126) ? (sA[tid + 1] + 1e-5f) : 0.f;
        float csum = scan128_add(pv, tid, sWT);         // sync inside
        sBuf[tid] = csum;
        __syncthreads();
        const float invS = 1.f / sBuf[125];

        // thread tid = bin: u in [c[tid], c[tid+1]) -> scatter fine z
        if (tid < 127) {
            float clo = (tid == 0) ? 0.f : sBuf[tid - 1] * invS;
            bool last = (tid == 126);
            float chi = last ? 3.0e38f : sBuf[tid] * invS;
            int t0 = max(0, (int)ceilf(fmaf(128.f, clo, -0.5f)));
            int t1 = last ? 127 : (min(128, (int)ceilf(fmaf(128.f, chi, -0.5f))) - 1);
            if (t0 <= t1) {
                int above = min(tid + 1, 126);
                float cb = clo;
                float ca = sBuf[above - 1] * invS;
                float bb = sC[tid], ba = sC[above];
                float den = ca - cb;
                if (den < 1e-5f) den = 1.f;
                float scale = (ba - bb) / den;
                for (int t = t0; t <= t1; t++) {
                    float u = 0.00390625f + (float)t * 0.0078125f;
                    sZ[NS + t] = bb + (u - cb) * scale;
                }
            }
        }
    }
    __syncthreads();

    // ========== Phase C: fine ==========
    float new_z = sZ[NS + tid];
    field_pass(sm, smem_base, tid, ox, oy, oz, dx, dy, dz, dirR0, dirR1, dirR2, NS);
    __syncthreads();

    // ========== Phase D: stable merge of two sorted runs ==========
    {
        float zA = sZ[tid], zB = new_z;
        int lo = 0, hi = NS;
        while (lo < hi) { int m = (lo + hi) >> 1; if (sZ[NS + m] < zA) lo = m + 1; else hi = m; }
        int posA = tid + lo;
        lo = 0; hi = NS;
        while (lo < hi) { int m = (lo + hi) >> 1; if (sZ[m] <= zB) lo = m + 1; else hi = m; }
        int posB = tid + lo;

        float sgA = sSig[tid], sgB = sSig[NS + tid];
        float a0 = sRGB[tid * 3 + 0], a1 = sRGB[tid * 3 + 1], a2 = sRGB[tid * 3 + 2];
        float b0 = sRGB[(NS + tid) * 3 + 0], b1v = sRGB[(NS + tid) * 3 + 1], b2v = sRGB[(NS + tid) * 3 + 2];
        __syncthreads();
        sZ[posA] = zA; sSig[posA] = sgA;
        sRGB[posA * 3 + 0] = a0; sRGB[posA * 3 + 1] = a1; sRGB[posA * 3 + 2] = a2;
        sZ[posB] = zB; sSig[posB] = sgB;
        sRGB[posB * 3 + 0] = b0; sRGB[posB * 3 + 1] = b1v; sRGB[posB * 3 + 2] = b2v;
        __syncthreads();
    }

    // ========== Phase E: final composite ==========
    {
        const int i0 = 2 * tid, i1 = 2 * tid + 1;
        float d0 = sZ[i0 + 1] - sZ[i0];
        float d1 = (i1 < NT - 1) ? (sZ[i1 + 1] - sZ[i1]) : sample_dist;
        float al0 = 1.f - __expf(-d0 * sSig[i0]);
        float al1 = 1.f - __expf(-d1 * sSig[i1]);
        float s0 = 1.f - al0 + 1e-15f;
        float s1 = 1.f - al1 + 1e-15f;

        int lane = tid & 31, w = tid >> 5;
        float p = s0 * s1;
        float pincl = warp_scan_mul(p, lane);
        if (lane == 31) sWT[w] = pincl;
        __syncthreads();
        float pre = 1.f;
#pragma unroll
        for (int k = 0; k < 3; k++) if (k < w) pre *= sWT[k];
        float e = __shfl_up_sync(0xffffffffu, pincl, 1);
        e = (lane == 0) ? 1.f : e;
        e *= pre;
        float w0 = al0 * e;
        float w1 = al1 * e * s0;

        float v0 = clipf((sZ[i0] - near) / span, 0.f, 1.f);
        float v1 = clipf((sZ[i1] - near) / span, 0.f, 1.f);
        float wsum = w0 + w1;
        float dsum = w0 * v0 + w1 * v1;
        float rs0 = fmaf(w0, sRGB[i0 * 3 + 0], w1 * sRGB[i1 * 3 + 0]);
        float rs1 = fmaf(w0, sRGB[i0 * 3 + 1], w1 * sRGB[i1 * 3 + 1]);
        float rs2 = fmaf(w0, sRGB[i0 * 3 + 2], w1 * sRGB[i1 * 3 + 2]);

#pragma unroll
        for (int o = 16; o > 0; o >>= 1) {
            wsum += __shfl_down_sync(0xffffffffu, wsum, o);
            dsum += __shfl_down_sync(0xffffffffu, dsum, o);
            rs0  += __shfl_down_sync(0xffffffffu, rs0, o);
            rs1  += __shfl_down_sync(0xffffffffu, rs1, o);
            rs2  += __shfl_down_sync(0xffffffffu, rs2, o);
        }
        if (lane == 0) {
            sRed[w * 5 + 0] = wsum; sRed[w * 5 + 1] = dsum;
            sRed[w * 5 + 2] = rs0;  sRed[w * 5 + 3] = rs1; sRed[w * 5 + 4] = rs2;
        }
        __syncthreads();
        if (tid == 0) {
            float W = 0, D = 0, R0 = 0, R1 = 0, R2 = 0;
#pragma unroll
            for (int w2 = 0; w2 < 4; w2++) {
                W += sRed[w2 * 5 + 0]; D += sRed[w2 * 5 + 1];
                R0 += sRed[w2 * 5 + 2]; R1 += sRed[w2 * 5 + 3]; R2 += sRed[w2 * 5 + 4];
            }
            float bg = 1.f - W;
            out[ray] = D;
            out[nrays + ray * 3 + 0] = R0 + bg;
            out[nrays + ray * 3 + 1] = R1 + bg;
            out[nrays + ray * 3 + 2] = R2 + bg;
        }
    }
}

extern "C" void kernel_launch(void* const* d_in, const int* in_sizes, int n_in,
                              void* d_out, int out_size) {
    const float* rays_o = (const float*)d_in[0];
    const float* rays_d = (const float*)d_in[1];
    const float* W1   = (const float*)d_in[2];
    const float* b1   = (const float*)d_in[3];
    const float* W2   = (const float*)d_in[4];
    const float* b2   = (const float*)d_in[5];
    const float* Wsig = (const float*)d_in[6];
    const float* Wrgb = (const float*)d_in[7];
    const float* brgb = (const float*)d_in[8];
    float* out = (float*)d_out;

    int nrays = in_sizes[0] / 3;   // B*N
    size_t smem_bytes = (size_t)SMEM_FLOATS * sizeof(float);
    cudaFuncSetAttribute(nerf_render_kernel,
                         cudaFuncAttributeMaxDynamicSharedMemorySize, (int)smem_bytes);
    nerf_render_kernel<<<nrays, 128, smem_bytes>>>(rays_o, rays_d, W1, b1, W2, b2,
                                                   Wsig, Wrgb, brgb, out, nrays);
}

// round 16
// speedup vs baseline: 1.9268x; 1.0958x over previous
#include <cuda_runtime.h>
#include <cuda_fp16.h>
#include <math.h>
#include <stdint.h>

#define NS 128
#define NT 256
#define BOUND 2.0f

// ---- dynamic shared memory layout (float indices) ----
#define O_W1    0        // 192
#define O_B1    192      // 64
#define O_WSIG  256      // 64
#define O_WRGB  320      // 201 (+3 pad)
#define O_BRGB  524      // 4
#define O_B2    528      // 64
#define O_Z     592      // 256
#define O_SIG   848      // 256
#define O_RGB   1104     // 768
#define O_RED   1872     // 32
#define O_WT    1904     // 16
#define O_BUF   1920     // 128
#define O_C     2048     // 128
#define O_A     2176     // 128
#define O_HD    2304     // 512 (4 warps x [32 rows][4 heads])
#define O_HB    2816     // 256 (prepacked head B-frags: [4 ks][32 lanes] x uint2)
#define O_BHI   3072     // 2048 floats = 64 rows x 128B (W2^T fp16), 1024B-aligned
#define SMEM_FLOATS 5120    // 20480 bytes

__device__ __forceinline__ uint32_t smem_u32(const void* p) {
    uint32_t a;
    asm("{ .reg .u64 t; cvta.to.shared.u64 t, %1; cvt.u32.u64 %0, t; }" : "=r"(a) : "l"(p));
    return a;
}

#define LDM_X4(r, addr) \
    asm volatile("ldmatrix.sync.aligned.m8n8.x4.shared.b16 {%0,%1,%2,%3}, [%4];" \
        : "=r"((r)[0]), "=r"((r)[1]), "=r"((r)[2]), "=r"((r)[3]) : "r"(addr))

#define MMA16816(d, a, b0, b1) \
    asm volatile("mma.sync.aligned.m16n8k16.row.col.f32.f16.f16.f32 " \
        "{%0,%1,%2,%3}, {%4,%5,%6,%7}, {%8,%9}, {%0,%1,%2,%3};" \
        : "+f"((d)[0]), "+f"((d)[1]), "+f"((d)[2]), "+f"((d)[3]) \
        : "r"((a)[0]), "r"((a)[1]), "r"((a)[2]), "r"((a)[3]), "r"(b0), "r"(b1))

// packed dual-FMA (sm_103a f32x2)
__device__ __forceinline__ float2 ffma2(float2 a, float2 b, float2 c) {
    float2 d;
    asm("fma.rn.f32x2 %0, %1, %2, %3;"
        : "=l"(reinterpret_cast<unsigned long long&>(d))
        : "l"(reinterpret_cast<unsigned long long&>(a)),
          "l"(reinterpret_cast<unsigned long long&>(b)),
          "l"(reinterpret_cast<unsigned long long&>(c)));
    return d;
}
// pack two f32 -> f16x2 (lo half = x, hi half = y)
__device__ __forceinline__ uint32_t pack_f16x2(float lo, float hi) {
    uint32_t w;
    asm("cvt.rn.f16x2.f32 %0, %1, %2;" : "=r"(w) : "f"(hi), "f"(lo));
    return w;
}
// packed relu on f16x2 (equivalent to relu-before-pack: negatives -> +0)
__device__ __forceinline__ uint32_t relu_f16x2(uint32_t w) {
    uint32_t r;
    asm("max.f16x2 %0, %1, %2;" : "=r"(r) : "r"(w), "r"(0u));
    return r;
}

__device__ __forceinline__ float clipf(float x, float lo, float hi) {
    return x < lo ? lo : (x > hi ? hi : x);
}

// ---- warp-shuffle scans ----
__device__ __forceinline__ float warp_scan_mul(float v, int lane) {
#pragma unroll
    for (int o = 1; o < 32; o <<= 1) {
        float t = __shfl_up_sync(0xffffffffu, v, o);
        if (lane >= o) v *= t;
    }
    return v;
}
__device__ __forceinline__ float warp_scan_add(float v, int lane) {
#pragma unroll
    for (int o = 1; o < 32; o <<= 1) {
        float t = __shfl_up_sync(0xffffffffu, v, o);
        if (lane >= o) v += t;
    }
    return v;
}
__device__ __forceinline__ float scan128_mul(float v, int tid, float* wt) {
    int lane = tid & 31, w = tid >> 5;
    float s = warp_scan_mul(v, lane);
    if (lane == 31) wt[w] = s;
    __syncthreads();
    float pre = 1.f;
#pragma unroll
    for (int k = 0; k < 3; k++) if (k < w) pre *= wt[k];
    return s * pre;
}
__device__ __forceinline__ float scan128_add(float v, int tid, float* wt) {
    int lane = tid & 31, w = tid >> 5;
    float s = warp_scan_add(v, lane);
    if (lane == 31) wt[w] = s;
    __syncthreads();
    float pre = 0.f;
#pragma unroll
    for (int k = 0; k < 3; k++) if (k < w) pre += wt[k];
    return s + pre;
}

// ---------------------------------------------------------------------------
// One field pass for 128 samples. Warp w owns rows 32w..32w+31.
// Layer 1 computed directly in m16n8k16 A-fragment layout (no SMEM staging).
// Pure fp16 single-term MMA. relu fused into packed f16x2 max.
// ---------------------------------------------------------------------------
__device__ __forceinline__ void field_pass(
    float* sm, uint32_t smem_base, int tid,
    float ox, float oy, float oz, float dx, float dy, float dz,
    float dirR0, float dirR1, float dirR2, int outBase)
{
    const int lane = tid & 31;
    const int wid = tid >> 5;
    const int c = lane & 3, g = lane >> 2;
    const int m0 = 32 * wid;

    const int br = (lane & 7) + ((lane >> 4) << 3);    // B row within n16 group
    const int bkh = (lane >> 3) & 1;                   // B k-half
    const uint32_t bHiBase = smem_base + O_BHI * 4;

    // ---- per-fragment ray points: rows m0 + 8i + g, i = 0..3 ----
    float pxs[4], pys[4], pzs[4];
#pragma unroll
    for (int i = 0; i < 4; i++) {
        float z = sm[O_Z + outBase + m0 + 8 * i + g];
        pxs[i] = clipf(fmaf(dx, z, ox), -BOUND, BOUND);
        pys[i] = clipf(fmaf(dy, z, oy), -BOUND, BOUND);
        pzs[i] = clipf(fmaf(dz, z, oz), -BOUND, BOUND);
    }

    // ---- warp MMA: D[32][64] = A(fp16) * B(fp16), fp32 accum ----
    float d[2][8][4];
#pragma unroll
    for (int mt = 0; mt < 2; mt++)
#pragma unroll
        for (int n = 0; n < 8; n++)
#pragma unroll
            for (int e = 0; e < 4; e++) d[mt][n][e] = 0.f;

    const float2* w1p = (const float2*)(sm + O_W1);
    const float2* b1p = (const float2*)(sm + O_B1);

#pragma unroll
    for (int ks = 0; ks < 4; ks++) {
        // A-fragments computed in registers (layer 1, fp16, fused relu)
        uint32_t ahi[2][4];
        const int p0 = 8 * ks + c, p1 = p0 + 4;
        float2 W0x = w1p[p0],      W1x = w1p[p1];
        float2 W0y = w1p[32 + p0], W1y = w1p[32 + p1];
        float2 W0z = w1p[64 + p0], W1z = w1p[64 + p1];
        float2 B0  = b1p[p0],      B1  = b1p[p1];
#pragma unroll
        for (int mt = 0; mt < 2; mt++) {
#pragma unroll
            for (int rr = 0; rr < 2; rr++) {
                int i = 2 * mt + rr;
                float2 PX = make_float2(pxs[i], pxs[i]);
                float2 PY = make_float2(pys[i], pys[i]);
                float2 PZ = make_float2(pzs[i], pzs[i]);
                float2 v0 = ffma2(PX, W0x, ffma2(PY, W0y, ffma2(PZ, W0z, B0)));
                float2 v1 = ffma2(PX, W1x, ffma2(PY, W1y, ffma2(PZ, W1z, B1)));
                ahi[mt][0 + rr] = relu_f16x2(pack_f16x2(v0.x, v0.y));
                ahi[mt][2 + rr] = relu_f16x2(pack_f16x2(v1.x, v1.y));
            }
        }
#pragma unroll
        for (int np = 0; np < 4; np++) {
            uint32_t bh[4];
            uint32_t boff = (uint32_t)(16 * np + br) * 128u +
                            (uint32_t)(((2 * ks + bkh) ^ (br & 7)) << 4);
            LDM_X4(bh, bHiBase + boff);
            MMA16816(d[0][2 * np + 0], ahi[0], bh[0], bh[1]);
            MMA16816(d[0][2 * np + 1], ahi[0], bh[2], bh[3]);
            MMA16816(d[1][2 * np + 0], ahi[1], bh[0], bh[1]);
            MMA16816(d[1][2 * np + 1], ahi[1], bh[2], bh[3]);
        }
    }

    // ---- head MMA epilogue: heads[128][8] = relu(D+b2) @ Whead[64][8] ----
    {
        float d2[2][4];
#pragma unroll
        for (int mt = 0; mt < 2; mt++)
#pragma unroll
            for (int e = 0; e < 4; e++) d2[mt][e] = 0.f;

#pragma unroll
        for (int ks = 0; ks < 4; ks++) {
            uint2 hb = *(const uint2*)(sm + O_HB + (ks * 32 + lane) * 2);
            uint32_t bh0 = hb.x, bh1 = hb.y;

            float2 b2a = *(const float2*)(sm + O_B2 + 16 * ks + 2 * c);
            float2 b2b = *(const float2*)(sm + O_B2 + 16 * ks + 8 + 2 * c);

            uint32_t ah[2][4];
#pragma unroll
            for (int mt = 0; mt < 2; mt++) {
                float e00 = d[mt][2 * ks][0] + b2a.x;
                float e01 = d[mt][2 * ks][1] + b2a.y;
                float e02 = d[mt][2 * ks][2] + b2a.x;
                float e03 = d[mt][2 * ks][3] + b2a.y;
                float e10 = d[mt][2 * ks + 1][0] + b2b.x;
                float e11 = d[mt][2 * ks + 1][1] + b2b.y;
                float e12 = d[mt][2 * ks + 1][2] + b2b.x;
                float e13 = d[mt][2 * ks + 1][3] + b2b.y;

                ah[mt][0] = relu_f16x2(pack_f16x2(e00, e01));
                ah[mt][1] = relu_f16x2(pack_f16x2(e02, e03));
                ah[mt][2] = relu_f16x2(pack_f16x2(e10, e11));
                ah[mt][3] = relu_f16x2(pack_f16x2(e12, e13));
            }
            MMA16816(d2[0], ah[0], bh0, bh1);
            MMA16816(d2[1], ah[1], bh0, bh1);
        }

        // stage heads to warp-private scratch
        float* sHD = sm + O_HD + wid * 128;   // [32 rows][4 heads]
        if (c < 2) {
#pragma unroll
            for (int mt = 0; mt < 2; mt++) {
                *(float2*)(sHD + (16 * mt + g) * 4 + 2 * c)     = make_float2(d2[mt][0], d2[mt][1]);
                *(float2*)(sHD + (16 * mt + 8 + g) * 4 + 2 * c) = make_float2(d2[mt][2], d2[mt][3]);
            }
        }
        __syncwarp();

        // finalize: thread = its own sample
        float4 hd = *(const float4*)(sHD + lane * 4);
        float sg = hd.x;
        float sigma = fmaxf(sg, 0.f) + __logf(1.f + __expf(-fabsf(sg)));
        float r0 = hd.y + dirR0;
        float r1 = hd.z + dirR1;
        float r2 = hd.w + dirR2;
        sm[O_SIG + outBase + tid] = sigma;
        sm[O_RGB + (outBase + tid) * 3 + 0] = 1.f / (1.f + __expf(-r0));
        sm[O_RGB + (outBase + tid) * 3 + 1] = 1.f / (1.f + __expf(-r1));
        sm[O_RGB + (outBase + tid) * 3 + 2] = 1.f / (1.f + __expf(-r2));
    }
}

// ---------------------------------------------------------------------------
__global__ void __launch_bounds__(128, 5)
nerf_render_kernel(const float* __restrict__ rays_o, const float* __restrict__ rays_d,
                   const float* __restrict__ W1, const float* __restrict__ b1,
                   const float* __restrict__ W2, const float* __restrict__ b2,
                   const float* __restrict__ Wsig, const float* __restrict__ Wrgb,
                   const float* __restrict__ brgb,
                   float* __restrict__ out, int nrays)
{
    extern __shared__ float sm[];
    const int tid = threadIdx.x;
    const int ray = blockIdx.x;
    const uint32_t smem_base = smem_u32(sm);

    // ---- cooperative weight load ----
    for (int i = tid; i < 192; i += 128) sm[O_W1 + i] = W1[i];
    if (tid < 64) { sm[O_B1 + tid] = b1[tid]; sm[O_B2 + tid] = b2[tid]; sm[O_WSIG + tid] = Wsig[tid]; }
    for (int i = tid; i < 201; i += 128) sm[O_WRGB + i] = Wrgb[i];
    if (tid < 3) sm[O_BRGB + tid] = brgb[tid];

    // W2 -> fp16 B plane: B[j][k] = W2[k][j], 128B rows, chunk-granular swizzle.
    // Thread owns whole 16B chunks: j = idx&63 (coalesced LDG), c = idx>>6;
    // swizzled chunk = c ^ (j&7). One STS.128 per chunk (conflict-friendly).
    {
        char* bhi = (char*)(sm + O_BHI);
#pragma unroll
        for (int t = 0; t < 4; t++) {
            int idx = tid + t * 128;           // 0..511
            int j = idx & 63, cch = idx >> 6;  // row, chunk
            uint32_t w[4];
#pragma unroll
            for (int q = 0; q < 4; q++) {
                int k0 = cch * 8 + 2 * q;
                float f0 = W2[k0 * 64 + j];
                float f1 = W2[(k0 + 1) * 64 + j];
                w[q] = pack_f16x2(f0, f1);
            }
            int swc = cch ^ (j & 7);
            *(uint4*)(bhi + j * 128 + swc * 16) = make_uint4(w[0], w[1], w[2], w[3]);
        }
    }
    __syncthreads();   // WSIG/WRGB visible for prepack

    // ---- prepack head-MMA B-fragments (ray-invariant, once per CTA) ----
    {
        int ks = tid >> 5, lane = tid & 31;
        int tig = lane & 3, g = lane >> 2;
        int kb = 16 * ks + 2 * tig;
        float w0, w1, w2, w3;
        if (g == 0) {
            w0 = sm[O_WSIG + kb];     w1 = sm[O_WSIG + kb + 1];
            w2 = sm[O_WSIG + kb + 8]; w3 = sm[O_WSIG + kb + 9];
        } else if (g < 4) {
            int ch = g - 1;
            w0 = sm[O_WRGB + 3 * kb + ch];       w1 = sm[O_WRGB + 3 * (kb + 1) + ch];
            w2 = sm[O_WRGB + 3 * (kb + 8) + ch]; w3 = sm[O_WRGB + 3 * (kb + 9) + ch];
        } else {
            w0 = w1 = w2 = w3 = 0.f;
        }
        uint32_t bh0 = pack_f16x2(w0, w1);
        uint32_t bh1 = pack_f16x2(w2, w3);
        *(uint2*)(sm + O_HB + tid * 2) = make_uint2(bh0, bh1);
    }

    // ---- per-ray setup ----
    const float ox = rays_o[ray * 3 + 0], oy = rays_o[ray * 3 + 1], oz = rays_o[ray * 3 + 2];
    const float dx = rays_d[ray * 3 + 0], dy = rays_d[ray * 3 + 1], dz = rays_d[ray * 3 + 2];

    float near = -3.0e38f, far = 3.0e38f;
    {
        float o3[3] = {ox, oy, oz}, d3[3] = {dx, dy, dz};
#pragma unroll
        for (int c = 0; c < 3; c++) {
            float den = d3[c] + 1e-15f;
            float tmn = (-BOUND - o3[c]) / den;
            float tmx = ( BOUND - o3[c]) / den;
            near = fmaxf(near, fminf(tmn, tmx));
            far  = fminf(far,  fmaxf(tmn, tmx));
        }
        if (far < near) { near = 1e9f; far = 1e9f; }
        near = fmaxf(near, 0.05f);
    }
    const float span = far - near;
    const float sample_dist = span / (float)NS;

    float* sZ   = sm + O_Z;
    float* sSig = sm + O_SIG;
    float* sRGB = sm + O_RGB;
    float* sBuf = sm + O_BUF;
    float* sC   = sm + O_C;
    float* sA   = sm + O_A;
    float* sRed = sm + O_RED;
    float* sWT  = sm + O_WT;

    // dir-dependent head terms
    const float dirR0 = fmaf(dx, sm[O_WRGB + 64 * 3 + 0], fmaf(dy, sm[O_WRGB + 65 * 3 + 0], fmaf(dz, sm[O_WRGB + 66 * 3 + 0], sm[O_BRGB + 0])));
    const float dirR1 = fmaf(dx, sm[O_WRGB + 64 * 3 + 1], fmaf(dy, sm[O_WRGB + 65 * 3 + 1], fmaf(dz, sm[O_WRGB + 66 * 3 + 1], sm[O_BRGB + 1])));
    const float dirR2 = fmaf(dx, sm[O_WRGB + 64 * 3 + 2], fmaf(dy, sm[O_WRGB + 65 * 3 + 2], fmaf(dz, sm[O_WRGB + 66 * 3 + 2], sm[O_BRGB + 2])));

    // ========== Phase A: coarse ==========
    sZ[tid] = near + span * ((float)tid * (1.f / 127.f));
    __syncthreads();   // sZ + HB prepack visible
    field_pass(sm, smem_base, tid, ox, oy, oz, dx, dy, dz, dirR0, dirR1, dirR2, 0);
    __syncthreads();

    // ========== Phase B: weights -> pdf -> inverse-CDF scatter ==========
    {
        float delta = (tid < NS - 1) ? (sZ[tid + 1] - sZ[tid]) : sample_dist;
        float alpha = 1.f - __expf(-delta * sSig[tid]);
        float shifted = 1.f - alpha + 1e-15f;
        if (tid < NS - 1) sC[tid] = sZ[tid] + 0.5f * delta;
        float Tincl = scan128_mul(shifted, tid, sWT);   // sync inside
        float w = alpha * (Tincl / shifted);            // exclusive via division
        sA[tid] = w;
        __syncthreads();
        float pv = (tid < 126) ? (sA[tid + 1] + 1e-5f) : 0.f;
        float csum = scan128_add(pv, tid, sWT);         // sync inside
        sBuf[tid] = csum;
        __syncthreads();
        const float invS = 1.f / sBuf[125];

        // thread tid = bin: u in [c[tid], c[tid+1]) -> scatter fine z
        if (tid < 127) {
            float clo = (tid == 0) ? 0.f : sBuf[tid - 1] * invS;
            bool last = (tid == 126);
            float chi = last ? 3.0e38f : sBuf[tid] * invS;
            int t0 = max(0, (int)ceilf(fmaf(128.f, clo, -0.5f)));
            int t1 = last ? 127 : (min(128, (int)ceilf(fmaf(128.f, chi, -0.5f))) - 1);
            if (t0 <= t1) {
                int above = min(tid + 1, 126);
                float cb = clo;
                float ca = sBuf[above - 1] * invS;
                float bb = sC[tid], ba = sC[above];
                float den = ca - cb;
                if (den < 1e-5f) den = 1.f;
                float scale = (ba - bb) / den;
                for (int t = t0; t <= t1; t++) {
                    float u = 0.00390625f + (float)t * 0.0078125f;
                    sZ[NS + t] = bb + (u - cb) * scale;
                }
            }
        }
    }
    __syncthreads();

    // ========== Phase C: fine ==========
    float new_z = sZ[NS + tid];
    field_pass(sm, smem_base, tid, ox, oy, oz, dx, dy, dz, dirR0, dirR1, dirR2, NS);
    __syncthreads();

    // ========== Phase D: stable merge of two sorted runs ==========
    {
        float zA = sZ[tid], zB = new_z;
        int lo = 0, hi = NS;
        while (lo < hi) { int m = (lo + hi) >> 1; if (sZ[NS + m] < zA) lo = m + 1; else hi = m; }
        int posA = tid + lo;
        lo = 0; hi = NS;
        while (lo < hi) { int m = (lo + hi) >> 1; if (sZ[m] <= zB) lo = m + 1; else hi = m; }
        int posB = tid + lo;

        float sgA = sSig[tid], sgB = sSig[NS + tid];
        float a0 = sRGB[tid * 3 + 0], a1 = sRGB[tid * 3 + 1], a2 = sRGB[tid * 3 + 2];
        float b0 = sRGB[(NS + tid) * 3 + 0], b1v = sRGB[(NS + tid) * 3 + 1], b2v = sRGB[(NS + tid) * 3 + 2];
        __syncthreads();
        sZ[posA] = zA; sSig[posA] = sgA;
        sRGB[posA * 3 + 0] = a0; sRGB[posA * 3 + 1] = a1; sRGB[posA * 3 + 2] = a2;
        sZ[posB] = zB; sSig[posB] = sgB;
        sRGB[posB * 3 + 0] = b0; sRGB[posB * 3 + 1] = b1v; sRGB[posB * 3 + 2] = b2v;
        __syncthreads();
    }

    // ========== Phase E: final composite ==========
    {
        const int i0 = 2 * tid, i1 = 2 * tid + 1;
        float d0 = sZ[i0 + 1] - sZ[i0];
        float d1 = (i1 < NT - 1) ? (sZ[i1 + 1] - sZ[i1]) : sample_dist;
        float al0 = 1.f - __expf(-d0 * sSig[i0]);
        float al1 = 1.f - __expf(-d1 * sSig[i1]);
        float s0 = 1.f - al0 + 1e-15f;
        float s1 = 1.f - al1 + 1e-15f;

        int lane = tid & 31, w = tid >> 5;
        float p = s0 * s1;
        float pincl = warp_scan_mul(p, lane);
        if (lane == 31) sWT[w] = pincl;
        __syncthreads();
        float pre = 1.f;
#pragma unroll
        for (int k = 0; k < 3; k++) if (k < w) pre *= sWT[k];
        float e = __shfl_up_sync(0xffffffffu, pincl, 1);
        e = (lane == 0) ? 1.f : e;
        e *= pre;
        float w0 = al0 * e;
        float w1 = al1 * e * s0;

        float v0 = clipf((sZ[i0] - near) / span, 0.f, 1.f);
        float v1 = clipf((sZ[i1] - near) / span, 0.f, 1.f);
        float wsum = w0 + w1;
        float dsum = w0 * v0 + w1 * v1;
        float rs0 = fmaf(w0, sRGB[i0 * 3 + 0], w1 * sRGB[i1 * 3 + 0]);
        float rs1 = fmaf(w0, sRGB[i0 * 3 + 1], w1 * sRGB[i1 * 3 + 1]);
        float rs2 = fmaf(w0, sRGB[i0 * 3 + 2], w1 * sRGB[i1 * 3 + 2]);

#pragma unroll
        for (int o = 16; o > 0; o >>= 1) {
            wsum += __shfl_down_sync(0xffffffffu, wsum, o);
            dsum += __shfl_down_sync(0xffffffffu, dsum, o);
            rs0  += __shfl_down_sync(0xffffffffu, rs0, o);
            rs1  += __shfl_down_sync(0xffffffffu, rs1, o);
            rs2  += __shfl_down_sync(0xffffffffu, rs2, o);
        }
        if (lane == 0) {
            sRed[w * 5 + 0] = wsum; sRed[w * 5 + 1] = dsum;
            sRed[w * 5 + 2] = rs0;  sRed[w * 5 + 3] = rs1; sRed[w * 5 + 4] = rs2;
        }
        __syncthreads();
        if (tid == 0) {
            float W = 0, D = 0, R0 = 0, R1 = 0, R2 = 0;
#pragma unroll
            for (int w2 = 0; w2 < 4; w2++) {
                W += sRed[w2 * 5 + 0]; D += sRed[w2 * 5 + 1];
                R0 += sRed[w2 * 5 + 2]; R1 += sRed[w2 * 5 + 3]; R2 += sRed[w2 * 5 + 4];
            }
            float bg = 1.f - W;
            out[ray] = D;
            out[nrays + ray * 3 + 0] = R0 + bg;
            out[nrays + ray * 3 + 1] = R1 + bg;
            out[nrays + ray * 3 + 2] = R2 + bg;
        }
    }
}

extern "C" void kernel_launch(void* const* d_in, const int* in_sizes, int n_in,
                              void* d_out, int out_size) {
    const float* rays_o = (const float*)d_in[0];
    const float* rays_d = (const float*)d_in[1];
    const float* W1   = (const float*)d_in[2];
    const float* b1   = (const float*)d_in[3];
    const float* W2   = (const float*)d_in[4];
    const float* b2   = (const float*)d_in[5];
    const float* Wsig = (const float*)d_in[6];
    const float* Wrgb = (const float*)d_in[7];
    const float* brgb = (const float*)d_in[8];
    float* out = (float*)d_out;

    int nrays = in_sizes[0] / 3;   // B*N
    size_t smem_bytes = (size_t)SMEM_FLOATS * sizeof(float);
    cudaFuncSetAttribute(nerf_render_kernel,
                         cudaFuncAttributeMaxDynamicSharedMemorySize, (int)smem_bytes);
    nerf_render_kernel<<<nrays, 128, smem_bytes>>>(rays_o, rays_d, W1, b1, W2, b2,
                                                   Wsig, Wrgb, brgb, out, nrays);
}

// round 17
// speedup vs baseline: 1.9790x; 1.0271x over previous
#include <cuda_runtime.h>
#include <cuda_fp16.h>
#include <math.h>
#include <stdint.h>

#define NS 128
#define NT 256
#define BOUND 2.0f

// ---- dynamic shared memory layout (float indices) ----
#define O_W1    0        // 192
#define O_B1    192      // 64
#define O_WSIG  256      // 64
#define O_WRGB  320      // 201 (+3 pad)
#define O_BRGB  524      // 4
#define O_B2    528      // 64
#define O_Z     592      // 256
#define O_SIG   848      // 256
#define O_RGB   1104     // 768
#define O_RED   1872     // 32
#define O_WT    1904     // 16
#define O_BUF   1920     // 128
#define O_C     2048     // 128
#define O_A     2176     // 128
#define O_HD    2304     // 512 (4 warps x [32 rows][4 heads])
#define O_HB    2816     // 256 (prepacked head B-frags: [4 ks][32 lanes] x uint2)
#define O_BHI   3072     // 2048 floats = 64 rows x 128B (W2^T fp16), 1024B-aligned
#define SMEM_FLOATS 5120    // 20480 bytes

__device__ __forceinline__ uint32_t smem_u32(const void* p) {
    uint32_t a;
    asm("{ .reg .u64 t; cvta.to.shared.u64 t, %1; cvt.u32.u64 %0, t; }" : "=r"(a) : "l"(p));
    return a;
}

#define LDM_X4(r, addr) \
    asm volatile("ldmatrix.sync.aligned.m8n8.x4.shared.b16 {%0,%1,%2,%3}, [%4];" \
        : "=r"((r)[0]), "=r"((r)[1]), "=r"((r)[2]), "=r"((r)[3]) : "r"(addr))

#define MMA16816(d, a, b0, b1) \
    asm volatile("mma.sync.aligned.m16n8k16.row.col.f32.f16.f16.f32 " \
        "{%0,%1,%2,%3}, {%4,%5,%6,%7}, {%8,%9}, {%0,%1,%2,%3};" \
        : "+f"((d)[0]), "+f"((d)[1]), "+f"((d)[2]), "+f"((d)[3]) \
        : "r"((a)[0]), "r"((a)[1]), "r"((a)[2]), "r"((a)[3]), "r"(b0), "r"(b1))

// packed dual-FMA (sm_103a f32x2)
__device__ __forceinline__ float2 ffma2(float2 a, float2 b, float2 c) {
    float2 d;
    asm("fma.rn.f32x2 %0, %1, %2, %3;"
        : "=l"(reinterpret_cast<unsigned long long&>(d))
        : "l"(reinterpret_cast<unsigned long long&>(a)),
          "l"(reinterpret_cast<unsigned long long&>(b)),
          "l"(reinterpret_cast<unsigned long long&>(c)));
    return d;
}
// pack two f32 -> f16x2 (lo half = x, hi half = y)
__device__ __forceinline__ uint32_t pack_f16x2(float lo, float hi) {
    uint32_t w;
    asm("cvt.rn.f16x2.f32 %0, %1, %2;" : "=r"(w) : "f"(hi), "f"(lo));
    return w;
}
// packed relu on f16x2 (equivalent to relu-before-pack: negatives -> +0)
__device__ __forceinline__ uint32_t relu_f16x2(uint32_t w) {
    uint32_t r;
    asm("max.f16x2 %0, %1, %2;" : "=r"(r) : "r"(w), "r"(0u));
    return r;
}

__device__ __forceinline__ float clipf(float x, float lo, float hi) {
    return x < lo ? lo : (x > hi ? hi : x);
}

// ---- warp-shuffle scans ----
__device__ __forceinline__ float warp_scan_mul(float v, int lane) {
#pragma unroll
    for (int o = 1; o < 32; o <<= 1) {
        float t = __shfl_up_sync(0xffffffffu, v, o);
        if (lane >= o) v *= t;
    }
    return v;
}
__device__ __forceinline__ float warp_scan_add(float v, int lane) {
#pragma unroll
    for (int o = 1; o < 32; o <<= 1) {
        float t = __shfl_up_sync(0xffffffffu, v, o);
        if (lane >= o) v += t;
    }
    return v;
}
__device__ __forceinline__ float scan128_mul(float v, int tid, float* wt) {
    int lane = tid & 31, w = tid >> 5;
    float s = warp_scan_mul(v, lane);
    if (lane == 31) wt[w] = s;
    __syncthreads();
    float pre = 1.f;
#pragma unroll
    for (int k = 0; k < 3; k++) if (k < w) pre *= wt[k];
    return s * pre;
}
__device__ __forceinline__ float scan128_add(float v, int tid, float* wt) {
    int lane = tid & 31, w = tid >> 5;
    float s = warp_scan_add(v, lane);
    if (lane == 31) wt[w] = s;
    __syncthreads();
    float pre = 0.f;
#pragma unroll
    for (int k = 0; k < 3; k++) if (k < w) pre += wt[k];
    return s + pre;
}

// ---------------------------------------------------------------------------
// One field pass for 128 samples. Warp w owns rows 32w..32w+31.
// Layer 1 computed directly in m16n8k16 A-fragment layout (no SMEM staging).
// Pure fp16 single-term MMA; relu fused into packed f16x2 max.
// COARSE template param: z computed arithmetically (no LDS) for the coarse pass.
// ---------------------------------------------------------------------------
template <bool COARSE>
__device__ __forceinline__ void field_pass(
    float* sm, uint32_t smem_base, int tid,
    float ox, float oy, float oz, float dx, float dy, float dz,
    float near, float span,
    float dirR0, float dirR1, float dirR2, int outBase)
{
    const int lane = tid & 31;
    const int wid = tid >> 5;
    const int c = lane & 3, g = lane >> 2;
    const int m0 = 32 * wid;

    const int br = (lane & 7) + ((lane >> 4) << 3);    // B row within n16 group
    const int bkh = (lane >> 3) & 1;                   // B k-half
    const uint32_t bHiBase = smem_base + O_BHI * 4;

    // ---- per-fragment ray points: rows m0 + 8i + g, i = 0..3 ----
    float pxs[4], pys[4], pzs[4];
#pragma unroll
    for (int i = 0; i < 4; i++) {
        int row = m0 + 8 * i + g;
        float z = COARSE ? (near + span * ((float)row * (1.f / 127.f)))
                         : sm[O_Z + outBase + row];
        pxs[i] = clipf(fmaf(dx, z, ox), -BOUND, BOUND);
        pys[i] = clipf(fmaf(dy, z, oy), -BOUND, BOUND);
        pzs[i] = clipf(fmaf(dz, z, oz), -BOUND, BOUND);
    }

    // ---- warp MMA: D[32][64] = A(fp16) * B(fp16), fp32 accum ----
    float d[2][8][4];
#pragma unroll
    for (int mt = 0; mt < 2; mt++)
#pragma unroll
        for (int n = 0; n < 8; n++)
#pragma unroll
            for (int e = 0; e < 4; e++) d[mt][n][e] = 0.f;

    const float2* w1p = (const float2*)(sm + O_W1);
    const float2* b1p = (const float2*)(sm + O_B1);

#pragma unroll
    for (int ks = 0; ks < 4; ks++) {
        // A-fragments computed in registers (layer 1, fp16, fused relu)
        uint32_t ahi[2][4];
        const int p0 = 8 * ks + c, p1 = p0 + 4;
        float2 W0x = w1p[p0],      W1x = w1p[p1];
        float2 W0y = w1p[32 + p0], W1y = w1p[32 + p1];
        float2 W0z = w1p[64 + p0], W1z = w1p[64 + p1];
        float2 B0  = b1p[p0],      B1  = b1p[p1];
#pragma unroll
        for (int mt = 0; mt < 2; mt++) {
#pragma unroll
            for (int rr = 0; rr < 2; rr++) {
                int i = 2 * mt + rr;
                float2 PX = make_float2(pxs[i], pxs[i]);
                float2 PY = make_float2(pys[i], pys[i]);
                float2 PZ = make_float2(pzs[i], pzs[i]);
                float2 v0 = ffma2(PX, W0x, ffma2(PY, W0y, ffma2(PZ, W0z, B0)));
                float2 v1 = ffma2(PX, W1x, ffma2(PY, W1y, ffma2(PZ, W1z, B1)));
                ahi[mt][0 + rr] = relu_f16x2(pack_f16x2(v0.x, v0.y));
                ahi[mt][2 + rr] = relu_f16x2(pack_f16x2(v1.x, v1.y));
            }
        }
#pragma unroll
        for (int np = 0; np < 4; np++) {
            uint32_t bh[4];
            uint32_t boff = (uint32_t)(16 * np + br) * 128u +
                            (uint32_t)(((2 * ks + bkh) ^ (br & 7)) << 4);
            LDM_X4(bh, bHiBase + boff);
            MMA16816(d[0][2 * np + 0], ahi[0], bh[0], bh[1]);
            MMA16816(d[0][2 * np + 1], ahi[0], bh[2], bh[3]);
            MMA16816(d[1][2 * np + 0], ahi[1], bh[0], bh[1]);
            MMA16816(d[1][2 * np + 1], ahi[1], bh[2], bh[3]);
        }
    }

    // ---- head MMA epilogue: heads[128][8] = relu(D+b2) @ Whead[64][8] ----
    {
        float d2[2][4];
#pragma unroll
        for (int mt = 0; mt < 2; mt++)
#pragma unroll
            for (int e = 0; e < 4; e++) d2[mt][e] = 0.f;

#pragma unroll
        for (int ks = 0; ks < 4; ks++) {
            uint2 hb = *(const uint2*)(sm + O_HB + (ks * 32 + lane) * 2);
            uint32_t bh0 = hb.x, bh1 = hb.y;

            float2 b2a = *(const float2*)(sm + O_B2 + 16 * ks + 2 * c);
            float2 b2b = *(const float2*)(sm + O_B2 + 16 * ks + 8 + 2 * c);

            uint32_t ah[2][4];
#pragma unroll
            for (int mt = 0; mt < 2; mt++) {
                float e00 = d[mt][2 * ks][0] + b2a.x;
                float e01 = d[mt][2 * ks][1] + b2a.y;
                float e02 = d[mt][2 * ks][2] + b2a.x;
                float e03 = d[mt][2 * ks][3] + b2a.y;
                float e10 = d[mt][2 * ks + 1][0] + b2b.x;
                float e11 = d[mt][2 * ks + 1][1] + b2b.y;
                float e12 = d[mt][2 * ks + 1][2] + b2b.x;
                float e13 = d[mt][2 * ks + 1][3] + b2b.y;

                ah[mt][0] = relu_f16x2(pack_f16x2(e00, e01));
                ah[mt][1] = relu_f16x2(pack_f16x2(e02, e03));
                ah[mt][2] = relu_f16x2(pack_f16x2(e10, e11));
                ah[mt][3] = relu_f16x2(pack_f16x2(e12, e13));
            }
            MMA16816(d2[0], ah[0], bh0, bh1);
            MMA16816(d2[1], ah[1], bh0, bh1);
        }

        // stage heads to warp-private scratch
        float* sHD = sm + O_HD + wid * 128;   // [32 rows][4 heads]
        if (c < 2) {
#pragma unroll
            for (int mt = 0; mt < 2; mt++) {
                *(float2*)(sHD + (16 * mt + g) * 4 + 2 * c)     = make_float2(d2[mt][0], d2[mt][1]);
                *(float2*)(sHD + (16 * mt + 8 + g) * 4 + 2 * c) = make_float2(d2[mt][2], d2[mt][3]);
            }
        }
        __syncwarp();

        // finalize: thread = its own sample
        float4 hd = *(const float4*)(sHD + lane * 4);
        float sg = hd.x;
        float sigma = fmaxf(sg, 0.f) + __logf(1.f + __expf(-fabsf(sg)));
        float r0 = hd.y + dirR0;
        float r1 = hd.z + dirR1;
        float r2 = hd.w + dirR2;
        sm[O_SIG + outBase + tid] = sigma;
        sm[O_RGB + (outBase + tid) * 3 + 0] = 1.f / (1.f + __expf(-r0));
        sm[O_RGB + (outBase + tid) * 3 + 1] = 1.f / (1.f + __expf(-r1));
        sm[O_RGB + (outBase + tid) * 3 + 2] = 1.f / (1.f + __expf(-r2));
    }
}

// ---------------------------------------------------------------------------
// Persistent CTAs: each CTA loops over rays (ray = blockIdx.x + k*gridDim.x).
// W2 convert + head-frag prepack run ONCE per CTA, stay resident in SMEM.
// ---------------------------------------------------------------------------
__global__ void __launch_bounds__(128, 5)
nerf_render_kernel(const float* __restrict__ rays_o, const float* __restrict__ rays_d,
                   const float* __restrict__ W1, const float* __restrict__ b1,
                   const float* __restrict__ W2, const float* __restrict__ b2,
                   const float* __restrict__ Wsig, const float* __restrict__ Wrgb,
                   const float* __restrict__ brgb,
                   float* __restrict__ out, int nrays)
{
    extern __shared__ float sm[];
    const int tid = threadIdx.x;
    const uint32_t smem_base = smem_u32(sm);

    // ======== per-CTA prologue (once) ========
    for (int i = tid; i < 192; i += 128) sm[O_W1 + i] = W1[i];
    if (tid < 64) { sm[O_B1 + tid] = b1[tid]; sm[O_B2 + tid] = b2[tid]; sm[O_WSIG + tid] = Wsig[tid]; }
    for (int i = tid; i < 201; i += 128) sm[O_WRGB + i] = Wrgb[i];
    if (tid < 3) sm[O_BRGB + tid] = brgb[tid];

    // W2 -> fp16 B plane: B[j][k] = W2[k][j], 128B rows, chunk-granular swizzle
    {
        char* bhi = (char*)(sm + O_BHI);
#pragma unroll
        for (int t = 0; t < 4; t++) {
            int idx = tid + t * 128;           // 0..511
            int j = idx & 63, cch = idx >> 6;  // row, chunk
            uint32_t w[4];
#pragma unroll
            for (int q = 0; q < 4; q++) {
                int k0 = cch * 8 + 2 * q;
                float f0 = W2[k0 * 64 + j];
                float f1 = W2[(k0 + 1) * 64 + j];
                w[q] = pack_f16x2(f0, f1);
            }
            int swc = cch ^ (j & 7);
            *(uint4*)(bhi + j * 128 + swc * 16) = make_uint4(w[0], w[1], w[2], w[3]);
        }
    }
    __syncthreads();   // WSIG/WRGB visible for prepack

    // prepack head-MMA B-fragments (ray-invariant)
    {
        int ks = tid >> 5, lane = tid & 31;
        int tig = lane & 3, g = lane >> 2;
        int kb = 16 * ks + 2 * tig;
        float w0, w1, w2, w3;
        if (g == 0) {
            w0 = sm[O_WSIG + kb];     w1 = sm[O_WSIG + kb + 1];
            w2 = sm[O_WSIG + kb + 8]; w3 = sm[O_WSIG + kb + 9];
        } else if (g < 4) {
            int ch = g - 1;
            w0 = sm[O_WRGB + 3 * kb + ch];       w1 = sm[O_WRGB + 3 * (kb + 1) + ch];
            w2 = sm[O_WRGB + 3 * (kb + 8) + ch]; w3 = sm[O_WRGB + 3 * (kb + 9) + ch];
        } else {
            w0 = w1 = w2 = w3 = 0.f;
        }
        *(uint2*)(sm + O_HB + tid * 2) = make_uint2(pack_f16x2(w0, w1), pack_f16x2(w2, w3));
    }
    __syncthreads();   // prologue tables ready

    float* sZ   = sm + O_Z;
    float* sSig = sm + O_SIG;
    float* sRGB = sm + O_RGB;
    float* sBuf = sm + O_BUF;
    float* sC   = sm + O_C;
    float* sA   = sm + O_A;
    float* sRed = sm + O_RED;
    float* sWT  = sm + O_WT;

    // ======== persistent ray loop ========
    for (int ray = blockIdx.x; ray < nrays; ray += gridDim.x) {

        const float ox = rays_o[ray * 3 + 0], oy = rays_o[ray * 3 + 1], oz = rays_o[ray * 3 + 2];
        const float dx = rays_d[ray * 3 + 0], dy = rays_d[ray * 3 + 1], dz = rays_d[ray * 3 + 2];

        float near = -3.0e38f, far = 3.0e38f;
        {
            float o3[3] = {ox, oy, oz}, d3[3] = {dx, dy, dz};
#pragma unroll
            for (int c = 0; c < 3; c++) {
                float den = d3[c] + 1e-15f;
                float tmn = (-BOUND - o3[c]) / den;
                float tmx = ( BOUND - o3[c]) / den;
                near = fmaxf(near, fminf(tmn, tmx));
                far  = fminf(far,  fmaxf(tmn, tmx));
            }
            if (far < near) { near = 1e9f; far = 1e9f; }
            near = fmaxf(near, 0.05f);
        }
        const float span = far - near;
        const float sample_dist = span / (float)NS;
        const float invSpan = 1.f / span;

        // dir-dependent head terms
        const float dirR0 = fmaf(dx, sm[O_WRGB + 64 * 3 + 0], fmaf(dy, sm[O_WRGB + 65 * 3 + 0], fmaf(dz, sm[O_WRGB + 66 * 3 + 0], sm[O_BRGB + 0])));
        const float dirR1 = fmaf(dx, sm[O_WRGB + 64 * 3 + 1], fmaf(dy, sm[O_WRGB + 65 * 3 + 1], fmaf(dz, sm[O_WRGB + 66 * 3 + 1], sm[O_BRGB + 1])));
        const float dirR2 = fmaf(dx, sm[O_WRGB + 64 * 3 + 2], fmaf(dy, sm[O_WRGB + 65 * 3 + 2], fmaf(dz, sm[O_WRGB + 66 * 3 + 2], sm[O_BRGB + 2])));

        // ========== Phase A: coarse (z computed arithmetically) ==========
        float zc = near + span * ((float)tid * (1.f / 127.f));
        sZ[tid] = zc;     // needed by phase B deltas
        field_pass<true>(sm, smem_base, tid, ox, oy, oz, dx, dy, dz, near, span,
                         dirR0, dirR1, dirR2, 0);
        __syncthreads();

        // ========== Phase B: weights -> pdf -> inverse-CDF scatter ==========
        {
            float delta = (tid < NS - 1) ? (sZ[tid + 1] - sZ[tid]) : sample_dist;
            float alpha = 1.f - __expf(-delta * sSig[tid]);
            float shifted = 1.f - alpha + 1e-15f;
            if (tid < NS - 1) sC[tid] = sZ[tid] + 0.5f * delta;
            float Tincl = scan128_mul(shifted, tid, sWT);   // sync inside
            float w = alpha * (Tincl / shifted);            // exclusive via division
            sA[tid] = w;
            __syncthreads();
            float pv = (tid < 126) ? (sA[tid + 1] + 1e-5f) : 0.f;
            float csum = scan128_add(pv, tid, sWT);         // sync inside
            sBuf[tid] = csum;
            __syncthreads();
            const float invS = 1.f / sBuf[125];

            // thread tid = bin: u in [c[tid], c[tid+1]) -> scatter fine z
            if (tid < 127) {
                float clo = (tid == 0) ? 0.f : sBuf[tid - 1] * invS;
                bool last = (tid == 126);
                float chi = last ? 3.0e38f : sBuf[tid] * invS;
                int t0 = max(0, (int)ceilf(fmaf(128.f, clo, -0.5f)));
                int t1 = last ? 127 : (min(128, (int)ceilf(fmaf(128.f, chi, -0.5f))) - 1);
                if (t0 <= t1) {
                    int above = min(tid + 1, 126);
                    float cb = clo;
                    float ca = sBuf[above - 1] * invS;
                    float bb = sC[tid], ba = sC[above];
                    float den = ca - cb;
                    if (den < 1e-5f) den = 1.f;
                    float scale = (ba - bb) / den;
                    for (int t = t0; t <= t1; t++) {
                        float u = 0.00390625f + (float)t * 0.0078125f;
                        sZ[NS + t] = bb + (u - cb) * scale;
                    }
                }
            }
        }
        __syncthreads();

        // ========== Phase C: fine ==========
        float new_z = sZ[NS + tid];
        field_pass<false>(sm, smem_base, tid, ox, oy, oz, dx, dy, dz, near, span,
                          dirR0, dirR1, dirR2, NS);
        __syncthreads();

        // ========== Phase D: stable merge of two sorted runs ==========
        {
            float zA = sZ[tid], zB = new_z;
            int lo = 0, hi = NS;
            while (lo < hi) { int m = (lo + hi) >> 1; if (sZ[NS + m] < zA) lo = m + 1; else hi = m; }
            int posA = tid + lo;
            lo = 0; hi = NS;
            while (lo < hi) { int m = (lo + hi) >> 1; if (sZ[m] <= zB) lo = m + 1; else hi = m; }
            int posB = tid + lo;

            float sgA = sSig[tid], sgB = sSig[NS + tid];
            float a0 = sRGB[tid * 3 + 0], a1 = sRGB[tid * 3 + 1], a2 = sRGB[tid * 3 + 2];
            float b0 = sRGB[(NS + tid) * 3 + 0], b1v = sRGB[(NS + tid) * 3 + 1], b2v = sRGB[(NS + tid) * 3 + 2];
            __syncthreads();
            sZ[posA] = zA; sSig[posA] = sgA;
            sRGB[posA * 3 + 0] = a0; sRGB[posA * 3 + 1] = a1; sRGB[posA * 3 + 2] = a2;
            sZ[posB] = zB; sSig[posB] = sgB;
            sRGB[posB * 3 + 0] = b0; sRGB[posB * 3 + 1] = b1v; sRGB[posB * 3 + 2] = b2v;
            __syncthreads();
        }

        // ========== Phase E: final composite ==========
        {
            const int i0 = 2 * tid, i1 = 2 * tid + 1;
            float d0 = sZ[i0 + 1] - sZ[i0];
            float d1 = (i1 < NT - 1) ? (sZ[i1 + 1] - sZ[i1]) : sample_dist;
            float al0 = 1.f - __expf(-d0 * sSig[i0]);
            float al1 = 1.f - __expf(-d1 * sSig[i1]);
            float s0 = 1.f - al0 + 1e-15f;
            float s1 = 1.f - al1 + 1e-15f;

            int lane = tid & 31, w = tid >> 5;
            float p = s0 * s1;
            float pincl = warp_scan_mul(p, lane);
            if (lane == 31) sWT[w] = pincl;
            __syncthreads();
            float pre = 1.f;
#pragma unroll
            for (int k = 0; k < 3; k++) if (k < w) pre *= sWT[k];
            float e = __shfl_up_sync(0xffffffffu, pincl, 1);
            e = (lane == 0) ? 1.f : e;
            e *= pre;
            float w0 = al0 * e;
            float w1 = al1 * e * s0;

            float v0 = clipf((sZ[i0] - near) * invSpan, 0.f, 1.f);
            float v1 = clipf((sZ[i1] - near) * invSpan, 0.f, 1.f);
            float wsum = w0 + w1;
            float dsum = w0 * v0 + w1 * v1;
            float rs0 = fmaf(w0, sRGB[i0 * 3 + 0], w1 * sRGB[i1 * 3 + 0]);
            float rs1 = fmaf(w0, sRGB[i0 * 3 + 1], w1 * sRGB[i1 * 3 + 1]);
            float rs2 = fmaf(w0, sRGB[i0 * 3 + 2], w1 * sRGB[i1 * 3 + 2]);

#pragma unroll
            for (int o = 16; o > 0; o >>= 1) {
                wsum += __shfl_down_sync(0xffffffffu, wsum, o);
                dsum += __shfl_down_sync(0xffffffffu, dsum, o);
                rs0  += __shfl_down_sync(0xffffffffu, rs0, o);
                rs1  += __shfl_down_sync(0xffffffffu, rs1, o);
                rs2  += __shfl_down_sync(0xffffffffu, rs2, o);
            }
            if (lane == 0) {
                sRed[w * 5 + 0] = wsum; sRed[w * 5 + 1] = dsum;
                sRed[w * 5 + 2] = rs0;  sRed[w * 5 + 3] = rs1; sRed[w * 5 + 4] = rs2;
            }
            __syncthreads();
            if (tid == 0) {
                float W = 0, D = 0, R0 = 0, R1 = 0, R2 = 0;
#pragma unroll
                for (int w2 = 0; w2 < 4; w2++) {
                    W += sRed[w2 * 5 + 0]; D += sRed[w2 * 5 + 1];
                    R0 += sRed[w2 * 5 + 2]; R1 += sRed[w2 * 5 + 3]; R2 += sRed[w2 * 5 + 4];
                }
                float bg = 1.f - W;
                out[ray] = D;
                out[nrays + ray * 3 + 0] = R0 + bg;
                out[nrays + ray * 3 + 1] = R1 + bg;
                out[nrays + ray * 3 + 2] = R2 + bg;
            }
        }
        // final phase-E __syncthreads above orders all reads of this ray's
        // buffers before next iteration's writes (sZ etc.) — loop is race-free.
    }
}

extern "C" void kernel_launch(void* const* d_in, const int* in_sizes, int n_in,
                              void* d_out, int out_size) {
    const float* rays_o = (const float*)d_in[0];
    const float* rays_d = (const float*)d_in[1];
    const float* W1   = (const float*)d_in[2];
    const float* b1   = (const float*)d_in[3];
    const float* W2   = (const float*)d_in[4];
    const float* b2   = (const float*)d_in[5];
    const float* Wsig = (const float*)d_in[6];
    const float* Wrgb = (const float*)d_in[7];
    const float* brgb = (const float*)d_in[8];
    float* out = (float*)d_out;

    int nrays = in_sizes[0] / 3;   // B*N
    int grid = 148 * 5;            // persistent: 5 CTAs/SM x 148 SMs
    if (grid > nrays) grid = nrays;
    size_t smem_bytes = (size_t)SMEM_FLOATS * sizeof(float);
    cudaFuncSetAttribute(nerf_render_kernel,
                         cudaFuncAttributeMaxDynamicSharedMemorySize, (int)smem_bytes);
    nerf_render_kernel<<<grid, 128, smem_bytes>>>(rays_o, rays_d, W1, b1, W2, b2,
                                                  Wsig, Wrgb, brgb, out, nrays);
}